// round 6
// baseline (speedup 1.0000x reference)
#include <cuda_runtime.h>
#include <math.h>
#include <stdint.h>
#include <stddef.h>

#define FEAT    36
#define NNODES  24
#define NROUTES 48
#define CH      128
#define COUT    32
#define RH      128
#define BATCH   512
#define NSEQ    (BATCH * NROUTES)     /* 24576 */
#define G3      (3 * RH)              /* 384   */
#define NROWS   (NNODES * NSEQ)       /* 589824 */

typedef unsigned long long ull;

/* ---- packed f32x2 helpers (SASS FFMA2 path, only reachable via PTX) ---- */
__device__ __forceinline__ ull pack2s(float x) {
    ull r; asm("mov.b64 %0, {%1, %1};" : "=l"(r) : "f"(x)); return r;
}
__device__ __forceinline__ ull pack2(float x, float y) {
    ull r; asm("mov.b64 %0, {%1, %2};" : "=l"(r) : "f"(x), "f"(y)); return r;
}
__device__ __forceinline__ ull ffma2(ull a, ull b, ull c) {
    ull d; asm("fma.rn.f32x2 %0, %1, %2, %3;" : "=l"(d) : "l"(a), "l"(b), "l"(c)); return d;
}
__device__ __forceinline__ float2 unpk(ull v) {
    float lo, hi; asm("mov.b64 {%0, %1}, %2;" : "=f"(lo), "=f"(hi) : "l"(v));
    return make_float2(lo, hi);
}
__device__ __forceinline__ float sigm(float x) { return 1.f / (1.f + expf(-x)); }

__device__ __forceinline__ void cp16(float* dst, const float4* src) {
    unsigned s = (unsigned)__cvta_generic_to_shared(dst);
    asm volatile("cp.async.ca.shared.global [%0], [%1], 16;" :: "r"(s), "l"(src));
}

/* scratch (no allocation allowed -> __device__ globals) */
__device__ float g_x32[(size_t)NROWS * COUT];   /* [t][n][32] node embeddings */
__device__ float g_last[(size_t)NSEQ * RH];     /* last GRU hidden per sequence */

/* GRU weights as duplicated (w,w) pairs, concatenated in streaming order:
   k-rows 0-31 wih0, 32-159 whh0, 160-287 wih1, 288-415 whh1.
   Chunk = 16 k-rows; within chunk: [kl][gate*128 + j] ull pairs. */
#define KCH 16
#define CHUNK_ULL (KCH * G3)       /* 6144 ull = 49152 B */
#define NCHUNK 26
__device__ ull g_wcat[(size_t)NCHUNK * CHUNK_ULL];

__device__ ull g_w1d[FEAT * CH];   /* (w1,w1) pairs for k_cust */
__device__ ull g_w2d[CH * COUT];

/* ==================== prep kernels ==================== */
__global__ __launch_bounds__(256) void k_prep_gru(
    const float* __restrict__ wih0, const float* __restrict__ whh0,
    const float* __restrict__ wih1, const float* __restrict__ whh1)
{
    int idx = blockIdx.x * 256 + threadIdx.x;   /* over 416*384 */
    if (idx >= 416 * 384) return;
    int k = idx / 384, c = idx - k * 384;
    int kk; const float* src;
    if      (k < 32)  { kk = k;       src = wih0; }
    else if (k < 160) { kk = k - 32;  src = whh0; }
    else if (k < 288) { kk = k - 160; src = wih1; }
    else              { kk = k - 288; src = whh1; }
    float v = src[kk * 384 + c];
    int chunk = k / KCH, kl = k - chunk * KCH;
    g_wcat[(size_t)chunk * CHUNK_ULL + kl * G3 + c] = pack2(v, v);
}

__global__ __launch_bounds__(256) void k_prep_cust(
    const float* __restrict__ w1, const float* __restrict__ w2)
{
    int idx = blockIdx.x * 256 + threadIdx.x;
    if (idx < FEAT * CH) {
        float v = w1[idx];
        g_w1d[idx] = pack2(v, v);
    }
    int i2 = idx - FEAT * CH;
    if (i2 >= 0 && i2 < CH * COUT) {
        float v = w2[i2];
        g_w2d[i2] = pack2(v, v);
    }
}

/* ==================== K1: customer MLP 36->128(tanh)->32(tanh) ==================== */
#define K1_ROWS 64
#define XT_ST   68
#define HT_ST   68

__global__ __launch_bounds__(256) void k_cust(
    const float* __restrict__ cust,           /* [NSEQ][NNODES*FEAT] */
    const float* __restrict__ b1, const float* __restrict__ b2)
{
    __shared__ __align__(16) float xT[FEAT * XT_ST];
    __shared__ __align__(16) float hT[CH * HT_ST];
    const int tid = threadIdx.x;
    const long long row0 = (long long)blockIdx.x * K1_ROWS;   /* row = t*NSEQ + n */

    #pragma unroll
    for (int rep = 0; rep < K1_ROWS * FEAT / 256; rep++) {
        int e = tid + rep * 256;
        int s = e / FEAT, f = e - s * FEAT;
        long long row = row0 + s;
        int t = (int)(row / NSEQ);
        int n = (int)(row - (long long)t * NSEQ);
        xT[f * XT_ST + s] = cust[(size_t)n * (NNODES * FEAT) + t * FEAT + f];
    }
    __syncthreads();

    /* phase 1 */
    {
        const int j  = tid & 127;
        const int s0 = (tid >> 7) * 32;
        ull a[16];
        ull bb = pack2s(b1[j]);
        #pragma unroll
        for (int u = 0; u < 16; u++) a[u] = bb;
        #pragma unroll 4
        for (int i = 0; i < FEAT; i++) {
            ull w = g_w1d[i * CH + j];
            const ulonglong2* xp = (const ulonglong2*)(xT + i * XT_ST + s0);
            #pragma unroll
            for (int q = 0; q < 8; q++) {
                ulonglong2 v = xp[q];
                a[2 * q]     = ffma2(w, v.x, a[2 * q]);
                a[2 * q + 1] = ffma2(w, v.y, a[2 * q + 1]);
            }
        }
        float* hp = hT + j * HT_ST + s0;
        #pragma unroll
        for (int q = 0; q < 8; q++) {
            float2 p0 = unpk(a[2 * q]), p1 = unpk(a[2 * q + 1]);
            float4 o = make_float4(tanhf(p0.x), tanhf(p0.y), tanhf(p1.x), tanhf(p1.y));
            *(float4*)(hp + 4 * q) = o;
        }
    }
    __syncthreads();

    /* phase 2 */
    {
        const int j2 = tid & 31;
        const int s0 = (tid >> 5) * 8;
        ull a[4];
        ull bb = pack2s(b2[j2]);
        #pragma unroll
        for (int u = 0; u < 4; u++) a[u] = bb;
        #pragma unroll 4
        for (int k = 0; k < CH; k++) {
            ull w = g_w2d[k * COUT + j2];
            const ulonglong2* hp = (const ulonglong2*)(hT + k * HT_ST + s0);
            ulonglong2 v0 = hp[0], v1 = hp[1];
            a[0] = ffma2(w, v0.x, a[0]);
            a[1] = ffma2(w, v0.y, a[1]);
            a[2] = ffma2(w, v1.x, a[2]);
            a[3] = ffma2(w, v1.y, a[3]);
        }
        size_t base = (size_t)(row0 + s0) * COUT + j2;
        #pragma unroll
        for (int q = 0; q < 4; q++) {
            float2 p = unpk(a[q]);
            g_x32[base + (size_t)(2 * q) * COUT]     = tanhf(p.x);
            g_x32[base + (size_t)(2 * q + 1) * COUT] = tanhf(p.y);
        }
    }
}

/* ==================== K2: fused 2-layer GRU, 1024 threads, cp.async ring ==================== */
#define STILE   64
#define PAD     68
#define NTHR    1024
/* smem floats: state 288*PAD = 19584 | bias 8*128 ull = 2048 fl | ring 2*CHUNK_ULL ull */
#define SM_BIAS 19584
#define SM_RING (19584 + 2048)
#define K2_SMEM ((SM_RING + 4 * CHUNK_ULL) * 4)   /* 184832 B */

__device__ __forceinline__ void compute_chunk(
    const ull* __restrict__ ws,      /* smem [KCH][384] dup-pair weights */
    const float* __restrict__ src,   /* smem activations, row-offset applied */
    int j, int s0,
    ull* __restrict__ ar, ull* __restrict__ az, ull* __restrict__ an)
{
    #pragma unroll 8
    for (int kl = 0; kl < KCH; kl++) {
        const ull* wp = ws + kl * G3 + j;
        ull wr = wp[0], wz = wp[128], wn = wp[256];
        const ulonglong2* pa = (const ulonglong2*)(src + kl * PAD + s0);
        ulonglong2 p0 = pa[0], p1 = pa[1];
        ar[0] = ffma2(wr, p0.x, ar[0]); az[0] = ffma2(wz, p0.x, az[0]); an[0] = ffma2(wn, p0.x, an[0]);
        ar[1] = ffma2(wr, p0.y, ar[1]); az[1] = ffma2(wz, p0.y, az[1]); an[1] = ffma2(wn, p0.y, an[1]);
        ar[2] = ffma2(wr, p1.x, ar[2]); az[2] = ffma2(wz, p1.x, az[2]); an[2] = ffma2(wn, p1.x, an[2]);
        ar[3] = ffma2(wr, p1.y, ar[3]); az[3] = ffma2(wz, p1.y, az[3]); an[3] = ffma2(wn, p1.y, an[3]);
    }
}

__device__ __forceinline__ void issue_chunk(int cid, ull* slot, int tid)
{
    const float4* g = (const float4*)(g_wcat + (size_t)cid * CHUNK_ULL);
    float4* d = (float4*)slot;
    #pragma unroll
    for (int i = 0; i < 3; i++)
        cp16((float*)(d + tid + i * NTHR), g + tid + i * NTHR);
    asm volatile("cp.async.commit_group;");
}

__global__ __launch_bounds__(NTHR, 1) void k_gru(
    const float* __restrict__ bih0, const float* __restrict__ bhh0,
    const float* __restrict__ bih1, const float* __restrict__ bhh1)
{
    extern __shared__ __align__(16) float smem[];
    float* h0buf = smem;                       /* [128][PAD] */
    float* h1buf = smem + 128 * PAD;           /* [128][PAD] */
    float* xt    = smem + 256 * PAD;           /* [32][PAD]  */
    ull*   bias_u = (ull*)(smem + SM_BIAS);    /* [8][128]   */
    ull*   wring  = (ull*)(smem + SM_RING);    /* [2][CHUNK_ULL] */
    const int tid = threadIdx.x;
    const int j   = tid & 127;
    const int s0  = (tid >> 7) * 8;            /* 8 seqs per thread */
    const int nbase = blockIdx.x * STILE;

    for (int i = tid; i < 256 * PAD; i += NTHR) smem[i] = 0.f;   /* h0 = h1 = 0 */
    if (tid < 128) {
        bias_u[0 * 128 + tid] = pack2s(bih0[tid] + bhh0[tid]);
        bias_u[1 * 128 + tid] = pack2s(bih0[128 + tid] + bhh0[128 + tid]);
        bias_u[2 * 128 + tid] = pack2s(bih0[256 + tid]);
        bias_u[3 * 128 + tid] = pack2s(bhh0[256 + tid]);
        bias_u[4 * 128 + tid] = pack2s(bih1[tid] + bhh1[tid]);
        bias_u[5 * 128 + tid] = pack2s(bih1[128 + tid] + bhh1[128 + tid]);
        bias_u[6 * 128 + tid] = pack2s(bih1[256 + tid]);
        bias_u[7 * 128 + tid] = pack2s(bhh1[256 + tid]);
    }

    /* ring prologue: chunks 0 and 1 in flight */
    issue_chunk(0, wring, tid);
    issue_chunk(1, wring + CHUNK_ULL, tid);
    int cc = 0;

    ull ar[4], az[4], ai[4], ah[4];
    ull hn[4];

#define RING_STEP(SRC, TGT)                                                      \
    do {                                                                         \
        asm volatile("cp.async.wait_group 1;");                                  \
        __syncthreads();                                                         \
        compute_chunk(wring + (cc & 1) * CHUNK_ULL, (SRC), j, s0, ar, az, (TGT));\
        __syncthreads();                                                         \
        issue_chunk((cc + 2) % NCHUNK, wring + (cc & 1) * CHUNK_ULL, tid);       \
        cc++;                                                                    \
    } while (0)

    for (int t = 0; t < NNODES; t++) {
        /* load & transpose this step's inputs: 64 seqs x 32 feats */
        const float* srcx = g_x32 + ((size_t)t * NSEQ + nbase) * COUT;
        #pragma unroll
        for (int rep = 0; rep < 2; rep++) {
            int e = tid + rep * NTHR;
            xt[(e & 31) * PAD + (e >> 5)] = srcx[e];
        }
        /* xt stores ordered by RING_STEP's pre-compute barrier */

        /* ---- cell 0 ---- */
        {
            ull b0 = bias_u[0 * 128 + j], b1 = bias_u[1 * 128 + j];
            ull b2 = bias_u[2 * 128 + j], b3 = bias_u[3 * 128 + j];
            #pragma unroll
            for (int u = 0; u < 4; u++) { ar[u] = b0; az[u] = b1; ai[u] = b2; ah[u] = b3; }
        }
        RING_STEP(xt, ai);                              /* chunks 0-1: wih0 @ x_t */
        RING_STEP(xt + 16 * PAD, ai);
        #pragma unroll 1
        for (int q = 0; q < 8; q++)
            RING_STEP(h0buf + q * 16 * PAD, ah);        /* chunks 2-9: whh0 @ h0 */
        /* epilogue 0 (reads old h0) */
        #pragma unroll
        for (int u = 0; u < 4; u++) {
            float2 hold = *(const float2*)(h0buf + j * PAD + s0 + 2 * u);
            float2 R = unpk(ar[u]), Z = unpk(az[u]), I = unpk(ai[u]), H = unpk(ah[u]);
            float r0 = sigm(R.x), z0 = sigm(Z.x);
            float n0 = tanhf(I.x + r0 * H.x);
            float o0 = (1.f - z0) * n0 + z0 * hold.x;
            float r1 = sigm(R.y), z1 = sigm(Z.y);
            float n1 = tanhf(I.y + r1 * H.y);
            float o1 = (1.f - z1) * n1 + z1 * hold.y;
            hn[u] = pack2(o0, o1);
        }
        __syncthreads();
        #pragma unroll
        for (int u = 0; u < 4; u++)
            *(ull*)(h0buf + j * PAD + s0 + 2 * u) = hn[u];
        /* h0 stores ordered by next RING_STEP barrier */

        /* ---- cell 1 ---- */
        {
            ull b0 = bias_u[4 * 128 + j], b1 = bias_u[5 * 128 + j];
            ull b2 = bias_u[6 * 128 + j], b3 = bias_u[7 * 128 + j];
            #pragma unroll
            for (int u = 0; u < 4; u++) { ar[u] = b0; az[u] = b1; ai[u] = b2; ah[u] = b3; }
        }
        #pragma unroll 1
        for (int q = 0; q < 8; q++)
            RING_STEP(h0buf + q * 16 * PAD, ai);        /* chunks 10-17: wih1 @ h0_new */
        #pragma unroll 1
        for (int q = 0; q < 8; q++)
            RING_STEP(h1buf + q * 16 * PAD, ah);        /* chunks 18-25: whh1 @ h1 */
        /* epilogue 1 (reads old h1) */
        #pragma unroll
        for (int u = 0; u < 4; u++) {
            float2 hold = *(const float2*)(h1buf + j * PAD + s0 + 2 * u);
            float2 R = unpk(ar[u]), Z = unpk(az[u]), I = unpk(ai[u]), H = unpk(ah[u]);
            float r0 = sigm(R.x), z0 = sigm(Z.x);
            float n0 = tanhf(I.x + r0 * H.x);
            float o0 = (1.f - z0) * n0 + z0 * hold.x;
            float r1 = sigm(R.y), z1 = sigm(Z.y);
            float n1 = tanhf(I.y + r1 * H.y);
            float o1 = (1.f - z1) * n1 + z1 * hold.y;
            hn[u] = pack2(o0, o1);
        }
        __syncthreads();
        #pragma unroll
        for (int u = 0; u < 4; u++)
            *(ull*)(h1buf + j * PAD + s0 + 2 * u) = hn[u];
        /* h1/xt reuse ordered by next step's RING_STEP barrier */
    }
#undef RING_STEP

    asm volatile("cp.async.wait_group 0;");

    /* hn holds the final (t = 23) layer-1 state for this thread's 8 seqs */
    #pragma unroll
    for (int u = 0; u < 4; u++) {
        int s = s0 + 2 * u;
        float2 v = unpk(hn[u]);
        g_last[(size_t)(nbase + s) * RH + j]     = v.x;
        g_last[(size_t)(nbase + s + 1) * RH + j] = v.y;
    }
}

/* ==================== K3: mean over routes + head MLP ==================== */
__global__ __launch_bounds__(128) void k_final(
    const float* __restrict__ cand,
    const float* __restrict__ cand_w, const float* __restrict__ cand_b,
    const float* __restrict__ fc1w, const float* __restrict__ fc1b,
    const float* __restrict__ fc2w, const float* __restrict__ fc2b,
    const float* __restrict__ fc3w, const float* __restrict__ fc3b,
    float* __restrict__ out)
{
    __shared__ float xr[RH + 64];
    __shared__ float h[128];
    __shared__ float red[128];
    const int b = blockIdx.x, tid = threadIdx.x;

    {
        const float* base = g_last + (size_t)b * NROUTES * RH;
        float acc = 0.f;
        #pragma unroll 8
        for (int r = 0; r < NROUTES; r++) acc += base[r * RH + tid];
        xr[tid] = acc * (1.f / NROUTES);
    }
    if (tid < 64) {
        float a = cand_b[tid];
        #pragma unroll 8
        for (int i = 0; i < 2 * FEAT; i++)
            a += cand[b * 2 * FEAT + i] * cand_w[i * 64 + tid];
        xr[RH + tid] = a;
    }
    __syncthreads();

    {
        float a = fc1b[tid];
        #pragma unroll 8
        for (int i = 0; i < RH + 64; i++) a += xr[i] * fc1w[i * 128 + tid];
        h[tid] = tanhf(a);
    }
    __syncthreads();
    {
        float a = fc2b[tid];
        #pragma unroll 8
        for (int i = 0; i < 128; i++) a += h[i] * fc2w[i * 128 + tid];
        red[tid] = tanhf(a) * fc3w[tid];
    }
    __syncthreads();
    for (int s = 64; s > 0; s >>= 1) {
        if (tid < s) red[tid] += red[tid + s];
        __syncthreads();
    }
    if (tid == 0) out[b] = red[0] + fc3b[0];
}

/* ==================== launch ==================== */
extern "C" void kernel_launch(void* const* d_in, const int* in_sizes, int n_in,
                              void* d_out, int out_size)
{
    const float* candidates = (const float*)d_in[0];
    const float* customers  = (const float*)d_in[1];
    const float* cust_w1 = (const float*)d_in[2];
    const float* cust_b1 = (const float*)d_in[3];
    const float* cust_w2 = (const float*)d_in[4];
    const float* cust_b2 = (const float*)d_in[5];
    const float* wih0 = (const float*)d_in[6];
    const float* whh0 = (const float*)d_in[7];
    const float* bih0 = (const float*)d_in[8];
    const float* bhh0 = (const float*)d_in[9];
    const float* wih1 = (const float*)d_in[10];
    const float* whh1 = (const float*)d_in[11];
    const float* bih1 = (const float*)d_in[12];
    const float* bhh1 = (const float*)d_in[13];
    const float* cand_w = (const float*)d_in[14];
    const float* cand_b = (const float*)d_in[15];
    const float* fc1w = (const float*)d_in[16];
    const float* fc1b = (const float*)d_in[17];
    const float* fc2w = (const float*)d_in[18];
    const float* fc2b = (const float*)d_in[19];
    const float* fc3w = (const float*)d_in[20];
    const float* fc3b = (const float*)d_in[21];

    cudaFuncSetAttribute(k_gru, cudaFuncAttributeMaxDynamicSharedMemorySize, K2_SMEM);

    k_prep_gru<<<(416 * 384 + 255) / 256, 256>>>(wih0, whh0, wih1, whh1);
    k_prep_cust<<<(FEAT * CH + CH * COUT + 255) / 256, 256>>>(cust_w1, cust_w2);
    k_cust<<<NROWS / K1_ROWS, 256>>>(customers, cust_b1, cust_b2);
    k_gru<<<NSEQ / STILE, NTHR, K2_SMEM>>>(bih0, bhh0, bih1, bhh1);
    k_final<<<BATCH, 128>>>(candidates, cand_w, cand_b,
                            fc1w, fc1b, fc2w, fc2b, fc3w, fc3b,
                            (float*)d_out);
}

// round 7
// speedup vs baseline: 1.1987x; 1.1987x over previous
#include <cuda_runtime.h>
#include <math.h>
#include <stdint.h>
#include <stddef.h>

#define FEAT    36
#define NNODES  24
#define NROUTES 48
#define CH      128
#define COUT    32
#define RH      128
#define BATCH   512
#define NSEQ    (BATCH * NROUTES)     /* 24576 */
#define G3      (3 * RH)              /* 384   */
#define NROWS   (NNODES * NSEQ)       /* 589824 */

typedef unsigned long long ull;

/* ---- packed f32x2 helpers (SASS FFMA2 path, only reachable via PTX) ---- */
__device__ __forceinline__ ull pack2s(float x) {
    ull r; asm("mov.b64 %0, {%1, %1};" : "=l"(r) : "f"(x)); return r;
}
__device__ __forceinline__ ull pack2(float x, float y) {
    ull r; asm("mov.b64 %0, {%1, %2};" : "=l"(r) : "f"(x), "f"(y)); return r;
}
__device__ __forceinline__ ull ffma2(ull a, ull b, ull c) {
    ull d; asm("fma.rn.f32x2 %0, %1, %2, %3;" : "=l"(d) : "l"(a), "l"(b), "l"(c)); return d;
}
__device__ __forceinline__ float2 unpk(ull v) {
    float lo, hi; asm("mov.b64 {%0, %1}, %2;" : "=f"(lo), "=f"(hi) : "l"(v));
    return make_float2(lo, hi);
}
__device__ __forceinline__ float sigm(float x) { return 1.f / (1.f + expf(-x)); }

__device__ __forceinline__ void cp16(float* dst, const float4* src) {
    unsigned s = (unsigned)__cvta_generic_to_shared(dst);
    asm volatile("cp.async.ca.shared.global [%0], [%1], 16;" :: "r"(s), "l"(src));
}

/* scratch (no allocation allowed -> __device__ globals) */
__device__ float g_x32[(size_t)NROWS * COUT];   /* [t][n][32] node embeddings */
__device__ float g_last[(size_t)NSEQ * RH];     /* last GRU hidden per sequence */

/* GRU weights (scalar floats) concatenated in streaming order:
   k-rows 0-31 wih0, 32-159 whh0, 160-287 wih1, 288-415 whh1; row = 384 gate cols */
#define KCH 32
#define CHUNK_FLOATS (KCH * G3)    /* 12288 floats = 49152 B */
#define NCHUNK 13
__device__ float g_wcat[NCHUNK * CHUNK_FLOATS];

__device__ ull g_w1d[FEAT * CH];   /* (w1,w1) pairs for k_cust */
__device__ ull g_w2d[CH * COUT];

/* ==================== prep kernels ==================== */
__global__ __launch_bounds__(256) void k_prep_gru(
    const float* __restrict__ wih0, const float* __restrict__ whh0,
    const float* __restrict__ wih1, const float* __restrict__ whh1)
{
    int idx = blockIdx.x * 256 + threadIdx.x;   /* over 416*384 */
    if (idx >= 416 * 384) return;
    int k = idx / 384, c = idx - k * 384;
    int kk; const float* src;
    if      (k < 32)  { kk = k;       src = wih0; }
    else if (k < 160) { kk = k - 32;  src = whh0; }
    else if (k < 288) { kk = k - 160; src = wih1; }
    else              { kk = k - 288; src = whh1; }
    g_wcat[idx] = src[kk * 384 + c];
}

__global__ __launch_bounds__(256) void k_prep_cust(
    const float* __restrict__ w1, const float* __restrict__ w2)
{
    int idx = blockIdx.x * 256 + threadIdx.x;
    if (idx < FEAT * CH) {
        float v = w1[idx];
        g_w1d[idx] = pack2(v, v);
    }
    int i2 = idx - FEAT * CH;
    if (i2 >= 0 && i2 < CH * COUT) {
        float v = w2[i2];
        g_w2d[i2] = pack2(v, v);
    }
}

/* ==================== K1: customer MLP 36->128(tanh)->32(tanh) ==================== */
#define K1_ROWS 64
#define XT_ST   68
#define HT_ST   68

__global__ __launch_bounds__(256) void k_cust(
    const float* __restrict__ cust,           /* [NSEQ][NNODES*FEAT] */
    const float* __restrict__ b1, const float* __restrict__ b2)
{
    __shared__ __align__(16) float xT[FEAT * XT_ST];
    __shared__ __align__(16) float hT[CH * HT_ST];
    const int tid = threadIdx.x;
    const long long row0 = (long long)blockIdx.x * K1_ROWS;   /* row = t*NSEQ + n */

    #pragma unroll
    for (int rep = 0; rep < K1_ROWS * FEAT / 256; rep++) {
        int e = tid + rep * 256;
        int s = e / FEAT, f = e - s * FEAT;
        long long row = row0 + s;
        int t = (int)(row / NSEQ);
        int n = (int)(row - (long long)t * NSEQ);
        xT[f * XT_ST + s] = cust[(size_t)n * (NNODES * FEAT) + t * FEAT + f];
    }
    __syncthreads();

    /* phase 1 */
    {
        const int j  = tid & 127;
        const int s0 = (tid >> 7) * 32;
        ull a[16];
        ull bb = pack2s(b1[j]);
        #pragma unroll
        for (int u = 0; u < 16; u++) a[u] = bb;
        #pragma unroll 4
        for (int i = 0; i < FEAT; i++) {
            ull w = g_w1d[i * CH + j];
            const ulonglong2* xp = (const ulonglong2*)(xT + i * XT_ST + s0);
            #pragma unroll
            for (int q = 0; q < 8; q++) {
                ulonglong2 v = xp[q];
                a[2 * q]     = ffma2(w, v.x, a[2 * q]);
                a[2 * q + 1] = ffma2(w, v.y, a[2 * q + 1]);
            }
        }
        float* hp = hT + j * HT_ST + s0;
        #pragma unroll
        for (int q = 0; q < 8; q++) {
            float2 p0 = unpk(a[2 * q]), p1 = unpk(a[2 * q + 1]);
            float4 o = make_float4(tanhf(p0.x), tanhf(p0.y), tanhf(p1.x), tanhf(p1.y));
            *(float4*)(hp + 4 * q) = o;
        }
    }
    __syncthreads();

    /* phase 2 */
    {
        const int j2 = tid & 31;
        const int s0 = (tid >> 5) * 8;
        ull a[4];
        ull bb = pack2s(b2[j2]);
        #pragma unroll
        for (int u = 0; u < 4; u++) a[u] = bb;
        #pragma unroll 4
        for (int k = 0; k < CH; k++) {
            ull w = g_w2d[k * COUT + j2];
            const ulonglong2* hp = (const ulonglong2*)(hT + k * HT_ST + s0);
            ulonglong2 v0 = hp[0], v1 = hp[1];
            a[0] = ffma2(w, v0.x, a[0]);
            a[1] = ffma2(w, v0.y, a[1]);
            a[2] = ffma2(w, v1.x, a[2]);
            a[3] = ffma2(w, v1.y, a[3]);
        }
        size_t base = (size_t)(row0 + s0) * COUT + j2;
        #pragma unroll
        for (int q = 0; q < 4; q++) {
            float2 p = unpk(a[q]);
            g_x32[base + (size_t)(2 * q) * COUT]     = tanhf(p.x);
            g_x32[base + (size_t)(2 * q + 1) * COUT] = tanhf(p.y);
        }
    }
}

/* ==================== K2: fused 2-layer GRU, 1024 thr, scalar-weight cp.async ring ==================== */
#define STILE   64
#define PAD     68
#define NTHR    1024
/* smem floats: state 288*PAD = 19584 | bias 8*128 ull = 2048 fl | ring 2*CHUNK_FLOATS */
#define SM_BIAS 19584
#define SM_RING (19584 + 2048)
#define K2_SMEM ((SM_RING + 2 * CHUNK_FLOATS) * 4)   /* 184832 B */

__device__ __forceinline__ void compute_chunk(
    const float* __restrict__ ws,    /* smem [KCH][384] scalar weights */
    const float* __restrict__ src,   /* smem activations, row-offset applied */
    int j, int s0,
    ull* __restrict__ ar, ull* __restrict__ az, ull* __restrict__ an)
{
    #pragma unroll 8
    for (int kl = 0; kl < KCH; kl++) {
        const float* wp = ws + kl * G3 + j;
        ull wr = pack2s(wp[0]);
        ull wz = pack2s(wp[128]);
        ull wn = pack2s(wp[256]);
        const ulonglong2* pa = (const ulonglong2*)(src + kl * PAD + s0);
        ulonglong2 p0 = pa[0], p1 = pa[1];
        ar[0] = ffma2(wr, p0.x, ar[0]); az[0] = ffma2(wz, p0.x, az[0]); an[0] = ffma2(wn, p0.x, an[0]);
        ar[1] = ffma2(wr, p0.y, ar[1]); az[1] = ffma2(wz, p0.y, az[1]); an[1] = ffma2(wn, p0.y, an[1]);
        ar[2] = ffma2(wr, p1.x, ar[2]); az[2] = ffma2(wz, p1.x, az[2]); an[2] = ffma2(wn, p1.x, an[2]);
        ar[3] = ffma2(wr, p1.y, ar[3]); az[3] = ffma2(wz, p1.y, az[3]); an[3] = ffma2(wn, p1.y, an[3]);
    }
}

__device__ __forceinline__ void issue_chunk(int cid, float* slot, int tid)
{
    const float4* g = (const float4*)(g_wcat + (size_t)cid * CHUNK_FLOATS);
    float4* d = (float4*)slot;
    #pragma unroll
    for (int i = 0; i < 3; i++)
        cp16((float*)(d + tid + i * NTHR), g + tid + i * NTHR);
    asm volatile("cp.async.commit_group;");
}

__global__ __launch_bounds__(NTHR, 1) void k_gru(
    const float* __restrict__ bih0, const float* __restrict__ bhh0,
    const float* __restrict__ bih1, const float* __restrict__ bhh1)
{
    extern __shared__ __align__(16) float smem[];
    float* h0buf = smem;                       /* [128][PAD] */
    float* h1buf = smem + 128 * PAD;           /* [128][PAD] */
    float* xt    = smem + 256 * PAD;           /* [32][PAD]  */
    ull*   bias_u = (ull*)(smem + SM_BIAS);    /* [8][128]   */
    float* wring  = smem + SM_RING;            /* [2][CHUNK_FLOATS] */
    const int tid = threadIdx.x;
    const int j   = tid & 127;
    const int s0  = (tid >> 7) * 8;            /* 8 seqs per thread */
    const int nbase = blockIdx.x * STILE;

    for (int i = tid; i < 256 * PAD; i += NTHR) smem[i] = 0.f;   /* h0 = h1 = 0 */
    if (tid < 128) {
        bias_u[0 * 128 + tid] = pack2s(bih0[tid] + bhh0[tid]);
        bias_u[1 * 128 + tid] = pack2s(bih0[128 + tid] + bhh0[128 + tid]);
        bias_u[2 * 128 + tid] = pack2s(bih0[256 + tid]);
        bias_u[3 * 128 + tid] = pack2s(bhh0[256 + tid]);
        bias_u[4 * 128 + tid] = pack2s(bih1[tid] + bhh1[tid]);
        bias_u[5 * 128 + tid] = pack2s(bih1[128 + tid] + bhh1[128 + tid]);
        bias_u[6 * 128 + tid] = pack2s(bih1[256 + tid]);
        bias_u[7 * 128 + tid] = pack2s(bhh1[256 + tid]);
    }

    /* ring prologue: chunks 0 and 1 in flight */
    issue_chunk(0, wring, tid);
    issue_chunk(1, wring + CHUNK_FLOATS, tid);
    int cc = 0;

    ull ar[4], az[4], ai[4], ah[4];
    ull hn[4];

#define RING_STEP(SRC, TGT)                                                        \
    do {                                                                           \
        asm volatile("cp.async.wait_group 1;");                                    \
        __syncthreads();                                                           \
        compute_chunk(wring + (cc & 1) * CHUNK_FLOATS, (SRC), j, s0, ar, az, (TGT)); \
        __syncthreads();                                                           \
        issue_chunk((cc + 2) % NCHUNK, wring + (cc & 1) * CHUNK_FLOATS, tid);      \
        cc++;                                                                      \
    } while (0)

    for (int t = 0; t < NNODES; t++) {
        /* load & transpose this step's inputs: 64 seqs x 32 feats */
        const float* srcx = g_x32 + ((size_t)t * NSEQ + nbase) * COUT;
        #pragma unroll
        for (int rep = 0; rep < 2; rep++) {
            int e = tid + rep * NTHR;
            xt[(e & 31) * PAD + (e >> 5)] = srcx[e];
        }
        /* xt stores ordered by RING_STEP's pre-compute barrier */

        /* ---- cell 0 ---- */
        {
            ull b0 = bias_u[0 * 128 + j], b1 = bias_u[1 * 128 + j];
            ull b2 = bias_u[2 * 128 + j], b3 = bias_u[3 * 128 + j];
            #pragma unroll
            for (int u = 0; u < 4; u++) { ar[u] = b0; az[u] = b1; ai[u] = b2; ah[u] = b3; }
        }
        RING_STEP(xt, ai);                              /* chunk 0: wih0 @ x_t (32 rows) */
        #pragma unroll 1
        for (int q = 0; q < 4; q++)
            RING_STEP(h0buf + q * 32 * PAD, ah);        /* chunks 1-4: whh0 @ h0 */
        /* epilogue 0 (reads old h0) */
        #pragma unroll
        for (int u = 0; u < 4; u++) {
            float2 hold = *(const float2*)(h0buf + j * PAD + s0 + 2 * u);
            float2 R = unpk(ar[u]), Z = unpk(az[u]), I = unpk(ai[u]), H = unpk(ah[u]);
            float r0 = sigm(R.x), z0 = sigm(Z.x);
            float n0 = tanhf(I.x + r0 * H.x);
            float o0 = (1.f - z0) * n0 + z0 * hold.x;
            float r1 = sigm(R.y), z1 = sigm(Z.y);
            float n1 = tanhf(I.y + r1 * H.y);
            float o1 = (1.f - z1) * n1 + z1 * hold.y;
            hn[u] = pack2(o0, o1);
        }
        __syncthreads();
        #pragma unroll
        for (int u = 0; u < 4; u++)
            *(ull*)(h0buf + j * PAD + s0 + 2 * u) = hn[u];
        /* h0 stores ordered by next RING_STEP barrier */

        /* ---- cell 1 ---- */
        {
            ull b0 = bias_u[4 * 128 + j], b1 = bias_u[5 * 128 + j];
            ull b2 = bias_u[6 * 128 + j], b3 = bias_u[7 * 128 + j];
            #pragma unroll
            for (int u = 0; u < 4; u++) { ar[u] = b0; az[u] = b1; ai[u] = b2; ah[u] = b3; }
        }
        #pragma unroll 1
        for (int q = 0; q < 4; q++)
            RING_STEP(h0buf + q * 32 * PAD, ai);        /* chunks 5-8: wih1 @ h0_new */
        #pragma unroll 1
        for (int q = 0; q < 4; q++)
            RING_STEP(h1buf + q * 32 * PAD, ah);        /* chunks 9-12: whh1 @ h1 */
        /* epilogue 1 (reads old h1) */
        #pragma unroll
        for (int u = 0; u < 4; u++) {
            float2 hold = *(const float2*)(h1buf + j * PAD + s0 + 2 * u);
            float2 R = unpk(ar[u]), Z = unpk(az[u]), I = unpk(ai[u]), H = unpk(ah[u]);
            float r0 = sigm(R.x), z0 = sigm(Z.x);
            float n0 = tanhf(I.x + r0 * H.x);
            float o0 = (1.f - z0) * n0 + z0 * hold.x;
            float r1 = sigm(R.y), z1 = sigm(Z.y);
            float n1 = tanhf(I.y + r1 * H.y);
            float o1 = (1.f - z1) * n1 + z1 * hold.y;
            hn[u] = pack2(o0, o1);
        }
        __syncthreads();
        #pragma unroll
        for (int u = 0; u < 4; u++)
            *(ull*)(h1buf + j * PAD + s0 + 2 * u) = hn[u];
        /* h1/xt reuse ordered by next step's RING_STEP barrier */
    }
#undef RING_STEP

    asm volatile("cp.async.wait_group 0;");

    /* hn holds the final (t = 23) layer-1 state for this thread's 8 seqs */
    #pragma unroll
    for (int u = 0; u < 4; u++) {
        int s = s0 + 2 * u;
        float2 v = unpk(hn[u]);
        g_last[(size_t)(nbase + s) * RH + j]     = v.x;
        g_last[(size_t)(nbase + s + 1) * RH + j] = v.y;
    }
}

/* ==================== K3: mean over routes + head MLP ==================== */
__global__ __launch_bounds__(128) void k_final(
    const float* __restrict__ cand,
    const float* __restrict__ cand_w, const float* __restrict__ cand_b,
    const float* __restrict__ fc1w, const float* __restrict__ fc1b,
    const float* __restrict__ fc2w, const float* __restrict__ fc2b,
    const float* __restrict__ fc3w, const float* __restrict__ fc3b,
    float* __restrict__ out)
{
    __shared__ float xr[RH + 64];
    __shared__ float h[128];
    __shared__ float red[128];
    const int b = blockIdx.x, tid = threadIdx.x;

    {
        const float* base = g_last + (size_t)b * NROUTES * RH;
        float acc = 0.f;
        #pragma unroll 8
        for (int r = 0; r < NROUTES; r++) acc += base[r * RH + tid];
        xr[tid] = acc * (1.f / NROUTES);
    }
    if (tid < 64) {
        float a = cand_b[tid];
        #pragma unroll 8
        for (int i = 0; i < 2 * FEAT; i++)
            a += cand[b * 2 * FEAT + i] * cand_w[i * 64 + tid];
        xr[RH + tid] = a;
    }
    __syncthreads();

    {
        float a = fc1b[tid];
        #pragma unroll 8
        for (int i = 0; i < RH + 64; i++) a += xr[i] * fc1w[i * 128 + tid];
        h[tid] = tanhf(a);
    }
    __syncthreads();
    {
        float a = fc2b[tid];
        #pragma unroll 8
        for (int i = 0; i < 128; i++) a += h[i] * fc2w[i * 128 + tid];
        red[tid] = tanhf(a) * fc3w[tid];
    }
    __syncthreads();
    for (int s = 64; s > 0; s >>= 1) {
        if (tid < s) red[tid] += red[tid + s];
        __syncthreads();
    }
    if (tid == 0) out[b] = red[0] + fc3b[0];
}

/* ==================== launch ==================== */
extern "C" void kernel_launch(void* const* d_in, const int* in_sizes, int n_in,
                              void* d_out, int out_size)
{
    const float* candidates = (const float*)d_in[0];
    const float* customers  = (const float*)d_in[1];
    const float* cust_w1 = (const float*)d_in[2];
    const float* cust_b1 = (const float*)d_in[3];
    const float* cust_w2 = (const float*)d_in[4];
    const float* cust_b2 = (const float*)d_in[5];
    const float* wih0 = (const float*)d_in[6];
    const float* whh0 = (const float*)d_in[7];
    const float* bih0 = (const float*)d_in[8];
    const float* bhh0 = (const float*)d_in[9];
    const float* wih1 = (const float*)d_in[10];
    const float* whh1 = (const float*)d_in[11];
    const float* bih1 = (const float*)d_in[12];
    const float* bhh1 = (const float*)d_in[13];
    const float* cand_w = (const float*)d_in[14];
    const float* cand_b = (const float*)d_in[15];
    const float* fc1w = (const float*)d_in[16];
    const float* fc1b = (const float*)d_in[17];
    const float* fc2w = (const float*)d_in[18];
    const float* fc2b = (const float*)d_in[19];
    const float* fc3w = (const float*)d_in[20];
    const float* fc3b = (const float*)d_in[21];

    cudaFuncSetAttribute(k_gru, cudaFuncAttributeMaxDynamicSharedMemorySize, K2_SMEM);

    k_prep_gru<<<(416 * 384 + 255) / 256, 256>>>(wih0, whh0, wih1, whh1);
    k_prep_cust<<<(FEAT * CH + CH * COUT + 255) / 256, 256>>>(cust_w1, cust_w2);
    k_cust<<<NROWS / K1_ROWS, 256>>>(customers, cust_b1, cust_b2);
    k_gru<<<NSEQ / STILE, NTHR, K2_SMEM>>>(bih0, bhh0, bih1, bhh1);
    k_final<<<BATCH, 128>>>(candidates, cand_w, cand_b,
                            fc1w, fc1b, fc2w, fc2b, fc3w, fc3b,
                            (float*)d_out);
}

// round 8
// speedup vs baseline: 1.2658x; 1.0560x over previous
#include <cuda_runtime.h>
#include <math.h>
#include <stdint.h>
#include <stddef.h>

#define FEAT    36
#define NNODES  24
#define NROUTES 48
#define CH      128
#define COUT    32
#define RH      128
#define BATCH   512
#define NSEQ    (BATCH * NROUTES)     /* 24576 */
#define G3      (3 * RH)              /* 384   */
#define NROWS   (NNODES * NSEQ)       /* 589824 */

typedef unsigned long long ull;

/* ---- packed f32x2 helpers (SASS FFMA2 path, only reachable via PTX) ---- */
__device__ __forceinline__ ull pack2s(float x) {
    ull r; asm("mov.b64 %0, {%1, %1};" : "=l"(r) : "f"(x)); return r;
}
__device__ __forceinline__ ull pack2(float x, float y) {
    ull r; asm("mov.b64 %0, {%1, %2};" : "=l"(r) : "f"(x), "f"(y)); return r;
}
__device__ __forceinline__ ull ffma2(ull a, ull b, ull c) {
    ull d; asm("fma.rn.f32x2 %0, %1, %2, %3;" : "=l"(d) : "l"(a), "l"(b), "l"(c)); return d;
}
__device__ __forceinline__ float2 unpk(ull v) {
    float lo, hi; asm("mov.b64 {%0, %1}, %2;" : "=f"(lo), "=f"(hi) : "l"(v));
    return make_float2(lo, hi);
}
__device__ __forceinline__ float sigm(float x) { return 1.f / (1.f + expf(-x)); }

__device__ __forceinline__ void cp16(float* dst, const float4* src) {
    unsigned s = (unsigned)__cvta_generic_to_shared(dst);
    asm volatile("cp.async.ca.shared.global [%0], [%1], 16;" :: "r"(s), "l"(src));
}

/* scratch (no allocation allowed -> __device__ globals) */
__device__ float g_x32[(size_t)NROWS * COUT];   /* [t][n][32] node embeddings */
__device__ float g_last[(size_t)NSEQ * RH];     /* last GRU hidden per sequence */

/* GRU weights (scalar floats) concatenated in streaming order:
   k-rows 0-31 wih0, 32-159 whh0, 160-287 wih1, 288-415 whh1; row = 384 gate cols */
#define KCH 32
#define CHUNK_FLOATS (KCH * G3)    /* 12288 floats = 49152 B */
#define NCHUNK 13
__device__ float g_wcat[NCHUNK * CHUNK_FLOATS];

__device__ ull g_w1d[FEAT * CH];   /* (w1,w1) pairs for k_cust */
__device__ ull g_w2d[CH * COUT];

/* ==================== prep kernels ==================== */
__global__ __launch_bounds__(256) void k_prep_gru(
    const float* __restrict__ wih0, const float* __restrict__ whh0,
    const float* __restrict__ wih1, const float* __restrict__ whh1)
{
    int idx = blockIdx.x * 256 + threadIdx.x;   /* over 416*384 */
    if (idx >= 416 * 384) return;
    int k = idx / 384, c = idx - k * 384;
    int kk; const float* src;
    if      (k < 32)  { kk = k;       src = wih0; }
    else if (k < 160) { kk = k - 32;  src = whh0; }
    else if (k < 288) { kk = k - 160; src = wih1; }
    else              { kk = k - 288; src = whh1; }
    g_wcat[idx] = src[kk * 384 + c];
}

__global__ __launch_bounds__(256) void k_prep_cust(
    const float* __restrict__ w1, const float* __restrict__ w2)
{
    int idx = blockIdx.x * 256 + threadIdx.x;
    if (idx < FEAT * CH) {
        float v = w1[idx];
        g_w1d[idx] = pack2(v, v);
    }
    int i2 = idx - FEAT * CH;
    if (i2 >= 0 && i2 < CH * COUT) {
        float v = w2[i2];
        g_w2d[i2] = pack2(v, v);
    }
}

/* ==================== K1: customer MLP 36->128(tanh)->32(tanh) ==================== */
#define K1_ROWS 64
#define XT_ST   68
#define HT_ST   68

__global__ __launch_bounds__(256) void k_cust(
    const float* __restrict__ cust,           /* [NSEQ][NNODES*FEAT] */
    const float* __restrict__ b1, const float* __restrict__ b2)
{
    __shared__ __align__(16) float xT[FEAT * XT_ST];
    __shared__ __align__(16) float hT[CH * HT_ST];
    const int tid = threadIdx.x;
    const long long row0 = (long long)blockIdx.x * K1_ROWS;   /* row = t*NSEQ + n */

    #pragma unroll
    for (int rep = 0; rep < K1_ROWS * FEAT / 256; rep++) {
        int e = tid + rep * 256;
        int s = e / FEAT, f = e - s * FEAT;
        long long row = row0 + s;
        int t = (int)(row / NSEQ);
        int n = (int)(row - (long long)t * NSEQ);
        xT[f * XT_ST + s] = cust[(size_t)n * (NNODES * FEAT) + t * FEAT + f];
    }
    __syncthreads();

    /* phase 1 */
    {
        const int j  = tid & 127;
        const int s0 = (tid >> 7) * 32;
        ull a[16];
        ull bb = pack2s(b1[j]);
        #pragma unroll
        for (int u = 0; u < 16; u++) a[u] = bb;
        #pragma unroll 4
        for (int i = 0; i < FEAT; i++) {
            ull w = g_w1d[i * CH + j];
            const ulonglong2* xp = (const ulonglong2*)(xT + i * XT_ST + s0);
            #pragma unroll
            for (int q = 0; q < 8; q++) {
                ulonglong2 v = xp[q];
                a[2 * q]     = ffma2(w, v.x, a[2 * q]);
                a[2 * q + 1] = ffma2(w, v.y, a[2 * q + 1]);
            }
        }
        float* hp = hT + j * HT_ST + s0;
        #pragma unroll
        for (int q = 0; q < 8; q++) {
            float2 p0 = unpk(a[2 * q]), p1 = unpk(a[2 * q + 1]);
            float4 o = make_float4(tanhf(p0.x), tanhf(p0.y), tanhf(p1.x), tanhf(p1.y));
            *(float4*)(hp + 4 * q) = o;
        }
    }
    __syncthreads();

    /* phase 2 */
    {
        const int j2 = tid & 31;
        const int s0 = (tid >> 5) * 8;
        ull a[4];
        ull bb = pack2s(b2[j2]);
        #pragma unroll
        for (int u = 0; u < 4; u++) a[u] = bb;
        #pragma unroll 4
        for (int k = 0; k < CH; k++) {
            ull w = g_w2d[k * COUT + j2];
            const ulonglong2* hp = (const ulonglong2*)(hT + k * HT_ST + s0);
            ulonglong2 v0 = hp[0], v1 = hp[1];
            a[0] = ffma2(w, v0.x, a[0]);
            a[1] = ffma2(w, v0.y, a[1]);
            a[2] = ffma2(w, v1.x, a[2]);
            a[3] = ffma2(w, v1.y, a[3]);
        }
        size_t base = (size_t)(row0 + s0) * COUT + j2;
        #pragma unroll
        for (int q = 0; q < 4; q++) {
            float2 p = unpk(a[q]);
            g_x32[base + (size_t)(2 * q) * COUT]     = tanhf(p.x);
            g_x32[base + (size_t)(2 * q + 1) * COUT] = tanhf(p.y);
        }
    }
}

/* ==================== K2: fused 2-layer GRU, 1024 thr, scalar-weight cp.async ring ==================== */
#define STILE   64
#define PAD     68
#define NTHR    1024
/* smem floats: state 288*PAD = 19584 | bias 8*128 ull = 2048 fl | ring 2*CHUNK_FLOATS */
#define SM_BIAS 19584
#define SM_RING (19584 + 2048)
#define K2_SMEM ((SM_RING + 2 * CHUNK_FLOATS) * 4)   /* 184832 B */

__device__ __forceinline__ void compute_chunk(
    const float* __restrict__ ws,    /* smem [KCH][384] scalar weights */
    const float* __restrict__ src,   /* smem activations, row-offset applied */
    int j, int s0,
    ull* __restrict__ ar, ull* __restrict__ az, ull* __restrict__ an)
{
    #pragma unroll 8
    for (int kl = 0; kl < KCH; kl++) {
        const float* wp = ws + kl * G3 + j;
        ull wr = pack2s(wp[0]);
        ull wz = pack2s(wp[128]);
        ull wn = pack2s(wp[256]);
        const ulonglong2* pa = (const ulonglong2*)(src + kl * PAD + s0);
        ulonglong2 p0 = pa[0], p1 = pa[1];
        ar[0] = ffma2(wr, p0.x, ar[0]); az[0] = ffma2(wz, p0.x, az[0]); an[0] = ffma2(wn, p0.x, an[0]);
        ar[1] = ffma2(wr, p0.y, ar[1]); az[1] = ffma2(wz, p0.y, az[1]); an[1] = ffma2(wn, p0.y, an[1]);
        ar[2] = ffma2(wr, p1.x, ar[2]); az[2] = ffma2(wz, p1.x, az[2]); an[2] = ffma2(wn, p1.x, an[2]);
        ar[3] = ffma2(wr, p1.y, ar[3]); az[3] = ffma2(wz, p1.y, az[3]); an[3] = ffma2(wn, p1.y, an[3]);
    }
}

__device__ __forceinline__ void issue_chunk(int cid, float* slot, int tid)
{
    const float4* g = (const float4*)(g_wcat + (size_t)cid * CHUNK_FLOATS);
    float4* d = (float4*)slot;
    #pragma unroll
    for (int i = 0; i < 3; i++)
        cp16((float*)(d + tid + i * NTHR), g + tid + i * NTHR);
    asm volatile("cp.async.commit_group;");
}

__global__ __launch_bounds__(NTHR, 1) void k_gru(
    const float* __restrict__ bih0, const float* __restrict__ bhh0,
    const float* __restrict__ bih1, const float* __restrict__ bhh1)
{
    extern __shared__ __align__(16) float smem[];
    float* h0buf = smem;                       /* [128][PAD] */
    float* h1buf = smem + 128 * PAD;           /* [128][PAD] */
    float* xt    = smem + 256 * PAD;           /* [32][PAD]  */
    ull*   bias_u = (ull*)(smem + SM_BIAS);    /* [8][128]   */
    float* wring  = smem + SM_RING;            /* [2][CHUNK_FLOATS] */
    const int tid = threadIdx.x;
    const int j   = tid & 127;
    const int s0  = (tid >> 7) * 8;            /* 8 seqs per thread */
    const int nbase = blockIdx.x * STILE;

    for (int i = tid; i < 256 * PAD; i += NTHR) smem[i] = 0.f;   /* h0 = h1 = 0 */
    if (tid < 128) {
        bias_u[0 * 128 + tid] = pack2s(bih0[tid] + bhh0[tid]);
        bias_u[1 * 128 + tid] = pack2s(bih0[128 + tid] + bhh0[128 + tid]);
        bias_u[2 * 128 + tid] = pack2s(bih0[256 + tid]);
        bias_u[3 * 128 + tid] = pack2s(bhh0[256 + tid]);
        bias_u[4 * 128 + tid] = pack2s(bih1[tid] + bhh1[tid]);
        bias_u[5 * 128 + tid] = pack2s(bih1[128 + tid] + bhh1[128 + tid]);
        bias_u[6 * 128 + tid] = pack2s(bih1[256 + tid]);
        bias_u[7 * 128 + tid] = pack2s(bhh1[256 + tid]);
    }

    /* ring prologue: chunks 0 and 1 in flight */
    issue_chunk(0, wring, tid);
    issue_chunk(1, wring + CHUNK_FLOATS, tid);
    int cc = 0;

    ull ar[4], az[4], ai[4], ah[4];
    ull hn[4];

#define RING_STEP(SRC, TGT)                                                        \
    do {                                                                           \
        asm volatile("cp.async.wait_group 1;");                                    \
        __syncthreads();                                                           \
        compute_chunk(wring + (cc & 1) * CHUNK_FLOATS, (SRC), j, s0, ar, az, (TGT)); \
        __syncthreads();                                                           \
        issue_chunk((cc + 2) % NCHUNK, wring + (cc & 1) * CHUNK_FLOATS, tid);      \
        cc++;                                                                      \
    } while (0)

    for (int t = 0; t < NNODES; t++) {
        /* load & transpose this step's inputs: 64 seqs x 32 feats */
        const float* srcx = g_x32 + ((size_t)t * NSEQ + nbase) * COUT;
        #pragma unroll
        for (int rep = 0; rep < 2; rep++) {
            int e = tid + rep * NTHR;
            xt[(e & 31) * PAD + (e >> 5)] = srcx[e];
        }
        /* xt stores ordered by RING_STEP's pre-compute barrier */

        /* ---- cell 0 ---- */
        {
            ull b0 = bias_u[0 * 128 + j], b1 = bias_u[1 * 128 + j];
            ull b2 = bias_u[2 * 128 + j], b3 = bias_u[3 * 128 + j];
            #pragma unroll
            for (int u = 0; u < 4; u++) { ar[u] = b0; az[u] = b1; ai[u] = b2; ah[u] = b3; }
        }
        RING_STEP(xt, ai);                              /* chunk 0: wih0 @ x_t (32 rows) */
        #pragma unroll 1
        for (int q = 0; q < 4; q++)
            RING_STEP(h0buf + q * 32 * PAD, ah);        /* chunks 1-4: whh0 @ h0 */
        /* epilogue 0 (reads old h0) */
        #pragma unroll
        for (int u = 0; u < 4; u++) {
            float2 hold = *(const float2*)(h0buf + j * PAD + s0 + 2 * u);
            float2 R = unpk(ar[u]), Z = unpk(az[u]), I = unpk(ai[u]), H = unpk(ah[u]);
            float r0 = sigm(R.x), z0 = sigm(Z.x);
            float n0 = tanhf(I.x + r0 * H.x);
            float o0 = (1.f - z0) * n0 + z0 * hold.x;
            float r1 = sigm(R.y), z1 = sigm(Z.y);
            float n1 = tanhf(I.y + r1 * H.y);
            float o1 = (1.f - z1) * n1 + z1 * hold.y;
            hn[u] = pack2(o0, o1);
        }
        __syncthreads();
        #pragma unroll
        for (int u = 0; u < 4; u++)
            *(ull*)(h0buf + j * PAD + s0 + 2 * u) = hn[u];
        /* h0 stores ordered by next RING_STEP barrier */

        /* ---- cell 1 ---- */
        {
            ull b0 = bias_u[4 * 128 + j], b1 = bias_u[5 * 128 + j];
            ull b2 = bias_u[6 * 128 + j], b3 = bias_u[7 * 128 + j];
            #pragma unroll
            for (int u = 0; u < 4; u++) { ar[u] = b0; az[u] = b1; ai[u] = b2; ah[u] = b3; }
        }
        #pragma unroll 1
        for (int q = 0; q < 4; q++)
            RING_STEP(h0buf + q * 32 * PAD, ai);        /* chunks 5-8: wih1 @ h0_new */
        #pragma unroll 1
        for (int q = 0; q < 4; q++)
            RING_STEP(h1buf + q * 32 * PAD, ah);        /* chunks 9-12: whh1 @ h1 */
        /* epilogue 1 (reads old h1) */
        #pragma unroll
        for (int u = 0; u < 4; u++) {
            float2 hold = *(const float2*)(h1buf + j * PAD + s0 + 2 * u);
            float2 R = unpk(ar[u]), Z = unpk(az[u]), I = unpk(ai[u]), H = unpk(ah[u]);
            float r0 = sigm(R.x), z0 = sigm(Z.x);
            float n0 = tanhf(I.x + r0 * H.x);
            float o0 = (1.f - z0) * n0 + z0 * hold.x;
            float r1 = sigm(R.y), z1 = sigm(Z.y);
            float n1 = tanhf(I.y + r1 * H.y);
            float o1 = (1.f - z1) * n1 + z1 * hold.y;
            hn[u] = pack2(o0, o1);
        }
        __syncthreads();
        #pragma unroll
        for (int u = 0; u < 4; u++)
            *(ull*)(h1buf + j * PAD + s0 + 2 * u) = hn[u];
        /* h1/xt reuse ordered by next step's RING_STEP barrier */
    }
#undef RING_STEP

    asm volatile("cp.async.wait_group 0;");

    /* hn holds the final (t = 23) layer-1 state for this thread's 8 seqs */
    #pragma unroll
    for (int u = 0; u < 4; u++) {
        int s = s0 + 2 * u;
        float2 v = unpk(hn[u]);
        g_last[(size_t)(nbase + s) * RH + j]     = v.x;
        g_last[(size_t)(nbase + s + 1) * RH + j] = v.y;
    }
}

/* ==================== K3: mean over routes + head MLP ==================== */
__global__ __launch_bounds__(128) void k_final(
    const float* __restrict__ cand,
    const float* __restrict__ cand_w, const float* __restrict__ cand_b,
    const float* __restrict__ fc1w, const float* __restrict__ fc1b,
    const float* __restrict__ fc2w, const float* __restrict__ fc2b,
    const float* __restrict__ fc3w, const float* __restrict__ fc3b,
    float* __restrict__ out)
{
    __shared__ float xr[RH + 64];
    __shared__ float h[128];
    __shared__ float red[128];
    const int b = blockIdx.x, tid = threadIdx.x;

    {
        const float* base = g_last + (size_t)b * NROUTES * RH;
        float acc = 0.f;
        #pragma unroll 8
        for (int r = 0; r < NROUTES; r++) acc += base[r * RH + tid];
        xr[tid] = acc * (1.f / NROUTES);
    }
    if (tid < 64) {
        float a = cand_b[tid];
        #pragma unroll 8
        for (int i = 0; i < 2 * FEAT; i++)
            a += cand[b * 2 * FEAT + i] * cand_w[i * 64 + tid];
        xr[RH + tid] = a;
    }
    __syncthreads();

    {
        float a = fc1b[tid];
        #pragma unroll 8
        for (int i = 0; i < RH + 64; i++) a += xr[i] * fc1w[i * 128 + tid];
        h[tid] = tanhf(a);
    }
    __syncthreads();
    {
        float a = fc2b[tid];
        #pragma unroll 8
        for (int i = 0; i < 128; i++) a += h[i] * fc2w[i * 128 + tid];
        red[tid] = tanhf(a) * fc3w[tid];
    }
    __syncthreads();
    for (int s = 64; s > 0; s >>= 1) {
        if (tid < s) red[tid] += red[tid + s];
        __syncthreads();
    }
    if (tid == 0) out[b] = red[0] + fc3b[0];
}

/* ==================== launch ==================== */
extern "C" void kernel_launch(void* const* d_in, const int* in_sizes, int n_in,
                              void* d_out, int out_size)
{
    const float* candidates = (const float*)d_in[0];
    const float* customers  = (const float*)d_in[1];
    const float* cust_w1 = (const float*)d_in[2];
    const float* cust_b1 = (const float*)d_in[3];
    const float* cust_w2 = (const float*)d_in[4];
    const float* cust_b2 = (const float*)d_in[5];
    const float* wih0 = (const float*)d_in[6];
    const float* whh0 = (const float*)d_in[7];
    const float* bih0 = (const float*)d_in[8];
    const float* bhh0 = (const float*)d_in[9];
    const float* wih1 = (const float*)d_in[10];
    const float* whh1 = (const float*)d_in[11];
    const float* bih1 = (const float*)d_in[12];
    const float* bhh1 = (const float*)d_in[13];
    const float* cand_w = (const float*)d_in[14];
    const float* cand_b = (const float*)d_in[15];
    const float* fc1w = (const float*)d_in[16];
    const float* fc1b = (const float*)d_in[17];
    const float* fc2w = (const float*)d_in[18];
    const float* fc2b = (const float*)d_in[19];
    const float* fc3w = (const float*)d_in[20];
    const float* fc3b = (const float*)d_in[21];

    cudaFuncSetAttribute(k_gru, cudaFuncAttributeMaxDynamicSharedMemorySize, K2_SMEM);

    k_prep_gru<<<(416 * 384 + 255) / 256, 256>>>(wih0, whh0, wih1, whh1);
    k_prep_cust<<<(FEAT * CH + CH * COUT + 255) / 256, 256>>>(cust_w1, cust_w2);
    k_cust<<<NROWS / K1_ROWS, 256>>>(customers, cust_b1, cust_b2);
    k_gru<<<NSEQ / STILE, NTHR, K2_SMEM>>>(bih0, bhh0, bih1, bhh1);
    k_final<<<BATCH, 128>>>(candidates, cand_w, cand_b,
                            fc1w, fc1b, fc2w, fc2b, fc3w, fc3b,
                            (float*)d_out);
}

// round 10
// speedup vs baseline: 2.4579x; 1.9418x over previous
#include <cuda_runtime.h>
#include <cuda_bf16.h>
#include <math.h>
#include <stdint.h>
#include <stddef.h>

#define FEAT    36
#define NNODES  24
#define NROUTES 48
#define CH      128
#define COUT    32
#define RH      128
#define BATCH   512
#define NSEQ    (BATCH * NROUTES)
#define G3      (3 * RH)
#define NROWS   (NNODES * NSEQ)

typedef unsigned long long ull;
typedef unsigned int u32;

/* ---- f32x2 helpers (k_cust scalar path) ---- */
__device__ __forceinline__ ull pack2s(float x) {
    ull r; asm("mov.b64 %0, {%1, %1};" : "=l"(r) : "f"(x)); return r;
}
__device__ __forceinline__ ull pack2(float x, float y) {
    ull r; asm("mov.b64 %0, {%1, %2};" : "=l"(r) : "f"(x), "f"(y)); return r;
}
__device__ __forceinline__ ull ffma2(ull a, ull b, ull c) {
    ull d; asm("fma.rn.f32x2 %0, %1, %2, %3;" : "=l"(d) : "l"(a), "l"(b), "l"(c)); return d;
}
__device__ __forceinline__ float2 unpk(ull v) {
    float lo, hi; asm("mov.b64 {%0, %1}, %2;" : "=f"(lo), "=f"(hi) : "l"(v));
    return make_float2(lo, hi);
}
__device__ __forceinline__ float sigm(float x) { return 1.f / (1.f + expf(-x)); }

__device__ __forceinline__ void cp16(float* dst, const float4* src) {
    unsigned s = (unsigned)__cvta_generic_to_shared(dst);
    asm volatile("cp.async.ca.shared.global [%0], [%1], 16;" :: "r"(s), "l"(src));
}
__device__ __forceinline__ u32 smem_u32(const void* p) {
    u32 a;
    asm("{ .reg .u64 t; cvta.to.shared.u64 t, %1; cvt.u32.u64 %0, t; }" : "=r"(a) : "l"(p));
    return a;
}

/* ---- HMMA helpers (sm_80 baseline features, valid on plain sm_103) ---- */
__device__ __forceinline__ void mma_bf16(float* c, const u32* a, u32 b0, u32 b1) {
    asm("mma.sync.aligned.m16n8k16.row.col.f32.bf16.bf16.f32 "
        "{%0,%1,%2,%3},{%4,%5,%6,%7},{%8,%9},{%0,%1,%2,%3};"
        : "+f"(c[0]), "+f"(c[1]), "+f"(c[2]), "+f"(c[3])
        : "r"(a[0]), "r"(a[1]), "r"(a[2]), "r"(a[3]), "r"(b0), "r"(b1));
}
__device__ __forceinline__ void ldsm_t2(u32& r0, u32& r1, u32 addr) {
    asm volatile("ldmatrix.sync.aligned.m8n8.x2.trans.shared.b16 {%0,%1}, [%2];"
                 : "=r"(r0), "=r"(r1) : "r"(addr));
}
__device__ __forceinline__ float bflo_f(u32 p) { return __uint_as_float(p << 16); }
__device__ __forceinline__ float bfhi_f(u32 p) { return __uint_as_float(p & 0xffff0000u); }

/* ---- device scratch ---- */
__device__ float g_x32[(size_t)NROWS * COUT];
__device__ float g_last[(size_t)NSEQ * RH];
__device__ uint4 g_wblob[26 * 2048];      /* 26 slices x 32KB A-fragment stream */
__device__ ull g_w1d[FEAT * CH];
__device__ ull g_w2d[CH * COUT];

/* ==================== prep: A-fragment blob (split-bf16) ====================
   Blob order: [slice 0..25][warp 16][frag 4: hi_t0,hi_t1,lo_t0,lo_t1][lane 32] x16B.
   Slices 0-9 = layer0 (2 ih over x, 8 hh over h0); 10-25 = layer1 (8 ih, 8 hh).
   A tile0 rows 0-7 = r-gates j0..j0+7, rows 8-15 = z-gates.
   A tile1 rows 0-7 = n-gate ih part (zero on hh slices), rows 8-15 = n-gate hh part. */
__global__ __launch_bounds__(256) void k_prep_gru(
    const float* __restrict__ wih0, const float* __restrict__ whh0,
    const float* __restrict__ wih1, const float* __restrict__ whh1)
{
    int idx = blockIdx.x * 256 + threadIdx.x;     /* bf16 element index */
    if (idx >= 26 * 16384) return;
    int off  = idx * 2;
    int sg   = off >> 15;                /* slice global 0..25 */
    int rem  = off & 32767;
    int wid  = rem >> 11;
    int rem2 = rem & 2047;
    int frag = rem2 >> 9;
    int rem3 = rem2 & 511;
    int lane = rem3 >> 4;
    int b    = rem3 & 15;
    int pos  = b >> 1;                   /* 0..7 bf16 within 16B */
    int areg = pos >> 1, elt = pos & 1;
    int row  = (lane >> 2) + (areg & 1) * 8;
    int col  = (lane & 3) * 2 + (areg >> 1) * 8 + elt;
    int tile = frag & 1, split = frag >> 1;
    int j    = wid * 8 + (row & 7);
    int phase = (sg < 10) ? 0 : 1;
    int sl    = phase ? sg - 10 : sg;
    int nih   = phase ? 8 : 2;
    bool is_ih = sl < nih;
    int k = (is_ih ? sl : sl - nih) * 16 + col;
    const float* W = phase == 0 ? (is_ih ? wih0 : whh0) : (is_ih ? wih1 : whh1);
    int gcol = (tile == 0) ? ((row < 8) ? j : 128 + j) : 256 + j;
    bool valid = (tile == 0) || ((row < 8) ? is_ih : !is_ih);
    float v = valid ? W[k * G3 + gcol] : 0.f;
    __nv_bfloat16 hb = __float2bfloat16(v);
    __nv_bfloat16 out = split ? __float2bfloat16(v - __bfloat162float(hb)) : hb;
    ((unsigned short*)g_wblob)[idx] = reinterpret_cast<unsigned short&>(out);
}

__global__ __launch_bounds__(256) void k_prep_cust(
    const float* __restrict__ w1, const float* __restrict__ w2)
{
    int idx = blockIdx.x * 256 + threadIdx.x;
    if (idx < FEAT * CH) { float v = w1[idx]; g_w1d[idx] = pack2(v, v); }
    int i2 = idx - FEAT * CH;
    if (i2 >= 0 && i2 < CH * COUT) { float v = w2[i2]; g_w2d[i2] = pack2(v, v); }
}

/* ==================== K1: customer MLP (R5 path, unchanged) ==================== */
#define K1_ROWS 64
#define XT_ST   68
#define HT_ST   68

__global__ __launch_bounds__(256) void k_cust(
    const float* __restrict__ cust,
    const float* __restrict__ b1, const float* __restrict__ b2)
{
    __shared__ __align__(16) float xT[FEAT * XT_ST];
    __shared__ __align__(16) float hT[CH * HT_ST];
    const int tid = threadIdx.x;
    const long long row0 = (long long)blockIdx.x * K1_ROWS;

    #pragma unroll
    for (int rep = 0; rep < K1_ROWS * FEAT / 256; rep++) {
        int e = tid + rep * 256;
        int s = e / FEAT, f = e - s * FEAT;
        long long row = row0 + s;
        int t = (int)(row / NSEQ);
        int n = (int)(row - (long long)t * NSEQ);
        xT[f * XT_ST + s] = cust[(size_t)n * (NNODES * FEAT) + t * FEAT + f];
    }
    __syncthreads();
    {
        const int j  = tid & 127;
        const int s0 = (tid >> 7) * 32;
        ull a[16];
        ull bb = pack2s(b1[j]);
        #pragma unroll
        for (int u = 0; u < 16; u++) a[u] = bb;
        #pragma unroll 4
        for (int i = 0; i < FEAT; i++) {
            ull w = g_w1d[i * CH + j];
            const ulonglong2* xp = (const ulonglong2*)(xT + i * XT_ST + s0);
            #pragma unroll
            for (int q = 0; q < 8; q++) {
                ulonglong2 v = xp[q];
                a[2 * q]     = ffma2(w, v.x, a[2 * q]);
                a[2 * q + 1] = ffma2(w, v.y, a[2 * q + 1]);
            }
        }
        float* hp = hT + j * HT_ST + s0;
        #pragma unroll
        for (int q = 0; q < 8; q++) {
            float2 p0 = unpk(a[2 * q]), p1 = unpk(a[2 * q + 1]);
            *(float4*)(hp + 4 * q) =
                make_float4(tanhf(p0.x), tanhf(p0.y), tanhf(p1.x), tanhf(p1.y));
        }
    }
    __syncthreads();
    {
        const int j2 = tid & 31;
        const int s0 = (tid >> 5) * 8;
        ull a[4];
        ull bb = pack2s(b2[j2]);
        #pragma unroll
        for (int u = 0; u < 4; u++) a[u] = bb;
        #pragma unroll 4
        for (int k = 0; k < CH; k++) {
            ull w = g_w2d[k * COUT + j2];
            const ulonglong2* hp = (const ulonglong2*)(hT + k * HT_ST + s0);
            ulonglong2 v0 = hp[0], v1 = hp[1];
            a[0] = ffma2(w, v0.x, a[0]);
            a[1] = ffma2(w, v0.y, a[1]);
            a[2] = ffma2(w, v1.x, a[2]);
            a[3] = ffma2(w, v1.y, a[3]);
        }
        size_t base = (size_t)(row0 + s0) * COUT + j2;
        #pragma unroll
        for (int q = 0; q < 4; q++) {
            float2 p = unpk(a[q]);
            g_x32[base + (size_t)(2 * q) * COUT]     = tanhf(p.x);
            g_x32[base + (size_t)(2 * q + 1) * COUT] = tanhf(p.y);
        }
    }
}

/* ==================== K2: HMMA GRU ==================== */
#define NTILE   64
#define BROW    144          /* B row stride bytes: 64 seqs*2B + 16 pad */
#define OFF_H0HI 0
#define OFF_H0LO 18432
#define OFF_H1HI 36864
#define OFF_H1LO 55296
#define OFF_XB   73728       /* +par*9216 +lo*4608 ; 2 parities */
#define OFF_STG  92160       /* 8KB staging */
#define GRU_SMEM 100352

template<int NSL, int NIH>
__device__ __forceinline__ void gemm_phase(
    const uint4* __restrict__ pA,   /* blob, pre-offset by warp+lane */
    u32 bih_hi, u32 bih_lo, u32 bhh_hi, u32 bhh_lo,
    int lane15, float* acc)
{
    uint4 a0 = pA[0], a1 = pA[32], a2 = pA[64], a3 = pA[96];
    #pragma unroll 1
    for (int sl = 0; sl < NSL; sl++) {
        uint4 n0, n1, n2, n3;
        if (sl + 1 < NSL) {
            const uint4* p = pA + (size_t)(sl + 1) * 2048;
            n0 = p[0]; n1 = p[32]; n2 = p[64]; n3 = p[96];
        }
        u32 rh, rl;
        if (sl < NIH) {
            rh = bih_hi + sl * 16 * BROW + lane15;
            rl = bih_lo + sl * 16 * BROW + lane15;
        } else {
            rh = bhh_hi + (sl - NIH) * 16 * BROW + lane15;
            rl = bhh_lo + (sl - NIH) * 16 * BROW + lane15;
        }
        #pragma unroll
        for (int nt = 0; nt < 8; nt++) {
            u32 bh0, bh1, bl0, bl1;
            ldsm_t2(bh0, bh1, rh + nt * 16);
            ldsm_t2(bl0, bl1, rl + nt * 16);
            float* c0 = acc + nt * 4;
            float* c1 = acc + 32 + nt * 4;
            mma_bf16(c0, (const u32*)&a0, bh0, bh1);
            mma_bf16(c0, (const u32*)&a0, bl0, bl1);
            mma_bf16(c0, (const u32*)&a2, bh0, bh1);
            mma_bf16(c1, (const u32*)&a1, bh0, bh1);
            mma_bf16(c1, (const u32*)&a1, bl0, bl1);
            mma_bf16(c1, (const u32*)&a3, bh0, bh1);
        }
        if (sl + 1 < NSL) { a0 = n0; a1 = n1; a2 = n2; a3 = n3; }
    }
}

__device__ __forceinline__ void gru_epilogue(
    const float* acc, float br, float bz, float bi, float bn,
    u32 rowhi, u32 rowlo, int sb,
    float* lastout, int j, int nbase)
{
    #pragma unroll
    for (int nt = 0; nt < 8; nt++) {
        int o = nt * 16 + sb;
        u32 ph, pl;
        asm volatile("ld.shared.b32 %0, [%1];" : "=r"(ph) : "r"(rowhi + o));
        asm volatile("ld.shared.b32 %0, [%1];" : "=r"(pl) : "r"(rowlo + o));
        float hold0 = bflo_f(ph) + bflo_f(pl);
        float hold1 = bfhi_f(ph) + bfhi_f(pl);
        float r0 = sigm(acc[nt * 4 + 0] + br);
        float r1 = sigm(acc[nt * 4 + 1] + br);
        float z0 = sigm(acc[nt * 4 + 2] + bz);
        float z1 = sigm(acc[nt * 4 + 3] + bz);
        float n0 = tanhf(acc[32 + nt * 4 + 0] + bi + r0 * (acc[32 + nt * 4 + 2] + bn));
        float n1 = tanhf(acc[32 + nt * 4 + 1] + bi + r1 * (acc[32 + nt * 4 + 3] + bn));
        float h0 = (1.f - z0) * n0 + z0 * hold0;
        float h1 = (1.f - z1) * n1 + z1 * hold1;
        u32 packh;
        asm("cvt.rn.bf16x2.f32 %0, %1, %2;" : "=r"(packh) : "f"(h1), "f"(h0));
        float l0 = h0 - bflo_f(packh);
        float l1 = h1 - bfhi_f(packh);
        u32 packl;
        asm("cvt.rn.bf16x2.f32 %0, %1, %2;" : "=r"(packl) : "f"(l1), "f"(l0));
        asm volatile("st.shared.b32 [%0], %1;" :: "r"(rowhi + o), "r"(packh) : "memory");
        asm volatile("st.shared.b32 [%0], %1;" :: "r"(rowlo + o), "r"(packl) : "memory");
        if (lastout) {
            int s = nt * 8 + (sb >> 1);
            lastout[(size_t)(nbase + s) * RH + j]     = h0;
            lastout[(size_t)(nbase + s + 1) * RH + j] = h1;
        }
    }
}

__device__ __forceinline__ void conv_x(const float* stg, char* smemc, int xoff, int tid)
{
    #pragma unroll
    for (int i = 0; i < 4; i++) {
        int e = 4 * tid + i;
        float v = stg[e];
        int s = e >> 5, f = e & 31;
        __nv_bfloat16 hb = __float2bfloat16(v);
        __nv_bfloat16 lb = __float2bfloat16(v - __bfloat162float(hb));
        *(__nv_bfloat16*)(smemc + xoff + f * BROW + s * 2) = hb;
        *(__nv_bfloat16*)(smemc + xoff + 4608 + f * BROW + s * 2) = lb;
    }
}

__global__ __launch_bounds__(512, 1) void k_gru(
    const float* __restrict__ bih0, const float* __restrict__ bhh0,
    const float* __restrict__ bih1, const float* __restrict__ bhh1)
{
    extern __shared__ __align__(16) char smem[];
    const int tid = threadIdx.x;
    const int wid = tid >> 5;
    const int lane = tid & 31;
    const int nbase = blockIdx.x * NTILE;
    const u32 sbase = smem_u32(smem);

    /* zero h/x regions */
    for (int i = tid; i < OFF_STG / 4; i += 512) ((u32*)smem)[i] = 0;

    const int j = wid * 8 + (lane >> 2);
    const float br0 = bih0[j] + bhh0[j];
    const float bz0 = bih0[128 + j] + bhh0[128 + j];
    const float bi0 = bih0[256 + j];
    const float bn0 = bhh0[256 + j];
    const float br1 = bih1[j] + bhh1[j];
    const float bz1 = bih1[128 + j] + bhh1[128 + j];
    const float bi1 = bih1[256 + j];
    const float bn1 = bhh1[256 + j];

    const int lane15 = (lane & 15) * BROW;
    const int sb = (lane & 3) * 4;
    const u32 hj0hi = sbase + OFF_H0HI + j * BROW;
    const u32 hj0lo = sbase + OFF_H0LO + j * BROW;
    const u32 hj1hi = sbase + OFF_H1HI + j * BROW;
    const u32 hj1lo = sbase + OFF_H1LO + j * BROW;

    const uint4* pb0 = g_wblob + (size_t)wid * 128 + lane;
    const uint4* pb1 = pb0 + (size_t)10 * 2048;
    float* stg = (float*)(smem + OFF_STG);

    /* prologue: stage & convert x(0) */
    {
        const float4* src = (const float4*)(g_x32 + (size_t)nbase * 32);
        cp16(stg + 4 * tid, src + tid);
        asm volatile("cp.async.commit_group;");
        asm volatile("cp.async.wait_group 0;");
        __syncthreads();                 /* zero-init visible before halfword writes */
        conv_x(stg, smem, OFF_XB, tid);
    }
    __syncthreads();

    float acc[64];

    for (int t = 0; t < NNODES; t++) {
        if (t < NNODES - 1) {
            const float4* src = (const float4*)(g_x32 + ((size_t)(t + 1) * NSEQ + nbase) * 32);
            cp16(stg + 4 * tid, src + tid);
            asm volatile("cp.async.commit_group;");
        }
        /* ---- layer 0 ---- */
        #pragma unroll
        for (int i = 0; i < 64; i++) acc[i] = 0.f;
        {
            u32 xh = sbase + OFF_XB + (t & 1) * 9216;
            gemm_phase<10, 2>(pb0, xh, xh + 4608,
                              sbase + OFF_H0HI, sbase + OFF_H0LO, lane15, acc);
        }
        __syncthreads();
        gru_epilogue(acc, br0, bz0, bi0, bn0, hj0hi, hj0lo, sb, (float*)0, j, nbase);
        if (t < NNODES - 1) {
            asm volatile("cp.async.wait_group 0;");
            conv_x(stg, smem, OFF_XB + ((t + 1) & 1) * 9216, tid);
        }
        __syncthreads();
        /* ---- layer 1 ---- */
        #pragma unroll
        for (int i = 0; i < 64; i++) acc[i] = 0.f;
        gemm_phase<16, 8>(pb1, sbase + OFF_H0HI, sbase + OFF_H0LO,
                          sbase + OFF_H1HI, sbase + OFF_H1LO, lane15, acc);
        __syncthreads();
        gru_epilogue(acc, br1, bz1, bi1, bn1, hj1hi, hj1lo, sb,
                     (t == NNODES - 1) ? g_last : (float*)0, j, nbase);
        __syncthreads();
    }
}

/* ==================== K3: mean over routes + head MLP ==================== */
__global__ __launch_bounds__(128) void k_final(
    const float* __restrict__ cand,
    const float* __restrict__ cand_w, const float* __restrict__ cand_b,
    const float* __restrict__ fc1w, const float* __restrict__ fc1b,
    const float* __restrict__ fc2w, const float* __restrict__ fc2b,
    const float* __restrict__ fc3w, const float* __restrict__ fc3b,
    float* __restrict__ out)
{
    __shared__ float xr[RH + 64];
    __shared__ float h[128];
    __shared__ float red[128];
    const int b = blockIdx.x, tid = threadIdx.x;
    {
        const float* base = g_last + (size_t)b * NROUTES * RH;
        float acc = 0.f;
        #pragma unroll 8
        for (int r = 0; r < NROUTES; r++) acc += base[r * RH + tid];
        xr[tid] = acc * (1.f / NROUTES);
    }
    if (tid < 64) {
        float a = cand_b[tid];
        #pragma unroll 8
        for (int i = 0; i < 2 * FEAT; i++)
            a += cand[b * 2 * FEAT + i] * cand_w[i * 64 + tid];
        xr[RH + tid] = a;
    }
    __syncthreads();
    {
        float a = fc1b[tid];
        #pragma unroll 8
        for (int i = 0; i < RH + 64; i++) a += xr[i] * fc1w[i * 128 + tid];
        h[tid] = tanhf(a);
    }
    __syncthreads();
    {
        float a = fc2b[tid];
        #pragma unroll 8
        for (int i = 0; i < 128; i++) a += h[i] * fc2w[i * 128 + tid];
        red[tid] = tanhf(a) * fc3w[tid];
    }
    __syncthreads();
    for (int s = 64; s > 0; s >>= 1) {
        if (tid < s) red[tid] += red[tid + s];
        __syncthreads();
    }
    if (tid == 0) out[b] = red[0] + fc3b[0];
}

/* ==================== launch ==================== */
extern "C" void kernel_launch(void* const* d_in, const int* in_sizes, int n_in,
                              void* d_out, int out_size)
{
    const float* candidates = (const float*)d_in[0];
    const float* customers  = (const float*)d_in[1];
    const float* cust_w1 = (const float*)d_in[2];
    const float* cust_b1 = (const float*)d_in[3];
    const float* cust_w2 = (const float*)d_in[4];
    const float* cust_b2 = (const float*)d_in[5];
    const float* wih0 = (const float*)d_in[6];
    const float* whh0 = (const float*)d_in[7];
    const float* bih0 = (const float*)d_in[8];
    const float* bhh0 = (const float*)d_in[9];
    const float* wih1 = (const float*)d_in[10];
    const float* whh1 = (const float*)d_in[11];
    const float* bih1 = (const float*)d_in[12];
    const float* bhh1 = (const float*)d_in[13];
    const float* cand_w = (const float*)d_in[14];
    const float* cand_b = (const float*)d_in[15];
    const float* fc1w = (const float*)d_in[16];
    const float* fc1b = (const float*)d_in[17];
    const float* fc2w = (const float*)d_in[18];
    const float* fc2b = (const float*)d_in[19];
    const float* fc3w = (const float*)d_in[20];
    const float* fc3b = (const float*)d_in[21];

    cudaFuncSetAttribute(k_gru, cudaFuncAttributeMaxDynamicSharedMemorySize, GRU_SMEM);

    k_prep_gru<<<(26 * 16384 + 255) / 256, 256>>>(wih0, whh0, wih1, whh1);
    k_prep_cust<<<(FEAT * CH + CH * COUT + 255) / 256, 256>>>(cust_w1, cust_w2);
    k_cust<<<NROWS / K1_ROWS, 256>>>(customers, cust_b1, cust_b2);
    k_gru<<<NSEQ / NTILE, 512, GRU_SMEM>>>(bih0, bhh0, bih1, bhh1);
    k_final<<<BATCH, 128>>>(candidates, cand_w, cand_b,
                            fc1w, fc1b, fc2w, fc2b, fc3w, fc3b,
                            (float*)d_out);
}

// round 11
// speedup vs baseline: 3.1359x; 1.2758x over previous
#include <cuda_runtime.h>
#include <cuda_bf16.h>
#include <cuda_fp16.h>
#include <math.h>
#include <stdint.h>
#include <stddef.h>

#define FEAT    36
#define NNODES  24
#define NROUTES 48
#define CH      128
#define COUT    32
#define RH      128
#define BATCH   512
#define NSEQ    (BATCH * NROUTES)
#define G3      (3 * RH)
#define NROWS   (NNODES * NSEQ)

typedef unsigned long long ull;
typedef unsigned int u32;

/* ---- f32x2 helpers (k_cust scalar path) ---- */
__device__ __forceinline__ ull pack2s(float x) {
    ull r; asm("mov.b64 %0, {%1, %1};" : "=l"(r) : "f"(x)); return r;
}
__device__ __forceinline__ ull pack2(float x, float y) {
    ull r; asm("mov.b64 %0, {%1, %2};" : "=l"(r) : "f"(x), "f"(y)); return r;
}
__device__ __forceinline__ ull ffma2(ull a, ull b, ull c) {
    ull d; asm("fma.rn.f32x2 %0, %1, %2, %3;" : "=l"(d) : "l"(a), "l"(b), "l"(c)); return d;
}
__device__ __forceinline__ float2 unpk(ull v) {
    float lo, hi; asm("mov.b64 {%0, %1}, %2;" : "=f"(lo), "=f"(hi) : "l"(v));
    return make_float2(lo, hi);
}
__device__ __forceinline__ float sigm(float x) { return 1.f / (1.f + expf(-x)); }

__device__ __forceinline__ void cp16(float* dst, const float4* src) {
    unsigned s = (unsigned)__cvta_generic_to_shared(dst);
    asm volatile("cp.async.ca.shared.global [%0], [%1], 16;" :: "r"(s), "l"(src));
}
__device__ __forceinline__ u32 smem_u32(const void* p) {
    u32 a;
    asm("{ .reg .u64 t; cvta.to.shared.u64 t, %1; cvt.u32.u64 %0, t; }" : "=r"(a) : "l"(p));
    return a;
}

/* ---- HMMA helpers (sm_80 baseline; valid on plain sm_103) ---- */
__device__ __forceinline__ void mma_f16(float* c, const u32* a, u32 b0, u32 b1) {
    asm("mma.sync.aligned.m16n8k16.row.col.f32.f16.f16.f32 "
        "{%0,%1,%2,%3},{%4,%5,%6,%7},{%8,%9},{%0,%1,%2,%3};"
        : "+f"(c[0]), "+f"(c[1]), "+f"(c[2]), "+f"(c[3])
        : "r"(a[0]), "r"(a[1]), "r"(a[2]), "r"(a[3]), "r"(b0), "r"(b1));
}
__device__ __forceinline__ void ldsm_t2(u32& r0, u32& r1, u32 addr) {
    asm volatile("ldmatrix.sync.aligned.m8n8.x2.trans.shared.b16 {%0,%1}, [%2];"
                 : "=r"(r0), "=r"(r1) : "r"(addr));
}
__device__ __forceinline__ float2 h2f2(u32 p) {
    __half2 h = *reinterpret_cast<__half2*>(&p);
    return __half22float2(h);
}

/* ---- device scratch ---- */
__device__ float g_x32[(size_t)NROWS * COUT];
__device__ float g_last[(size_t)NSEQ * RH];
__device__ uint4 g_wblob[26 * 2048];      /* 26 slices x 32KB A-fragment stream (fp16) */
__device__ ull g_w1d[FEAT * CH];
__device__ ull g_w2d[CH * COUT];

/* ==================== prep: A-fragment blob (split-fp16) ====================
   Blob order: [slice 0..25][warp 16][frag 4: hi_t0,hi_t1,lo_t0,lo_t1][lane 32] x16B.
   Slices 0-9 = layer0 (2 ih over x, 8 hh over h0); 10-25 = layer1 (8 ih, 8 hh).
   A tile0 rows 0-7 = r-gates, rows 8-15 = z-gates.
   A tile1 rows 0-7 = n-gate ih part (zero on hh slices), rows 8-15 = n-gate hh part. */
__global__ __launch_bounds__(256) void k_prep_gru(
    const float* __restrict__ wih0, const float* __restrict__ whh0,
    const float* __restrict__ wih1, const float* __restrict__ whh1)
{
    int idx = blockIdx.x * 256 + threadIdx.x;     /* fp16 element index */
    if (idx >= 26 * 16384) return;
    int off  = idx * 2;
    int sg   = off >> 15;
    int rem  = off & 32767;
    int wid  = rem >> 11;
    int rem2 = rem & 2047;
    int frag = rem2 >> 9;
    int rem3 = rem2 & 511;
    int lane = rem3 >> 4;
    int b    = rem3 & 15;
    int pos  = b >> 1;
    int areg = pos >> 1, elt = pos & 1;
    int row  = (lane >> 2) + (areg & 1) * 8;
    int col  = (lane & 3) * 2 + (areg >> 1) * 8 + elt;
    int tile = frag & 1, split = frag >> 1;
    int j    = wid * 8 + (row & 7);
    int phase = (sg < 10) ? 0 : 1;
    int sl    = phase ? sg - 10 : sg;
    int nih   = phase ? 8 : 2;
    bool is_ih = sl < nih;
    int k = (is_ih ? sl : sl - nih) * 16 + col;
    const float* W = phase == 0 ? (is_ih ? wih0 : whh0) : (is_ih ? wih1 : whh1);
    int gcol = (tile == 0) ? ((row < 8) ? j : 128 + j) : 256 + j;
    bool valid = (tile == 0) || ((row < 8) ? is_ih : !is_ih);
    float v = valid ? W[k * G3 + gcol] : 0.f;
    __half hb = __float2half(v);
    __half out = split ? __float2half(v - __half2float(hb)) : hb;
    ((unsigned short*)g_wblob)[idx] = reinterpret_cast<unsigned short&>(out);
}

__global__ __launch_bounds__(256) void k_prep_cust(
    const float* __restrict__ w1, const float* __restrict__ w2)
{
    int idx = blockIdx.x * 256 + threadIdx.x;
    if (idx < FEAT * CH) { float v = w1[idx]; g_w1d[idx] = pack2(v, v); }
    int i2 = idx - FEAT * CH;
    if (i2 >= 0 && i2 < CH * COUT) { float v = w2[i2]; g_w2d[i2] = pack2(v, v); }
}

/* ==================== K1: customer MLP (R5 path, unchanged) ==================== */
#define K1_ROWS 64
#define XT_ST   68
#define HT_ST   68

__global__ __launch_bounds__(256) void k_cust(
    const float* __restrict__ cust,
    const float* __restrict__ b1, const float* __restrict__ b2)
{
    __shared__ __align__(16) float xT[FEAT * XT_ST];
    __shared__ __align__(16) float hT[CH * HT_ST];
    const int tid = threadIdx.x;
    const long long row0 = (long long)blockIdx.x * K1_ROWS;

    #pragma unroll
    for (int rep = 0; rep < K1_ROWS * FEAT / 256; rep++) {
        int e = tid + rep * 256;
        int s = e / FEAT, f = e - s * FEAT;
        long long row = row0 + s;
        int t = (int)(row / NSEQ);
        int n = (int)(row - (long long)t * NSEQ);
        xT[f * XT_ST + s] = cust[(size_t)n * (NNODES * FEAT) + t * FEAT + f];
    }
    __syncthreads();
    {
        const int j  = tid & 127;
        const int s0 = (tid >> 7) * 32;
        ull a[16];
        ull bb = pack2s(b1[j]);
        #pragma unroll
        for (int u = 0; u < 16; u++) a[u] = bb;
        #pragma unroll 4
        for (int i = 0; i < FEAT; i++) {
            ull w = g_w1d[i * CH + j];
            const ulonglong2* xp = (const ulonglong2*)(xT + i * XT_ST + s0);
            #pragma unroll
            for (int q = 0; q < 8; q++) {
                ulonglong2 v = xp[q];
                a[2 * q]     = ffma2(w, v.x, a[2 * q]);
                a[2 * q + 1] = ffma2(w, v.y, a[2 * q + 1]);
            }
        }
        float* hp = hT + j * HT_ST + s0;
        #pragma unroll
        for (int q = 0; q < 8; q++) {
            float2 p0 = unpk(a[2 * q]), p1 = unpk(a[2 * q + 1]);
            *(float4*)(hp + 4 * q) =
                make_float4(tanhf(p0.x), tanhf(p0.y), tanhf(p1.x), tanhf(p1.y));
        }
    }
    __syncthreads();
    {
        const int j2 = tid & 31;
        const int s0 = (tid >> 5) * 8;
        ull a[4];
        ull bb = pack2s(b2[j2]);
        #pragma unroll
        for (int u = 0; u < 4; u++) a[u] = bb;
        #pragma unroll 4
        for (int k = 0; k < CH; k++) {
            ull w = g_w2d[k * COUT + j2];
            const ulonglong2* hp = (const ulonglong2*)(hT + k * HT_ST + s0);
            ulonglong2 v0 = hp[0], v1 = hp[1];
            a[0] = ffma2(w, v0.x, a[0]);
            a[1] = ffma2(w, v0.y, a[1]);
            a[2] = ffma2(w, v1.x, a[2]);
            a[3] = ffma2(w, v1.y, a[3]);
        }
        size_t base = (size_t)(row0 + s0) * COUT + j2;
        #pragma unroll
        for (int q = 0; q < 4; q++) {
            float2 p = unpk(a[q]);
            g_x32[base + (size_t)(2 * q) * COUT]     = tanhf(p.x);
            g_x32[base + (size_t)(2 * q + 1) * COUT] = tanhf(p.y);
        }
    }
}

/* ==================== K2: HMMA GRU (fp16, 4 MMAs/slice-nt) ==================== */
#define NTILE   64
#define BROW    144
#define OFF_H0HI 0
#define OFF_H0LO 18432
#define OFF_H1HI 36864
#define OFF_H1LO 55296
#define OFF_XB   73728       /* +par*4608 ; hi only, 2 parities */
#define OFF_STG  82944       /* 8KB staging */
#define GRU_SMEM 91136

template<int NSL, int NIH>
__device__ __forceinline__ void gemm_phase(
    const uint4* __restrict__ pA,
    u32 bih_hi, u32 bhh_hi,
    int lane15, float* acc)
{
    uint4 a0 = pA[0], a1 = pA[32], a2 = pA[64], a3 = pA[96];
    #pragma unroll 1
    for (int sl = 0; sl < NSL; sl++) {
        uint4 n0, n1, n2, n3;
        if (sl + 1 < NSL) {
            const uint4* p = pA + (size_t)(sl + 1) * 2048;
            n0 = p[0]; n1 = p[32]; n2 = p[64]; n3 = p[96];
        }
        u32 rh = (sl < NIH) ? (bih_hi + sl * 16 * BROW + lane15)
                            : (bhh_hi + (sl - NIH) * 16 * BROW + lane15);
        #pragma unroll
        for (int nt = 0; nt < 8; nt++) {
            u32 bh0, bh1;
            ldsm_t2(bh0, bh1, rh + nt * 16);
            float* c0 = acc + nt * 4;
            float* c1 = acc + 32 + nt * 4;
            mma_f16(c0, (const u32*)&a0, bh0, bh1);
            mma_f16(c0, (const u32*)&a2, bh0, bh1);
            mma_f16(c1, (const u32*)&a1, bh0, bh1);
            mma_f16(c1, (const u32*)&a3, bh0, bh1);
        }
        if (sl + 1 < NSL) { a0 = n0; a1 = n1; a2 = n2; a3 = n3; }
    }
}

__device__ __forceinline__ void gru_epilogue(
    const float* acc, float br, float bz, float bi, float bn,
    u32 rowhi, u32 rowlo, int sb,
    float* lastout, int j, int nbase)
{
    #pragma unroll
    for (int nt = 0; nt < 8; nt++) {
        int o = nt * 16 + sb;
        u32 ph, pl;
        asm volatile("ld.shared.b32 %0, [%1];" : "=r"(ph) : "r"(rowhi + o));
        asm volatile("ld.shared.b32 %0, [%1];" : "=r"(pl) : "r"(rowlo + o));
        float2 hh = h2f2(ph), hl = h2f2(pl);
        float hold0 = hh.x + hl.x;
        float hold1 = hh.y + hl.y;
        float r0 = sigm(acc[nt * 4 + 0] + br);
        float r1 = sigm(acc[nt * 4 + 1] + br);
        float z0 = sigm(acc[nt * 4 + 2] + bz);
        float z1 = sigm(acc[nt * 4 + 3] + bz);
        float n0 = tanhf(acc[32 + nt * 4 + 0] + bi + r0 * (acc[32 + nt * 4 + 2] + bn));
        float n1 = tanhf(acc[32 + nt * 4 + 1] + bi + r1 * (acc[32 + nt * 4 + 3] + bn));
        float h0 = (1.f - z0) * n0 + z0 * hold0;
        float h1 = (1.f - z1) * n1 + z1 * hold1;
        __half2 H2 = __floats2half2_rn(h0, h1);        /* x=lo seq, y=hi seq */
        float2 back = __half22float2(H2);
        __half2 L2 = __floats2half2_rn(h0 - back.x, h1 - back.y);
        u32 packh = *reinterpret_cast<u32*>(&H2);
        u32 packl = *reinterpret_cast<u32*>(&L2);
        asm volatile("st.shared.b32 [%0], %1;" :: "r"(rowhi + o), "r"(packh) : "memory");
        asm volatile("st.shared.b32 [%0], %1;" :: "r"(rowlo + o), "r"(packl) : "memory");
        if (lastout) {
            int s = nt * 8 + (sb >> 1);
            lastout[(size_t)(nbase + s) * RH + j]     = h0;
            lastout[(size_t)(nbase + s + 1) * RH + j] = h1;
        }
    }
}

__device__ __forceinline__ void conv_x(const float* stg, char* smemc, int xoff, int tid)
{
    #pragma unroll
    for (int i = 0; i < 4; i++) {
        int e = 4 * tid + i;
        float v = stg[e];
        int s = e >> 5, f = e & 31;
        *(__half*)(smemc + xoff + f * BROW + s * 2) = __float2half(v);
    }
}

__global__ __launch_bounds__(512, 1) void k_gru(
    const float* __restrict__ bih0, const float* __restrict__ bhh0,
    const float* __restrict__ bih1, const float* __restrict__ bhh1)
{
    extern __shared__ __align__(16) char smem[];
    const int tid = threadIdx.x;
    const int wid = tid >> 5;
    const int lane = tid & 31;
    const int nbase = blockIdx.x * NTILE;
    const u32 sbase = smem_u32(smem);

    for (int i = tid; i < OFF_STG / 4; i += 512) ((u32*)smem)[i] = 0;

    const int j = wid * 8 + (lane >> 2);
    const float br0 = bih0[j] + bhh0[j];
    const float bz0 = bih0[128 + j] + bhh0[128 + j];
    const float bi0 = bih0[256 + j];
    const float bn0 = bhh0[256 + j];
    const float br1 = bih1[j] + bhh1[j];
    const float bz1 = bih1[128 + j] + bhh1[128 + j];
    const float bi1 = bih1[256 + j];
    const float bn1 = bhh1[256 + j];

    const int lane15 = (lane & 15) * BROW;
    const int sb = (lane & 3) * 4;
    const u32 hj0hi = sbase + OFF_H0HI + j * BROW;
    const u32 hj0lo = sbase + OFF_H0LO + j * BROW;
    const u32 hj1hi = sbase + OFF_H1HI + j * BROW;
    const u32 hj1lo = sbase + OFF_H1LO + j * BROW;

    const uint4* pb0 = g_wblob + (size_t)wid * 128 + lane;
    const uint4* pb1 = pb0 + (size_t)10 * 2048;
    float* stg = (float*)(smem + OFF_STG);

    /* prologue: stage & convert x(0) */
    {
        const float4* src = (const float4*)(g_x32 + (size_t)nbase * 32);
        cp16(stg + 4 * tid, src + tid);
        asm volatile("cp.async.commit_group;");
        asm volatile("cp.async.wait_group 0;");
        __syncthreads();
        conv_x(stg, smem, OFF_XB, tid);
    }
    __syncthreads();

    float acc[64];

    for (int t = 0; t < NNODES; t++) {
        if (t < NNODES - 1) {
            const float4* src = (const float4*)(g_x32 + ((size_t)(t + 1) * NSEQ + nbase) * 32);
            cp16(stg + 4 * tid, src + tid);
            asm volatile("cp.async.commit_group;");
        }
        /* ---- layer 0 ---- */
        #pragma unroll
        for (int i = 0; i < 64; i++) acc[i] = 0.f;
        gemm_phase<10, 2>(pb0, sbase + OFF_XB + (t & 1) * 4608,
                          sbase + OFF_H0HI, lane15, acc);
        __syncthreads();
        gru_epilogue(acc, br0, bz0, bi0, bn0, hj0hi, hj0lo, sb, (float*)0, j, nbase);
        if (t < NNODES - 1) {
            asm volatile("cp.async.wait_group 0;");
            conv_x(stg, smem, OFF_XB + ((t + 1) & 1) * 4608, tid);
        }
        __syncthreads();
        /* ---- layer 1 ---- */
        #pragma unroll
        for (int i = 0; i < 64; i++) acc[i] = 0.f;
        gemm_phase<16, 8>(pb1, sbase + OFF_H0HI, sbase + OFF_H1HI, lane15, acc);
        __syncthreads();
        gru_epilogue(acc, br1, bz1, bi1, bn1, hj1hi, hj1lo, sb,
                     (t == NNODES - 1) ? g_last : (float*)0, j, nbase);
        __syncthreads();
    }
}

/* ==================== K3: mean over routes + head MLP ==================== */
__global__ __launch_bounds__(128) void k_final(
    const float* __restrict__ cand,
    const float* __restrict__ cand_w, const float* __restrict__ cand_b,
    const float* __restrict__ fc1w, const float* __restrict__ fc1b,
    const float* __restrict__ fc2w, const float* __restrict__ fc2b,
    const float* __restrict__ fc3w, const float* __restrict__ fc3b,
    float* __restrict__ out)
{
    __shared__ float xr[RH + 64];
    __shared__ float h[128];
    __shared__ float red[128];
    const int b = blockIdx.x, tid = threadIdx.x;
    {
        const float* base = g_last + (size_t)b * NROUTES * RH;
        float acc = 0.f;
        #pragma unroll 8
        for (int r = 0; r < NROUTES; r++) acc += base[r * RH + tid];
        xr[tid] = acc * (1.f / NROUTES);
    }
    if (tid < 64) {
        float a = cand_b[tid];
        #pragma unroll 8
        for (int i = 0; i < 2 * FEAT; i++)
            a += cand[b * 2 * FEAT + i] * cand_w[i * 64 + tid];
        xr[RH + tid] = a;
    }
    __syncthreads();
    {
        float a = fc1b[tid];
        #pragma unroll 8
        for (int i = 0; i < RH + 64; i++) a += xr[i] * fc1w[i * 128 + tid];
        h[tid] = tanhf(a);
    }
    __syncthreads();
    {
        float a = fc2b[tid];
        #pragma unroll 8
        for (int i = 0; i < 128; i++) a += h[i] * fc2w[i * 128 + tid];
        red[tid] = tanhf(a) * fc3w[tid];
    }
    __syncthreads();
    for (int s = 64; s > 0; s >>= 1) {
        if (tid < s) red[tid] += red[tid + s];
        __syncthreads();
    }
    if (tid == 0) out[b] = red[0] + fc3b[0];
}

/* ==================== launch ==================== */
extern "C" void kernel_launch(void* const* d_in, const int* in_sizes, int n_in,
                              void* d_out, int out_size)
{
    const float* candidates = (const float*)d_in[0];
    const float* customers  = (const float*)d_in[1];
    const float* cust_w1 = (const float*)d_in[2];
    const float* cust_b1 = (const float*)d_in[3];
    const float* cust_w2 = (const float*)d_in[4];
    const float* cust_b2 = (const float*)d_in[5];
    const float* wih0 = (const float*)d_in[6];
    const float* whh0 = (const float*)d_in[7];
    const float* bih0 = (const float*)d_in[8];
    const float* bhh0 = (const float*)d_in[9];
    const float* wih1 = (const float*)d_in[10];
    const float* whh1 = (const float*)d_in[11];
    const float* bih1 = (const float*)d_in[12];
    const float* bhh1 = (const float*)d_in[13];
    const float* cand_w = (const float*)d_in[14];
    const float* cand_b = (const float*)d_in[15];
    const float* fc1w = (const float*)d_in[16];
    const float* fc1b = (const float*)d_in[17];
    const float* fc2w = (const float*)d_in[18];
    const float* fc2b = (const float*)d_in[19];
    const float* fc3w = (const float*)d_in[20];
    const float* fc3b = (const float*)d_in[21];

    cudaFuncSetAttribute(k_gru, cudaFuncAttributeMaxDynamicSharedMemorySize, GRU_SMEM);

    k_prep_gru<<<(26 * 16384 + 255) / 256, 256>>>(wih0, whh0, wih1, whh1);
    k_prep_cust<<<(FEAT * CH + CH * COUT + 255) / 256, 256>>>(cust_w1, cust_w2);
    k_cust<<<NROWS / K1_ROWS, 256>>>(customers, cust_b1, cust_b2);
    k_gru<<<NSEQ / NTILE, 512, GRU_SMEM>>>(bih0, bhh0, bih1, bhh1);
    k_final<<<BATCH, 128>>>(candidates, cand_w, cand_b,
                            fc1w, fc1b, fc2w, fc2b, fc3w, fc3b,
                            (float*)d_out);
}

// round 13
// speedup vs baseline: 3.4032x; 1.0852x over previous
#include <cuda_runtime.h>
#include <cuda_fp16.h>
#include <math.h>
#include <stdint.h>
#include <stddef.h>

#define FEAT    36
#define NNODES  24
#define NROUTES 48
#define CH      128
#define COUT    32
#define RH      128
#define BATCH   512
#define NSEQ    (BATCH * NROUTES)
#define G3      (3 * RH)
#define NROWS   (NNODES * NSEQ)

typedef unsigned long long ull;
typedef unsigned int u32;

/* ---- f32x2 helpers (k_cust scalar path) ---- */
__device__ __forceinline__ ull pack2s(float x) {
    ull r; asm("mov.b64 %0, {%1, %1};" : "=l"(r) : "f"(x)); return r;
}
__device__ __forceinline__ ull pack2(float x, float y) {
    ull r; asm("mov.b64 %0, {%1, %2};" : "=l"(r) : "f"(x), "f"(y)); return r;
}
__device__ __forceinline__ ull ffma2(ull a, ull b, ull c) {
    ull d; asm("fma.rn.f32x2 %0, %1, %2, %3;" : "=l"(d) : "l"(a), "l"(b), "l"(c)); return d;
}
__device__ __forceinline__ float2 unpk(ull v) {
    float lo, hi; asm("mov.b64 {%0, %1}, %2;" : "=f"(lo), "=f"(hi) : "l"(v));
    return make_float2(lo, hi);
}

/* ---- fast gate nonlinearities (clamped; MUFU-based) ---- */
__device__ __forceinline__ float fsigm(float x) {
    x = fminf(fmaxf(x, -20.f), 20.f);
    float e = __expf(-x);
    return __fdividef(1.f, 1.f + e);
}
__device__ __forceinline__ float ftanh(float x) {
    x = fminf(fmaxf(x, -10.f), 10.f);
    float e = __expf(-2.f * x);
    return __fdividef(1.f - e, 1.f + e);
}

__device__ __forceinline__ void cp16(float* dst, const float4* src) {
    unsigned s = (unsigned)__cvta_generic_to_shared(dst);
    asm volatile("cp.async.ca.shared.global [%0], [%1], 16;" :: "r"(s), "l"(src));
}
__device__ __forceinline__ u32 smem_u32(const void* p) {
    u32 a;
    asm("{ .reg .u64 t; cvta.to.shared.u64 t, %1; cvt.u32.u64 %0, t; }" : "=r"(a) : "l"(p));
    return a;
}

/* ---- HMMA helpers (sm_80 baseline; valid on plain sm_103) ---- */
__device__ __forceinline__ void mma_f16(float* c, const u32* a, u32 b0, u32 b1) {
    asm("mma.sync.aligned.m16n8k16.row.col.f32.f16.f16.f32 "
        "{%0,%1,%2,%3},{%4,%5,%6,%7},{%8,%9},{%0,%1,%2,%3};"
        : "+f"(c[0]), "+f"(c[1]), "+f"(c[2]), "+f"(c[3])
        : "r"(a[0]), "r"(a[1]), "r"(a[2]), "r"(a[3]), "r"(b0), "r"(b1));
}
__device__ __forceinline__ void ldsm_t2(u32& r0, u32& r1, u32 addr) {
    asm volatile("ldmatrix.sync.aligned.m8n8.x2.trans.shared.b16 {%0,%1}, [%2];"
                 : "=r"(r0), "=r"(r1) : "r"(addr));
}

/* ---- device scratch ---- */
__device__ float g_x32[(size_t)NROWS * COUT];
__device__ float g_last[(size_t)NSEQ * RH];
__device__ uint4 g_wblob[26 * 2048];      /* 26 slices x 32KB A-fragment stream (fp16) */
__device__ ull g_w1d[FEAT * CH];
__device__ ull g_w2d[CH * COUT];

/* ==================== prep: A-fragment blob (split-fp16) ==================== */
__global__ __launch_bounds__(256) void k_prep_gru(
    const float* __restrict__ wih0, const float* __restrict__ whh0,
    const float* __restrict__ wih1, const float* __restrict__ whh1)
{
    int idx = blockIdx.x * 256 + threadIdx.x;     /* fp16 element index */
    if (idx >= 26 * 16384) return;
    int off  = idx * 2;
    int sg   = off >> 15;
    int rem  = off & 32767;
    int wid  = rem >> 11;
    int rem2 = rem & 2047;
    int frag = rem2 >> 9;
    int rem3 = rem2 & 511;
    int lane = rem3 >> 4;
    int b    = rem3 & 15;
    int pos  = b >> 1;
    int areg = pos >> 1, elt = pos & 1;
    int row  = (lane >> 2) + (areg & 1) * 8;
    int col  = (lane & 3) * 2 + (areg >> 1) * 8 + elt;
    int tile = frag & 1, split = frag >> 1;
    int j    = wid * 8 + (row & 7);
    int phase = (sg < 10) ? 0 : 1;
    int sl    = phase ? sg - 10 : sg;
    int nih   = phase ? 8 : 2;
    bool is_ih = sl < nih;
    int k = (is_ih ? sl : sl - nih) * 16 + col;
    const float* W = phase == 0 ? (is_ih ? wih0 : whh0) : (is_ih ? wih1 : whh1);
    int gcol = (tile == 0) ? ((row < 8) ? j : 128 + j) : 256 + j;
    bool valid = (tile == 0) || ((row < 8) ? is_ih : !is_ih);
    float v = valid ? W[k * G3 + gcol] : 0.f;
    __half hb = __float2half(v);
    __half out = split ? __float2half(v - __half2float(hb)) : hb;
    ((unsigned short*)g_wblob)[idx] = reinterpret_cast<unsigned short&>(out);
}

__global__ __launch_bounds__(256) void k_prep_cust(
    const float* __restrict__ w1, const float* __restrict__ w2)
{
    int idx = blockIdx.x * 256 + threadIdx.x;
    if (idx < FEAT * CH) { float v = w1[idx]; g_w1d[idx] = pack2(v, v); }
    int i2 = idx - FEAT * CH;
    if (i2 >= 0 && i2 < CH * COUT) { float v = w2[i2]; g_w2d[i2] = pack2(v, v); }
}

/* ==================== K1: customer MLP ==================== */
#define K1_ROWS 64
#define XT_ST   68
#define HT_ST   68

__global__ __launch_bounds__(256) void k_cust(
    const float* __restrict__ cust,
    const float* __restrict__ b1, const float* __restrict__ b2)
{
    __shared__ __align__(16) float xT[FEAT * XT_ST];
    __shared__ __align__(16) float hT[CH * HT_ST];
    const int tid = threadIdx.x;
    const long long row0 = (long long)blockIdx.x * K1_ROWS;

    #pragma unroll
    for (int rep = 0; rep < K1_ROWS * FEAT / 256; rep++) {
        int e = tid + rep * 256;
        int s = e / FEAT, f = e - s * FEAT;
        long long row = row0 + s;
        int t = (int)(row / NSEQ);
        int n = (int)(row - (long long)t * NSEQ);
        xT[f * XT_ST + s] = cust[(size_t)n * (NNODES * FEAT) + t * FEAT + f];
    }
    __syncthreads();
    {
        const int j  = tid & 127;
        const int s0 = (tid >> 7) * 32;
        ull a[16];
        ull bb = pack2s(b1[j]);
        #pragma unroll
        for (int u = 0; u < 16; u++) a[u] = bb;
        #pragma unroll 4
        for (int i = 0; i < FEAT; i++) {
            ull w = g_w1d[i * CH + j];
            const ulonglong2* xp = (const ulonglong2*)(xT + i * XT_ST + s0);
            #pragma unroll
            for (int q = 0; q < 8; q++) {
                ulonglong2 v = xp[q];
                a[2 * q]     = ffma2(w, v.x, a[2 * q]);
                a[2 * q + 1] = ffma2(w, v.y, a[2 * q + 1]);
            }
        }
        float* hp = hT + j * HT_ST + s0;
        #pragma unroll
        for (int q = 0; q < 8; q++) {
            float2 p0 = unpk(a[2 * q]), p1 = unpk(a[2 * q + 1]);
            *(float4*)(hp + 4 * q) =
                make_float4(ftanh(p0.x), ftanh(p0.y), ftanh(p1.x), ftanh(p1.y));
        }
    }
    __syncthreads();
    {
        const int j2 = tid & 31;
        const int s0 = (tid >> 5) * 8;
        ull a[4];
        ull bb = pack2s(b2[j2]);
        #pragma unroll
        for (int u = 0; u < 4; u++) a[u] = bb;
        #pragma unroll 4
        for (int k = 0; k < CH; k++) {
            ull w = g_w2d[k * COUT + j2];
            const ulonglong2* hp = (const ulonglong2*)(hT + k * HT_ST + s0);
            ulonglong2 v0 = hp[0], v1 = hp[1];
            a[0] = ffma2(w, v0.x, a[0]);
            a[1] = ffma2(w, v0.y, a[1]);
            a[2] = ffma2(w, v1.x, a[2]);
            a[3] = ffma2(w, v1.y, a[3]);
        }
        size_t base = (size_t)(row0 + s0) * COUT + j2;
        #pragma unroll
        for (int q = 0; q < 4; q++) {
            float2 p = unpk(a[q]);
            g_x32[base + (size_t)(2 * q) * COUT]     = ftanh(p.x);
            g_x32[base + (size_t)(2 * q + 1) * COUT] = ftanh(p.y);
        }
    }
}

/* ==================== K2: HMMA GRU, double-buffered h planes, fp32 carry ==================== */
#define NTILE   64
#define BROW    144
#define OFF_H0HI 0            /* 2 planes x 18432 */
#define OFF_H1HI 36864        /* 2 planes x 18432 */
#define OFF_F32  73728        /* 2 layers x 512 threads x 18 floats (72B, 8-aligned) */
#define OFF_XB   147456       /* 2 x 4608 */
#define OFF_STG  156672       /* 8KB staging */
#define GRU_SMEM 164864

template<int NSL, int NIH>
__device__ __forceinline__ void gemm_phase(
    const uint4* __restrict__ pA,
    u32 bih_hi, u32 bhh_hi,
    int lane15, float* acc)
{
    uint4 a0 = pA[0], a1 = pA[32], a2 = pA[64], a3 = pA[96];
    #pragma unroll 1
    for (int sl = 0; sl < NSL; sl++) {
        uint4 n0, n1, n2, n3;
        if (sl + 1 < NSL) {
            const uint4* p = pA + (size_t)(sl + 1) * 2048;
            n0 = p[0]; n1 = p[32]; n2 = p[64]; n3 = p[96];
        }
        u32 rh = (sl < NIH) ? (bih_hi + sl * 16 * BROW + lane15)
                            : (bhh_hi + (sl - NIH) * 16 * BROW + lane15);
        #pragma unroll
        for (int nt = 0; nt < 8; nt++) {
            u32 bh0, bh1;
            ldsm_t2(bh0, bh1, rh + nt * 16);
            float* c0 = acc + nt * 4;
            float* c1 = acc + 32 + nt * 4;
            mma_f16(c0, (const u32*)&a0, bh0, bh1);
            mma_f16(c0, (const u32*)&a2, bh0, bh1);
            mma_f16(c1, (const u32*)&a1, bh0, bh1);
            mma_f16(c1, (const u32*)&a3, bh0, bh1);
        }
        if (sl + 1 < NSL) { a0 = n0; a1 = n1; a2 = n2; a3 = n3; }
    }
}

__device__ __forceinline__ void gru_epilogue(
    const float* acc, float br, float bz, float bi, float bn,
    u32 rowhi_w,      /* write plane (p^1) row for this j */
    u32 rowf,         /* private fp32 carry: 16 floats + pad (72B stride, 8-aligned) */
    int sb, float* lastout, int j, int nbase)
{
    #pragma unroll
    for (int nt = 0; nt < 8; nt++) {
        int o = nt * 16 + sb;
        float2 hold;
        asm volatile("ld.shared.v2.f32 {%0,%1}, [%2];"
                     : "=f"(hold.x), "=f"(hold.y) : "r"(rowf + nt * 8));
        float r0 = fsigm(acc[nt * 4 + 0] + br);
        float r1 = fsigm(acc[nt * 4 + 1] + br);
        float z0 = fsigm(acc[nt * 4 + 2] + bz);
        float z1 = fsigm(acc[nt * 4 + 3] + bz);
        float n0 = ftanh(acc[32 + nt * 4 + 0] + bi + r0 * (acc[32 + nt * 4 + 2] + bn));
        float n1 = ftanh(acc[32 + nt * 4 + 1] + bi + r1 * (acc[32 + nt * 4 + 3] + bn));
        float h0 = (1.f - z0) * n0 + z0 * hold.x;
        float h1 = (1.f - z1) * n1 + z1 * hold.y;
        asm volatile("st.shared.v2.f32 [%0], {%1,%2};"
                     :: "r"(rowf + nt * 8), "f"(h0), "f"(h1) : "memory");
        __half2 H2 = __floats2half2_rn(h0, h1);
        u32 packh = *reinterpret_cast<u32*>(&H2);
        asm volatile("st.shared.b32 [%0], %1;" :: "r"(rowhi_w + o), "r"(packh) : "memory");
        if (lastout) {
            int s = nt * 8 + (sb >> 1);
            lastout[(size_t)(nbase + s) * RH + j]     = h0;
            lastout[(size_t)(nbase + s + 1) * RH + j] = h1;
        }
    }
}

__device__ __forceinline__ void conv_x(const float* stg, char* smemc, int xoff, int tid)
{
    #pragma unroll
    for (int i = 0; i < 4; i++) {
        int e = 4 * tid + i;
        float v = stg[e];
        int s = e >> 5, f = e & 31;
        *(__half*)(smemc + xoff + f * BROW + s * 2) = __float2half(v);
    }
}

__global__ __launch_bounds__(512, 1) void k_gru(
    const float* __restrict__ bih0, const float* __restrict__ bhh0,
    const float* __restrict__ bih1, const float* __restrict__ bhh1)
{
    extern __shared__ __align__(16) char smem[];
    const int tid = threadIdx.x;
    const int wid = tid >> 5;
    const int lane = tid & 31;
    const int nbase = blockIdx.x * NTILE;
    const u32 sbase = smem_u32(smem);

    /* zero h-hi planes (both buffers) + fp32 carry planes */
    for (int i = tid; i < OFF_XB / 4; i += 512) ((u32*)smem)[i] = 0;

    const int j = wid * 8 + (lane >> 2);
    const float br0 = bih0[j] + bhh0[j];
    const float bz0 = bih0[128 + j] + bhh0[128 + j];
    const float bi0 = bih0[256 + j];
    const float bn0 = bhh0[256 + j];
    const float br1 = bih1[j] + bhh1[j];
    const float bz1 = bih1[128 + j] + bhh1[128 + j];
    const float bi1 = bih1[256 + j];
    const float bn1 = bhh1[256 + j];

    const int lane15 = (lane & 15) * BROW;
    const int sb = (lane & 3) * 4;
    const u32 rowf0 = sbase + OFF_F32 + tid * 72;           /* 18 floats, 8-aligned */
    const u32 rowf1 = rowf0 + 36864;

    const uint4* pb0 = g_wblob + (size_t)wid * 128 + lane;
    const uint4* pb1 = pb0 + (size_t)10 * 2048;
    float* stg = (float*)(smem + OFF_STG);

    /* prologue: stage & convert x(0) into x-buffer 0 */
    {
        const float4* src = (const float4*)(g_x32 + (size_t)nbase * 32);
        cp16(stg + 4 * tid, src + tid);
        asm volatile("cp.async.commit_group;");
        asm volatile("cp.async.wait_group 0;");
        conv_x(stg, smem, OFF_XB, tid);
    }
    __syncthreads();

    float acc[64];

    for (int t = 0; t < NNODES; t++) {
        const int p = t & 1;
        if (t < NNODES - 1) {
            const float4* src = (const float4*)(g_x32 + ((size_t)(t + 1) * NSEQ + nbase) * 32);
            cp16(stg + 4 * tid, src + tid);
            asm volatile("cp.async.commit_group;");
        }
        /* ---- layer 0: GEMM reads x[p], h0hi[p]; epi writes h0hi[p^1] ---- */
        #pragma unroll
        for (int i = 0; i < 64; i++) acc[i] = 0.f;
        gemm_phase<10, 2>(pb0, sbase + OFF_XB + p * 4608,
                          sbase + OFF_H0HI + p * 18432, lane15, acc);
        gru_epilogue(acc, br0, bz0, bi0, bn0,
                     sbase + OFF_H0HI + (p ^ 1) * 18432 + j * BROW,
                     rowf0, sb, (float*)0, j, nbase);
        __syncthreads();      /* h0hi[p^1] complete for all warps */

        /* ---- layer 1: GEMM reads h0hi[p^1], h1hi[p]; epi writes h1hi[p^1] ---- */
        #pragma unroll
        for (int i = 0; i < 64; i++) acc[i] = 0.f;
        gemm_phase<16, 8>(pb1, sbase + OFF_H0HI + (p ^ 1) * 18432,
                          sbase + OFF_H1HI + p * 18432, lane15, acc);
        gru_epilogue(acc, br1, bz1, bi1, bn1,
                     sbase + OFF_H1HI + (p ^ 1) * 18432 + j * BROW,
                     rowf1, sb, (t == NNODES - 1) ? g_last : (float*)0, j, nbase);
        if (t < NNODES - 1) {
            asm volatile("cp.async.wait_group 0;");
            conv_x(stg, smem, OFF_XB + ((t + 1) & 1) * 4608, tid);
        }
        __syncthreads();      /* h1hi[p^1] + x(t+1) complete */
    }
}

/* ==================== K3: mean over routes + head MLP ==================== */
__global__ __launch_bounds__(128) void k_final(
    const float* __restrict__ cand,
    const float* __restrict__ cand_w, const float* __restrict__ cand_b,
    const float* __restrict__ fc1w, const float* __restrict__ fc1b,
    const float* __restrict__ fc2w, const float* __restrict__ fc2b,
    const float* __restrict__ fc3w, const float* __restrict__ fc3b,
    float* __restrict__ out)
{
    __shared__ float xr[RH + 64];
    __shared__ float h[128];
    __shared__ float red[128];
    const int b = blockIdx.x, tid = threadIdx.x;
    {
        const float* base = g_last + (size_t)b * NROUTES * RH;
        float acc = 0.f;
        #pragma unroll 8
        for (int r = 0; r < NROUTES; r++) acc += base[r * RH + tid];
        xr[tid] = acc * (1.f / NROUTES);
    }
    if (tid < 64) {
        float a = cand_b[tid];
        #pragma unroll 8
        for (int i = 0; i < 2 * FEAT; i++)
            a += cand[b * 2 * FEAT + i] * cand_w[i * 64 + tid];
        xr[RH + tid] = a;
    }
    __syncthreads();
    {
        float a = fc1b[tid];
        #pragma unroll 8
        for (int i = 0; i < RH + 64; i++) a += xr[i] * fc1w[i * 128 + tid];
        h[tid] = tanhf(a);
    }
    __syncthreads();
    {
        float a = fc2b[tid];
        #pragma unroll 8
        for (int i = 0; i < 128; i++) a += h[i] * fc2w[i * 128 + tid];
        red[tid] = tanhf(a) * fc3w[tid];
    }
    __syncthreads();
    for (int s = 64; s > 0; s >>= 1) {
        if (tid < s) red[tid] += red[tid + s];
        __syncthreads();
    }
    if (tid == 0) out[b] = red[0] + fc3b[0];
}

/* ==================== launch ==================== */
extern "C" void kernel_launch(void* const* d_in, const int* in_sizes, int n_in,
                              void* d_out, int out_size)
{
    const float* candidates = (const float*)d_in[0];
    const float* customers  = (const float*)d_in[1];
    const float* cust_w1 = (const float*)d_in[2];
    const float* cust_b1 = (const float*)d_in[3];
    const float* cust_w2 = (const float*)d_in[4];
    const float* cust_b2 = (const float*)d_in[5];
    const float* wih0 = (const float*)d_in[6];
    const float* whh0 = (const float*)d_in[7];
    const float* bih0 = (const float*)d_in[8];
    const float* bhh0 = (const float*)d_in[9];
    const float* wih1 = (const float*)d_in[10];
    const float* whh1 = (const float*)d_in[11];
    const float* bih1 = (const float*)d_in[12];
    const float* bhh1 = (const float*)d_in[13];
    const float* cand_w = (const float*)d_in[14];
    const float* cand_b = (const float*)d_in[15];
    const float* fc1w = (const float*)d_in[16];
    const float* fc1b = (const float*)d_in[17];
    const float* fc2w = (const float*)d_in[18];
    const float* fc2b = (const float*)d_in[19];
    const float* fc3w = (const float*)d_in[20];
    const float* fc3b = (const float*)d_in[21];

    cudaFuncSetAttribute(k_gru, cudaFuncAttributeMaxDynamicSharedMemorySize, GRU_SMEM);

    k_prep_gru<<<(26 * 16384 + 255) / 256, 256>>>(wih0, whh0, wih1, whh1);
    k_prep_cust<<<(FEAT * CH + CH * COUT + 255) / 256, 256>>>(cust_w1, cust_w2);
    k_cust<<<NROWS / K1_ROWS, 256>>>(customers, cust_b1, cust_b2);
    k_gru<<<NSEQ / NTILE, 512, GRU_SMEM>>>(bih0, bhh0, bih1, bhh1);
    k_final<<<BATCH, 128>>>(candidates, cand_w, cand_b,
                            fc1w, fc1b, fc2w, fc2b, fc3w, fc3b,
                            (float*)d_out);
}

// round 14
// speedup vs baseline: 3.7550x; 1.1034x over previous
#include <cuda_runtime.h>
#include <cuda_fp16.h>
#include <math.h>
#include <stdint.h>
#include <stddef.h>

#define FEAT    36
#define NNODES  24
#define NROUTES 48
#define CH      128
#define COUT    32
#define RH      128
#define BATCH   512
#define NSEQ    (BATCH * NROUTES)
#define G3      (3 * RH)
#define NROWS   (NNODES * NSEQ)

typedef unsigned long long ull;
typedef unsigned int u32;

/* ---- f32x2 helpers (k_cust scalar path) ---- */
__device__ __forceinline__ ull pack2s(float x) {
    ull r; asm("mov.b64 %0, {%1, %1};" : "=l"(r) : "f"(x)); return r;
}
__device__ __forceinline__ ull pack2(float x, float y) {
    ull r; asm("mov.b64 %0, {%1, %2};" : "=l"(r) : "f"(x), "f"(y)); return r;
}
__device__ __forceinline__ ull ffma2(ull a, ull b, ull c) {
    ull d; asm("fma.rn.f32x2 %0, %1, %2, %3;" : "=l"(d) : "l"(a), "l"(b), "l"(c)); return d;
}
__device__ __forceinline__ float2 unpk(ull v) {
    float lo, hi; asm("mov.b64 {%0, %1}, %2;" : "=f"(lo), "=f"(hi) : "l"(v));
    return make_float2(lo, hi);
}

/* ---- fast gate nonlinearities (clamped; MUFU-based) ---- */
__device__ __forceinline__ float fsigm(float x) {
    x = fminf(fmaxf(x, -20.f), 20.f);
    float e = __expf(-x);
    return __fdividef(1.f, 1.f + e);
}
__device__ __forceinline__ float ftanh(float x) {
    x = fminf(fmaxf(x, -10.f), 10.f);
    float e = __expf(-2.f * x);
    return __fdividef(1.f - e, 1.f + e);
}

__device__ __forceinline__ void cp16(float* dst, const float4* src) {
    unsigned s = (unsigned)__cvta_generic_to_shared(dst);
    asm volatile("cp.async.ca.shared.global [%0], [%1], 16;" :: "r"(s), "l"(src));
}
__device__ __forceinline__ u32 smem_u32(const void* p) {
    u32 a;
    asm("{ .reg .u64 t; cvta.to.shared.u64 t, %1; cvt.u32.u64 %0, t; }" : "=r"(a) : "l"(p));
    return a;
}

/* ---- HMMA helpers (sm_80 baseline; valid on plain sm_103) ---- */
__device__ __forceinline__ void mma_f16(float* c, const u32* a, u32 b0, u32 b1) {
    asm("mma.sync.aligned.m16n8k16.row.col.f32.f16.f16.f32 "
        "{%0,%1,%2,%3},{%4,%5,%6,%7},{%8,%9},{%0,%1,%2,%3};"
        : "+f"(c[0]), "+f"(c[1]), "+f"(c[2]), "+f"(c[3])
        : "r"(a[0]), "r"(a[1]), "r"(a[2]), "r"(a[3]), "r"(b0), "r"(b1));
}
__device__ __forceinline__ void ldsm_t2(u32& r0, u32& r1, u32 addr) {
    asm volatile("ldmatrix.sync.aligned.m8n8.x2.trans.shared.b16 {%0,%1}, [%2];"
                 : "=r"(r0), "=r"(r1) : "r"(addr));
}

/* ---- device scratch ---- */
__device__ float g_x32[(size_t)NROWS * COUT];
__device__ float g_last[(size_t)NSEQ * RH];
__device__ uint4 g_wblob[26 * 2048];      /* 26 slices x 32KB A-fragment stream (fp16) */
__device__ ull g_w1d[FEAT * CH];
__device__ ull g_w2d[CH * COUT];

/* ==================== prep: A-fragment blob (split-fp16) ==================== */
__global__ __launch_bounds__(256) void k_prep_gru(
    const float* __restrict__ wih0, const float* __restrict__ whh0,
    const float* __restrict__ wih1, const float* __restrict__ whh1)
{
    int idx = blockIdx.x * 256 + threadIdx.x;     /* fp16 element index */
    if (idx >= 26 * 16384) return;
    int off  = idx * 2;
    int sg   = off >> 15;
    int rem  = off & 32767;
    int wid  = rem >> 11;
    int rem2 = rem & 2047;
    int frag = rem2 >> 9;
    int rem3 = rem2 & 511;
    int lane = rem3 >> 4;
    int b    = rem3 & 15;
    int pos  = b >> 1;
    int areg = pos >> 1, elt = pos & 1;
    int row  = (lane >> 2) + (areg & 1) * 8;
    int col  = (lane & 3) * 2 + (areg >> 1) * 8 + elt;
    int tile = frag & 1, split = frag >> 1;
    int j    = wid * 8 + (row & 7);
    int phase = (sg < 10) ? 0 : 1;
    int sl    = phase ? sg - 10 : sg;
    int nih   = phase ? 8 : 2;
    bool is_ih = sl < nih;
    int k = (is_ih ? sl : sl - nih) * 16 + col;
    const float* W = phase == 0 ? (is_ih ? wih0 : whh0) : (is_ih ? wih1 : whh1);
    int gcol = (tile == 0) ? ((row < 8) ? j : 128 + j) : 256 + j;
    bool valid = (tile == 0) || ((row < 8) ? is_ih : !is_ih);
    float v = valid ? W[k * G3 + gcol] : 0.f;
    __half hb = __float2half(v);
    __half out = split ? __float2half(v - __half2float(hb)) : hb;
    ((unsigned short*)g_wblob)[idx] = reinterpret_cast<unsigned short&>(out);
}

__global__ __launch_bounds__(256) void k_prep_cust(
    const float* __restrict__ w1, const float* __restrict__ w2)
{
    int idx = blockIdx.x * 256 + threadIdx.x;
    if (idx < FEAT * CH) { float v = w1[idx]; g_w1d[idx] = pack2(v, v); }
    int i2 = idx - FEAT * CH;
    if (i2 >= 0 && i2 < CH * COUT) { float v = w2[i2]; g_w2d[i2] = pack2(v, v); }
}

/* ==================== K1: customer MLP ==================== */
#define K1_ROWS 64
#define XT_ST   68
#define HT_ST   68

__global__ __launch_bounds__(256) void k_cust(
    const float* __restrict__ cust,
    const float* __restrict__ b1, const float* __restrict__ b2)
{
    __shared__ __align__(16) float xT[FEAT * XT_ST];
    __shared__ __align__(16) float hT[CH * HT_ST];
    const int tid = threadIdx.x;
    const long long row0 = (long long)blockIdx.x * K1_ROWS;

    #pragma unroll
    for (int rep = 0; rep < K1_ROWS * FEAT / 256; rep++) {
        int e = tid + rep * 256;
        int s = e / FEAT, f = e - s * FEAT;
        long long row = row0 + s;
        int t = (int)(row / NSEQ);
        int n = (int)(row - (long long)t * NSEQ);
        xT[f * XT_ST + s] = cust[(size_t)n * (NNODES * FEAT) + t * FEAT + f];
    }
    __syncthreads();
    {
        const int j  = tid & 127;
        const int s0 = (tid >> 7) * 32;
        ull a[16];
        ull bb = pack2s(b1[j]);
        #pragma unroll
        for (int u = 0; u < 16; u++) a[u] = bb;
        #pragma unroll 4
        for (int i = 0; i < FEAT; i++) {
            ull w = g_w1d[i * CH + j];
            const ulonglong2* xp = (const ulonglong2*)(xT + i * XT_ST + s0);
            #pragma unroll
            for (int q = 0; q < 8; q++) {
                ulonglong2 v = xp[q];
                a[2 * q]     = ffma2(w, v.x, a[2 * q]);
                a[2 * q + 1] = ffma2(w, v.y, a[2 * q + 1]);
            }
        }
        float* hp = hT + j * HT_ST + s0;
        #pragma unroll
        for (int q = 0; q < 8; q++) {
            float2 p0 = unpk(a[2 * q]), p1 = unpk(a[2 * q + 1]);
            *(float4*)(hp + 4 * q) =
                make_float4(ftanh(p0.x), ftanh(p0.y), ftanh(p1.x), ftanh(p1.y));
        }
    }
    __syncthreads();
    {
        const int j2 = tid & 31;
        const int s0 = (tid >> 5) * 8;
        ull a[4];
        ull bb = pack2s(b2[j2]);
        #pragma unroll
        for (int u = 0; u < 4; u++) a[u] = bb;
        #pragma unroll 4
        for (int k = 0; k < CH; k++) {
            ull w = g_w2d[k * COUT + j2];
            const ulonglong2* hp = (const ulonglong2*)(hT + k * HT_ST + s0);
            ulonglong2 v0 = hp[0], v1 = hp[1];
            a[0] = ffma2(w, v0.x, a[0]);
            a[1] = ffma2(w, v0.y, a[1]);
            a[2] = ffma2(w, v1.x, a[2]);
            a[3] = ffma2(w, v1.y, a[3]);
        }
        size_t base = (size_t)(row0 + s0) * COUT + j2;
        #pragma unroll
        for (int q = 0; q < 4; q++) {
            float2 p = unpk(a[q]);
            g_x32[base + (size_t)(2 * q) * COUT]     = ftanh(p.x);
            g_x32[base + (size_t)(2 * q + 1) * COUT] = ftanh(p.y);
        }
    }
}

/* ==================== K2: HMMA GRU, pipelined B fragments ==================== */
#define NTILE   64
#define BROW    144
#define OFF_H0HI 0            /* 2 planes x 18432 */
#define OFF_H1HI 36864        /* 2 planes x 18432 */
#define OFF_F32  73728        /* 2 layers x 512 threads x 18 floats (72B, 8-aligned) */
#define OFF_XB   147456       /* 2 x 4608 */
#define OFF_STG  156672       /* 8KB staging */
#define GRU_SMEM 164864

template<int NSL, int NIH>
__device__ __forceinline__ void gemm_phase(
    const uint4* __restrict__ pA,
    u32 bih_hi, u32 bhh_hi,
    int lane15, float* acc)
{
    uint4 a0 = pA[0], a1 = pA[32], a2 = pA[64], a3 = pA[96];
    #pragma unroll 1
    for (int sl = 0; sl < NSL; sl++) {
        u32 rh = (sl < NIH) ? (bih_hi + sl * 16 * BROW + lane15)
                            : (bhh_hi + (sl - NIH) * 16 * BROW + lane15);
        /* batch all 8 B-fragment pairs up front: ldsm latency overlaps
           with the first MMAs; removes the per-nt scoreboard bubble */
        u32 b[16];
        #pragma unroll
        for (int nt = 0; nt < 8; nt++)
            ldsm_t2(b[2 * nt], b[2 * nt + 1], rh + nt * 16);
        /* prefetch next slice's A fragments (L2 hit ~250cyc, covered by 32 MMAs) */
        uint4 n0, n1, n2, n3;
        if (sl + 1 < NSL) {
            const uint4* p = pA + (size_t)(sl + 1) * 2048;
            n0 = p[0]; n1 = p[32]; n2 = p[64]; n3 = p[96];
        }
        /* pass 1: hi-W MMAs — 16 independent accumulator chains */
        #pragma unroll
        for (int nt = 0; nt < 8; nt++) {
            mma_f16(acc + nt * 4,      (const u32*)&a0, b[2 * nt], b[2 * nt + 1]);
            mma_f16(acc + 32 + nt * 4, (const u32*)&a1, b[2 * nt], b[2 * nt + 1]);
        }
        /* pass 2: lo-W accumulates */
        #pragma unroll
        for (int nt = 0; nt < 8; nt++) {
            mma_f16(acc + nt * 4,      (const u32*)&a2, b[2 * nt], b[2 * nt + 1]);
            mma_f16(acc + 32 + nt * 4, (const u32*)&a3, b[2 * nt], b[2 * nt + 1]);
        }
        if (sl + 1 < NSL) { a0 = n0; a1 = n1; a2 = n2; a3 = n3; }
    }
}

__device__ __forceinline__ void gru_epilogue(
    const float* acc, float br, float bz, float bi, float bn,
    u32 rowhi_w,      /* write plane (p^1) row for this j */
    u32 rowf,         /* private fp32 carry: 16 floats + pad (72B stride, 8-aligned) */
    int sb, float* lastout, int j, int nbase)
{
    #pragma unroll
    for (int nt = 0; nt < 8; nt++) {
        int o = nt * 16 + sb;
        float2 hold;
        asm volatile("ld.shared.v2.f32 {%0,%1}, [%2];"
                     : "=f"(hold.x), "=f"(hold.y) : "r"(rowf + nt * 8));
        float r0 = fsigm(acc[nt * 4 + 0] + br);
        float r1 = fsigm(acc[nt * 4 + 1] + br);
        float z0 = fsigm(acc[nt * 4 + 2] + bz);
        float z1 = fsigm(acc[nt * 4 + 3] + bz);
        float n0 = ftanh(acc[32 + nt * 4 + 0] + bi + r0 * (acc[32 + nt * 4 + 2] + bn));
        float n1 = ftanh(acc[32 + nt * 4 + 1] + bi + r1 * (acc[32 + nt * 4 + 3] + bn));
        float h0 = (1.f - z0) * n0 + z0 * hold.x;
        float h1 = (1.f - z1) * n1 + z1 * hold.y;
        asm volatile("st.shared.v2.f32 [%0], {%1,%2};"
                     :: "r"(rowf + nt * 8), "f"(h0), "f"(h1) : "memory");
        __half2 H2 = __floats2half2_rn(h0, h1);
        u32 packh = *reinterpret_cast<u32*>(&H2);
        asm volatile("st.shared.b32 [%0], %1;" :: "r"(rowhi_w + o), "r"(packh) : "memory");
        if (lastout) {
            int s = nt * 8 + (sb >> 1);
            lastout[(size_t)(nbase + s) * RH + j]     = h0;
            lastout[(size_t)(nbase + s + 1) * RH + j] = h1;
        }
    }
}

__device__ __forceinline__ void conv_x(const float* stg, char* smemc, int xoff, int tid)
{
    #pragma unroll
    for (int i = 0; i < 4; i++) {
        int e = 4 * tid + i;
        float v = stg[e];
        int s = e >> 5, f = e & 31;
        *(__half*)(smemc + xoff + f * BROW + s * 2) = __float2half(v);
    }
}

__global__ __launch_bounds__(512, 1) void k_gru(
    const float* __restrict__ bih0, const float* __restrict__ bhh0,
    const float* __restrict__ bih1, const float* __restrict__ bhh1)
{
    extern __shared__ __align__(16) char smem[];
    const int tid = threadIdx.x;
    const int wid = tid >> 5;
    const int lane = tid & 31;
    const int nbase = blockIdx.x * NTILE;
    const u32 sbase = smem_u32(smem);

    /* zero h-hi planes (both buffers) + fp32 carry planes */
    for (int i = tid; i < OFF_XB / 4; i += 512) ((u32*)smem)[i] = 0;

    const int j = wid * 8 + (lane >> 2);
    const float br0 = bih0[j] + bhh0[j];
    const float bz0 = bih0[128 + j] + bhh0[128 + j];
    const float bi0 = bih0[256 + j];
    const float bn0 = bhh0[256 + j];
    const float br1 = bih1[j] + bhh1[j];
    const float bz1 = bih1[128 + j] + bhh1[128 + j];
    const float bi1 = bih1[256 + j];
    const float bn1 = bhh1[256 + j];

    const int lane15 = (lane & 15) * BROW;
    const int sb = (lane & 3) * 4;
    const u32 rowf0 = sbase + OFF_F32 + tid * 72;           /* 18 floats, 8-aligned */
    const u32 rowf1 = rowf0 + 36864;

    const uint4* pb0 = g_wblob + (size_t)wid * 128 + lane;
    const uint4* pb1 = pb0 + (size_t)10 * 2048;
    float* stg = (float*)(smem + OFF_STG);

    /* prologue: stage & convert x(0) into x-buffer 0 */
    {
        const float4* src = (const float4*)(g_x32 + (size_t)nbase * 32);
        cp16(stg + 4 * tid, src + tid);
        asm volatile("cp.async.commit_group;");
        asm volatile("cp.async.wait_group 0;");
        conv_x(stg, smem, OFF_XB, tid);
    }
    __syncthreads();

    float acc[64];

    for (int t = 0; t < NNODES; t++) {
        const int p = t & 1;
        if (t < NNODES - 1) {
            const float4* src = (const float4*)(g_x32 + ((size_t)(t + 1) * NSEQ + nbase) * 32);
            cp16(stg + 4 * tid, src + tid);
            asm volatile("cp.async.commit_group;");
        }
        /* ---- layer 0: GEMM reads x[p], h0hi[p]; epi writes h0hi[p^1] ---- */
        #pragma unroll
        for (int i = 0; i < 64; i++) acc[i] = 0.f;
        gemm_phase<10, 2>(pb0, sbase + OFF_XB + p * 4608,
                          sbase + OFF_H0HI + p * 18432, lane15, acc);
        gru_epilogue(acc, br0, bz0, bi0, bn0,
                     sbase + OFF_H0HI + (p ^ 1) * 18432 + j * BROW,
                     rowf0, sb, (float*)0, j, nbase);
        __syncthreads();      /* h0hi[p^1] complete for all warps */

        /* ---- layer 1: GEMM reads h0hi[p^1], h1hi[p]; epi writes h1hi[p^1] ---- */
        #pragma unroll
        for (int i = 0; i < 64; i++) acc[i] = 0.f;
        gemm_phase<16, 8>(pb1, sbase + OFF_H0HI + (p ^ 1) * 18432,
                          sbase + OFF_H1HI + p * 18432, lane15, acc);
        gru_epilogue(acc, br1, bz1, bi1, bn1,
                     sbase + OFF_H1HI + (p ^ 1) * 18432 + j * BROW,
                     rowf1, sb, (t == NNODES - 1) ? g_last : (float*)0, j, nbase);
        if (t < NNODES - 1) {
            asm volatile("cp.async.wait_group 0;");
            conv_x(stg, smem, OFF_XB + ((t + 1) & 1) * 4608, tid);
        }
        __syncthreads();      /* h1hi[p^1] + x(t+1) complete */
    }
}

/* ==================== K3: mean over routes + head MLP ==================== */
__global__ __launch_bounds__(128) void k_final(
    const float* __restrict__ cand,
    const float* __restrict__ cand_w, const float* __restrict__ cand_b,
    const float* __restrict__ fc1w, const float* __restrict__ fc1b,
    const float* __restrict__ fc2w, const float* __restrict__ fc2b,
    const float* __restrict__ fc3w, const float* __restrict__ fc3b,
    float* __restrict__ out)
{
    __shared__ float xr[RH + 64];
    __shared__ float h[128];
    __shared__ float red[128];
    const int b = blockIdx.x, tid = threadIdx.x;
    {
        const float* base = g_last + (size_t)b * NROUTES * RH;
        float acc = 0.f;
        #pragma unroll 8
        for (int r = 0; r < NROUTES; r++) acc += base[r * RH + tid];
        xr[tid] = acc * (1.f / NROUTES);
    }
    if (tid < 64) {
        float a = cand_b[tid];
        #pragma unroll 8
        for (int i = 0; i < 2 * FEAT; i++)
            a += cand[b * 2 * FEAT + i] * cand_w[i * 64 + tid];
        xr[RH + tid] = a;
    }
    __syncthreads();
    {
        float a = fc1b[tid];
        #pragma unroll 8
        for (int i = 0; i < RH + 64; i++) a += xr[i] * fc1w[i * 128 + tid];
        h[tid] = tanhf(a);
    }
    __syncthreads();
    {
        float a = fc2b[tid];
        #pragma unroll 8
        for (int i = 0; i < 128; i++) a += h[i] * fc2w[i * 128 + tid];
        red[tid] = tanhf(a) * fc3w[tid];
    }
    __syncthreads();
    for (int s = 64; s > 0; s >>= 1) {
        if (tid < s) red[tid] += red[tid + s];
        __syncthreads();
    }
    if (tid == 0) out[b] = red[0] + fc3b[0];
}

/* ==================== launch ==================== */
extern "C" void kernel_launch(void* const* d_in, const int* in_sizes, int n_in,
                              void* d_out, int out_size)
{
    const float* candidates = (const float*)d_in[0];
    const float* customers  = (const float*)d_in[1];
    const float* cust_w1 = (const float*)d_in[2];
    const float* cust_b1 = (const float*)d_in[3];
    const float* cust_w2 = (const float*)d_in[4];
    const float* cust_b2 = (const float*)d_in[5];
    const float* wih0 = (const float*)d_in[6];
    const float* whh0 = (const float*)d_in[7];
    const float* bih0 = (const float*)d_in[8];
    const float* bhh0 = (const float*)d_in[9];
    const float* wih1 = (const float*)d_in[10];
    const float* whh1 = (const float*)d_in[11];
    const float* bih1 = (const float*)d_in[12];
    const float* bhh1 = (const float*)d_in[13];
    const float* cand_w = (const float*)d_in[14];
    const float* cand_b = (const float*)d_in[15];
    const float* fc1w = (const float*)d_in[16];
    const float* fc1b = (const float*)d_in[17];
    const float* fc2w = (const float*)d_in[18];
    const float* fc2b = (const float*)d_in[19];
    const float* fc3w = (const float*)d_in[20];
    const float* fc3b = (const float*)d_in[21];

    cudaFuncSetAttribute(k_gru, cudaFuncAttributeMaxDynamicSharedMemorySize, GRU_SMEM);

    k_prep_gru<<<(26 * 16384 + 255) / 256, 256>>>(wih0, whh0, wih1, whh1);
    k_prep_cust<<<(FEAT * CH + CH * COUT + 255) / 256, 256>>>(cust_w1, cust_w2);
    k_cust<<<NROWS / K1_ROWS, 256>>>(customers, cust_b1, cust_b2);
    k_gru<<<NSEQ / NTILE, 512, GRU_SMEM>>>(bih0, bhh0, bih1, bhh1);
    k_final<<<BATCH, 128>>>(candidates, cand_w, cand_b,
                            fc1w, fc1b, fc2w, fc2b, fc3w, fc3b,
                            (float*)d_out);
}

// round 15
// speedup vs baseline: 4.3070x; 1.1470x over previous
#include <cuda_runtime.h>
#include <cuda_fp16.h>
#include <math.h>
#include <stdint.h>
#include <stddef.h>

#define FEAT    36
#define NNODES  24
#define NROUTES 48
#define CH      128
#define COUT    32
#define RH      128
#define BATCH   512
#define NSEQ    (BATCH * NROUTES)
#define G3      (3 * RH)
#define NROWS   (NNODES * NSEQ)

typedef unsigned long long ull;
typedef unsigned int u32;

/* ---- fast gate nonlinearities (clamped; MUFU-based) ---- */
__device__ __forceinline__ float fsigm(float x) {
    x = fminf(fmaxf(x, -20.f), 20.f);
    float e = __expf(-x);
    return __fdividef(1.f, 1.f + e);
}
__device__ __forceinline__ float ftanh(float x) {
    x = fminf(fmaxf(x, -10.f), 10.f);
    float e = __expf(-2.f * x);
    return __fdividef(1.f - e, 1.f + e);
}

__device__ __forceinline__ void cp16(float* dst, const float4* src) {
    unsigned s = (unsigned)__cvta_generic_to_shared(dst);
    asm volatile("cp.async.ca.shared.global [%0], [%1], 16;" :: "r"(s), "l"(src));
}
__device__ __forceinline__ u32 smem_u32(const void* p) {
    u32 a;
    asm("{ .reg .u64 t; cvta.to.shared.u64 t, %1; cvt.u32.u64 %0, t; }" : "=r"(a) : "l"(p));
    return a;
}

/* ---- HMMA helpers (sm_80 baseline; valid on plain sm_103) ---- */
__device__ __forceinline__ void mma_f16(float* c, const u32* a, u32 b0, u32 b1) {
    asm("mma.sync.aligned.m16n8k16.row.col.f32.f16.f16.f32 "
        "{%0,%1,%2,%3},{%4,%5,%6,%7},{%8,%9},{%0,%1,%2,%3};"
        : "+f"(c[0]), "+f"(c[1]), "+f"(c[2]), "+f"(c[3])
        : "r"(a[0]), "r"(a[1]), "r"(a[2]), "r"(a[3]), "r"(b0), "r"(b1));
}
__device__ __forceinline__ void ldsm_t2(u32& r0, u32& r1, u32 addr) {
    asm volatile("ldmatrix.sync.aligned.m8n8.x2.trans.shared.b16 {%0,%1}, [%2];"
                 : "=r"(r0), "=r"(r1) : "r"(addr));
}

/* ---- device scratch ---- */
__device__ float g_x32[(size_t)NROWS * COUT];
__device__ float g_last[(size_t)NSEQ * RH];
__device__ uint4 g_wblob[26 * 2048];      /* GRU A-fragment stream (fp16 split) */
__device__ uint4 g_cblob1[1536];          /* k_cust GEMM1: [sl3][wm8][split2][lane32] */
__device__ uint4 g_cblob2[1024];          /* k_cust GEMM2: [sl8][mt2][split2][lane32] */

/* ==================== prep: GRU A-fragment blob (split-fp16) ==================== */
__global__ __launch_bounds__(256) void k_prep_gru(
    const float* __restrict__ wih0, const float* __restrict__ whh0,
    const float* __restrict__ wih1, const float* __restrict__ whh1)
{
    int idx = blockIdx.x * 256 + threadIdx.x;     /* fp16 element index */
    if (idx >= 26 * 16384) return;
    int off  = idx * 2;
    int sg   = off >> 15;
    int rem  = off & 32767;
    int wid  = rem >> 11;
    int rem2 = rem & 2047;
    int frag = rem2 >> 9;
    int rem3 = rem2 & 511;
    int lane = rem3 >> 4;
    int b    = rem3 & 15;
    int pos  = b >> 1;
    int areg = pos >> 1, elt = pos & 1;
    int row  = (lane >> 2) + (areg & 1) * 8;
    int col  = (lane & 3) * 2 + (areg >> 1) * 8 + elt;
    int tile = frag & 1, split = frag >> 1;
    int j    = wid * 8 + (row & 7);
    int phase = (sg < 10) ? 0 : 1;
    int sl    = phase ? sg - 10 : sg;
    int nih   = phase ? 8 : 2;
    bool is_ih = sl < nih;
    int k = (is_ih ? sl : sl - nih) * 16 + col;
    const float* W = phase == 0 ? (is_ih ? wih0 : whh0) : (is_ih ? wih1 : whh1);
    int gcol = (tile == 0) ? ((row < 8) ? j : 128 + j) : 256 + j;
    bool valid = (tile == 0) || ((row < 8) ? is_ih : !is_ih);
    float v = valid ? W[k * G3 + gcol] : 0.f;
    __half hb = __float2half(v);
    __half out = split ? __float2half(v - __half2float(hb)) : hb;
    ((unsigned short*)g_wblob)[idx] = reinterpret_cast<unsigned short&>(out);
}

/* ==================== prep: k_cust fragment blobs (split-fp16) ==================== */
__global__ __launch_bounds__(256) void k_prep_cblob(
    const float* __restrict__ w1, const float* __restrict__ w2)
{
    int idx = blockIdx.x * 256 + threadIdx.x;   /* fp16 elem over both blobs */
    if (idx >= 12288 + 8192) return;
    float v;
    unsigned short* dst;
    if (idx < 12288) {
        int p = idx & 7, l = idx >> 3;
        int areg = p >> 1, elt = p & 1;
        int lane = l & 31, split = (l >> 5) & 1, wm = (l >> 6) & 7, sl = l >> 9;
        int rowm = 16 * wm + (lane >> 2) + (areg & 1) * 8;          /* 0..127 */
        int kcol = sl * 16 + (lane & 3) * 2 + (areg >> 1) * 8 + elt; /* 0..47 */
        v = (kcol < FEAT) ? w1[kcol * CH + rowm] : 0.f;
        if (split) {
            __half hb = __float2half(v);
            v = v - __half2float(hb);
        }
        dst = ((unsigned short*)g_cblob1) + idx;
    } else {
        int i2 = idx - 12288;
        int p = i2 & 7, l = i2 >> 3;
        int areg = p >> 1, elt = p & 1;
        int lane = l & 31, split = (l >> 5) & 1, mt = (l >> 6) & 1, sl = l >> 7;
        int rowo = 16 * mt + (lane >> 2) + (areg & 1) * 8;           /* 0..31 */
        int kcol = sl * 16 + (lane & 3) * 2 + (areg >> 1) * 8 + elt; /* 0..127 */
        v = w2[kcol * COUT + rowo];
        if (split) {
            __half hb = __float2half(v);
            v = v - __half2float(hb);
        }
        dst = ((unsigned short*)g_cblob2) + i2;
    }
    __half out = __float2half(v);
    *dst = reinterpret_cast<unsigned short&>(out);
}

/* ==================== K1: customer MLP via HMMA ==================== */
#define CB_ROW   272          /* 128 seqs * 2B + 16 pad */
#define CB_STAGE 0            /* 128 rows x 36 floats = 18432 B */
#define CB_XP    18432        /* 48 k-rows x 272 = 13056 B */
#define CB_HP    31488        /* 128 k-rows x 272 = 34816 B */
#define CB_SMEM  66304

__global__ __launch_bounds__(512) void k_cust_mma(
    const float* __restrict__ cust,
    const float* __restrict__ b1, const float* __restrict__ b2)
{
    extern __shared__ __align__(16) char smem[];
    const int tid = threadIdx.x;
    const int wid = tid >> 5;
    const int lane = tid & 31;
    const u32 sbase = smem_u32(smem);
    const long long row0 = (long long)blockIdx.x * 128;   /* row = t*NSEQ + n */

    float* stage = (float*)(smem + CB_STAGE);

    /* stage 128 rows x 36 floats via cp.async (9 float4 per row) */
    #pragma unroll
    for (int rep = 0; rep < 3; rep++) {
        int e = tid + rep * 512;
        if (e < 128 * 9) {
            int s = e / 9, q = e - s * 9;
            long long row = row0 + s;
            int t = (int)(row / NSEQ);
            int n = (int)(row - (long long)t * NSEQ);
            cp16(stage + s * 36 + q * 4,
                 (const float4*)(cust + (size_t)n * (NNODES * FEAT) + t * FEAT) + q);
        }
    }
    asm volatile("cp.async.commit_group;");
    /* zero xp pad rows 36..47 */
    for (int i = tid; i < 12 * CB_ROW / 4; i += 512)
        *(u32*)(smem + CB_XP + 36 * CB_ROW + i * 4) = 0;
    asm volatile("cp.async.wait_group 0;");
    __syncthreads();

    /* transpose+convert: xp[f][s] fp16 */
    #pragma unroll
    for (int i = 0; i < 9; i++) {
        int e = tid + i * 512;          /* e = f*128 + s */
        int f = e >> 7, s = e & 127;
        *(__half*)(smem + CB_XP + f * CB_ROW + s * 2) = __float2half(stage[s * 36 + f]);
    }
    __syncthreads();

    /* ---- GEMM1: h[128, 128seq] = W1^T @ x ---- */
    const int wg = wid >> 3;            /* seq half */
    const int wm = wid & 7;             /* m16 tile */
    float acc[32];
    #pragma unroll
    for (int i = 0; i < 32; i++) acc[i] = 0.f;
    {
        const u32 bb = sbase + CB_XP + wg * 128 + (lane & 15) * CB_ROW;
        #pragma unroll
        for (int sl = 0; sl < 3; sl++) {
            u32 b[16];
            #pragma unroll
            for (int nt = 0; nt < 8; nt++)
                ldsm_t2(b[2 * nt], b[2 * nt + 1], bb + sl * 16 * CB_ROW + nt * 16);
            uint4 ahi = g_cblob1[sl * 512 + wm * 64 + lane];
            uint4 alo = g_cblob1[sl * 512 + wm * 64 + 32 + lane];
            #pragma unroll
            for (int nt = 0; nt < 8; nt++)
                mma_f16(acc + nt * 4, (const u32*)&ahi, b[2 * nt], b[2 * nt + 1]);
            #pragma unroll
            for (int nt = 0; nt < 8; nt++)
                mma_f16(acc + nt * 4, (const u32*)&alo, b[2 * nt], b[2 * nt + 1]);
        }
    }
    /* epilogue 1: tanh -> hp plane */
    {
        const int r0 = 16 * wm + (lane >> 2);
        const float ba = b1[r0], bb_ = b1[r0 + 8];
        #pragma unroll
        for (int nt = 0; nt < 8; nt++) {
            int col = wg * 64 + nt * 8 + 2 * (lane & 3);
            float t00 = ftanh(acc[nt * 4 + 0] + ba);
            float t01 = ftanh(acc[nt * 4 + 1] + ba);
            float t10 = ftanh(acc[nt * 4 + 2] + bb_);
            float t11 = ftanh(acc[nt * 4 + 3] + bb_);
            __half2 hA = __floats2half2_rn(t00, t01);
            __half2 hB = __floats2half2_rn(t10, t11);
            *(__half2*)(smem + CB_HP + r0 * CB_ROW + col * 2) = hA;
            *(__half2*)(smem + CB_HP + (r0 + 8) * CB_ROW + col * 2) = hB;
        }
    }
    __syncthreads();

    /* ---- GEMM2: y[32, 128seq] = W2^T @ h ---- */
    const int mt = wid & 1;
    const int sq = wid >> 1;            /* 16-seq block */
    float a2[8];
    #pragma unroll
    for (int i = 0; i < 8; i++) a2[i] = 0.f;
    {
        const u32 bb = sbase + CB_HP + sq * 32 + (lane & 15) * CB_ROW;
        #pragma unroll
        for (int sl = 0; sl < 8; sl++) {
            u32 b[4];
            ldsm_t2(b[0], b[1], bb + sl * 16 * CB_ROW);
            ldsm_t2(b[2], b[3], bb + sl * 16 * CB_ROW + 16);
            uint4 ahi = g_cblob2[sl * 128 + mt * 64 + lane];
            uint4 alo = g_cblob2[sl * 128 + mt * 64 + 32 + lane];
            mma_f16(a2 + 0, (const u32*)&ahi, b[0], b[1]);
            mma_f16(a2 + 4, (const u32*)&ahi, b[2], b[3]);
            mma_f16(a2 + 0, (const u32*)&alo, b[0], b[1]);
            mma_f16(a2 + 4, (const u32*)&alo, b[2], b[3]);
        }
    }
    /* epilogue 2: tanh -> g_x32 */
    {
        const int o0 = 16 * mt + (lane >> 2);
        const float ba = b2[o0], bb_ = b2[o0 + 8];
        #pragma unroll
        for (int nt = 0; nt < 2; nt++) {
            int s0 = sq * 16 + nt * 8 + 2 * (lane & 3);
            size_t base = (size_t)(row0 + s0) * COUT;
            g_x32[base + o0]            = ftanh(a2[nt * 4 + 0] + ba);
            g_x32[base + COUT + o0]     = ftanh(a2[nt * 4 + 1] + ba);
            g_x32[base + o0 + 8]        = ftanh(a2[nt * 4 + 2] + bb_);
            g_x32[base + COUT + o0 + 8] = ftanh(a2[nt * 4 + 3] + bb_);
        }
    }
}

/* ==================== K2: HMMA GRU (R14, frozen) ==================== */
#define NTILE   64
#define BROW    144
#define OFF_H0HI 0
#define OFF_H1HI 36864
#define OFF_F32  73728
#define OFF_XB   147456
#define OFF_STG  156672
#define GRU_SMEM 164864

template<int NSL, int NIH>
__device__ __forceinline__ void gemm_phase(
    const uint4* __restrict__ pA,
    u32 bih_hi, u32 bhh_hi,
    int lane15, float* acc)
{
    uint4 a0 = pA[0], a1 = pA[32], a2 = pA[64], a3 = pA[96];
    #pragma unroll 1
    for (int sl = 0; sl < NSL; sl++) {
        u32 rh = (sl < NIH) ? (bih_hi + sl * 16 * BROW + lane15)
                            : (bhh_hi + (sl - NIH) * 16 * BROW + lane15);
        u32 b[16];
        #pragma unroll
        for (int nt = 0; nt < 8; nt++)
            ldsm_t2(b[2 * nt], b[2 * nt + 1], rh + nt * 16);
        uint4 n0, n1, n2, n3;
        if (sl + 1 < NSL) {
            const uint4* p = pA + (size_t)(sl + 1) * 2048;
            n0 = p[0]; n1 = p[32]; n2 = p[64]; n3 = p[96];
        }
        #pragma unroll
        for (int nt = 0; nt < 8; nt++) {
            mma_f16(acc + nt * 4,      (const u32*)&a0, b[2 * nt], b[2 * nt + 1]);
            mma_f16(acc + 32 + nt * 4, (const u32*)&a1, b[2 * nt], b[2 * nt + 1]);
        }
        #pragma unroll
        for (int nt = 0; nt < 8; nt++) {
            mma_f16(acc + nt * 4,      (const u32*)&a2, b[2 * nt], b[2 * nt + 1]);
            mma_f16(acc + 32 + nt * 4, (const u32*)&a3, b[2 * nt], b[2 * nt + 1]);
        }
        if (sl + 1 < NSL) { a0 = n0; a1 = n1; a2 = n2; a3 = n3; }
    }
}

__device__ __forceinline__ void gru_epilogue(
    const float* acc, float br, float bz, float bi, float bn,
    u32 rowhi_w, u32 rowf,
    int sb, float* lastout, int j, int nbase)
{
    #pragma unroll
    for (int nt = 0; nt < 8; nt++) {
        int o = nt * 16 + sb;
        float2 hold;
        asm volatile("ld.shared.v2.f32 {%0,%1}, [%2];"
                     : "=f"(hold.x), "=f"(hold.y) : "r"(rowf + nt * 8));
        float r0 = fsigm(acc[nt * 4 + 0] + br);
        float r1 = fsigm(acc[nt * 4 + 1] + br);
        float z0 = fsigm(acc[nt * 4 + 2] + bz);
        float z1 = fsigm(acc[nt * 4 + 3] + bz);
        float n0 = ftanh(acc[32 + nt * 4 + 0] + bi + r0 * (acc[32 + nt * 4 + 2] + bn));
        float n1 = ftanh(acc[32 + nt * 4 + 1] + bi + r1 * (acc[32 + nt * 4 + 3] + bn));
        float h0 = (1.f - z0) * n0 + z0 * hold.x;
        float h1 = (1.f - z1) * n1 + z1 * hold.y;
        asm volatile("st.shared.v2.f32 [%0], {%1,%2};"
                     :: "r"(rowf + nt * 8), "f"(h0), "f"(h1) : "memory");
        __half2 H2 = __floats2half2_rn(h0, h1);
        u32 packh = *reinterpret_cast<u32*>(&H2);
        asm volatile("st.shared.b32 [%0], %1;" :: "r"(rowhi_w + o), "r"(packh) : "memory");
        if (lastout) {
            int s = nt * 8 + (sb >> 1);
            lastout[(size_t)(nbase + s) * RH + j]     = h0;
            lastout[(size_t)(nbase + s + 1) * RH + j] = h1;
        }
    }
}

__device__ __forceinline__ void conv_x(const float* stg, char* smemc, int xoff, int tid)
{
    #pragma unroll
    for (int i = 0; i < 4; i++) {
        int e = 4 * tid + i;
        float v = stg[e];
        int s = e >> 5, f = e & 31;
        *(__half*)(smemc + xoff + f * BROW + s * 2) = __float2half(v);
    }
}

__global__ __launch_bounds__(512, 1) void k_gru(
    const float* __restrict__ bih0, const float* __restrict__ bhh0,
    const float* __restrict__ bih1, const float* __restrict__ bhh1)
{
    extern __shared__ __align__(16) char smem[];
    const int tid = threadIdx.x;
    const int wid = tid >> 5;
    const int lane = tid & 31;
    const int nbase = blockIdx.x * NTILE;
    const u32 sbase = smem_u32(smem);

    for (int i = tid; i < OFF_XB / 4; i += 512) ((u32*)smem)[i] = 0;

    const int j = wid * 8 + (lane >> 2);
    const float br0 = bih0[j] + bhh0[j];
    const float bz0 = bih0[128 + j] + bhh0[128 + j];
    const float bi0 = bih0[256 + j];
    const float bn0 = bhh0[256 + j];
    const float br1 = bih1[j] + bhh1[j];
    const float bz1 = bih1[128 + j] + bhh1[128 + j];
    const float bi1 = bih1[256 + j];
    const float bn1 = bhh1[256 + j];

    const int lane15 = (lane & 15) * BROW;
    const int sb = (lane & 3) * 4;
    const u32 rowf0 = sbase + OFF_F32 + tid * 72;
    const u32 rowf1 = rowf0 + 36864;

    const uint4* pb0 = g_wblob + (size_t)wid * 128 + lane;
    const uint4* pb1 = pb0 + (size_t)10 * 2048;
    float* stg = (float*)(smem + OFF_STG);

    {
        const float4* src = (const float4*)(g_x32 + (size_t)nbase * 32);
        cp16(stg + 4 * tid, src + tid);
        asm volatile("cp.async.commit_group;");
        asm volatile("cp.async.wait_group 0;");
        conv_x(stg, smem, OFF_XB, tid);
    }
    __syncthreads();

    float acc[64];

    for (int t = 0; t < NNODES; t++) {
        const int p = t & 1;
        if (t < NNODES - 1) {
            const float4* src = (const float4*)(g_x32 + ((size_t)(t + 1) * NSEQ + nbase) * 32);
            cp16(stg + 4 * tid, src + tid);
            asm volatile("cp.async.commit_group;");
        }
        #pragma unroll
        for (int i = 0; i < 64; i++) acc[i] = 0.f;
        gemm_phase<10, 2>(pb0, sbase + OFF_XB + p * 4608,
                          sbase + OFF_H0HI + p * 18432, lane15, acc);
        gru_epilogue(acc, br0, bz0, bi0, bn0,
                     sbase + OFF_H0HI + (p ^ 1) * 18432 + j * BROW,
                     rowf0, sb, (float*)0, j, nbase);
        __syncthreads();

        #pragma unroll
        for (int i = 0; i < 64; i++) acc[i] = 0.f;
        gemm_phase<16, 8>(pb1, sbase + OFF_H0HI + (p ^ 1) * 18432,
                          sbase + OFF_H1HI + p * 18432, lane15, acc);
        gru_epilogue(acc, br1, bz1, bi1, bn1,
                     sbase + OFF_H1HI + (p ^ 1) * 18432 + j * BROW,
                     rowf1, sb, (t == NNODES - 1) ? g_last : (float*)0, j, nbase);
        if (t < NNODES - 1) {
            asm volatile("cp.async.wait_group 0;");
            conv_x(stg, smem, OFF_XB + ((t + 1) & 1) * 4608, tid);
        }
        __syncthreads();
    }
}

/* ==================== K3: mean over routes + head MLP ==================== */
__global__ __launch_bounds__(128) void k_final(
    const float* __restrict__ cand,
    const float* __restrict__ cand_w, const float* __restrict__ cand_b,
    const float* __restrict__ fc1w, const float* __restrict__ fc1b,
    const float* __restrict__ fc2w, const float* __restrict__ fc2b,
    const float* __restrict__ fc3w, const float* __restrict__ fc3b,
    float* __restrict__ out)
{
    __shared__ float xr[RH + 64];
    __shared__ float h[128];
    __shared__ float red[128];
    const int b = blockIdx.x, tid = threadIdx.x;
    {
        const float* base = g_last + (size_t)b * NROUTES * RH;
        float acc = 0.f;
        #pragma unroll 8
        for (int r = 0; r < NROUTES; r++) acc += base[r * RH + tid];
        xr[tid] = acc * (1.f / NROUTES);
    }
    if (tid < 64) {
        float a = cand_b[tid];
        #pragma unroll 8
        for (int i = 0; i < 2 * FEAT; i++)
            a += cand[b * 2 * FEAT + i] * cand_w[i * 64 + tid];
        xr[RH + tid] = a;
    }
    __syncthreads();
    {
        float a = fc1b[tid];
        #pragma unroll 8
        for (int i = 0; i < RH + 64; i++) a += xr[i] * fc1w[i * 128 + tid];
        h[tid] = tanhf(a);
    }
    __syncthreads();
    {
        float a = fc2b[tid];
        #pragma unroll 8
        for (int i = 0; i < 128; i++) a += h[i] * fc2w[i * 128 + tid];
        red[tid] = tanhf(a) * fc3w[tid];
    }
    __syncthreads();
    for (int s = 64; s > 0; s >>= 1) {
        if (tid < s) red[tid] += red[tid + s];
        __syncthreads();
    }
    if (tid == 0) out[b] = red[0] + fc3b[0];
}

/* ==================== launch ==================== */
extern "C" void kernel_launch(void* const* d_in, const int* in_sizes, int n_in,
                              void* d_out, int out_size)
{
    const float* candidates = (const float*)d_in[0];
    const float* customers  = (const float*)d_in[1];
    const float* cust_w1 = (const float*)d_in[2];
    const float* cust_b1 = (const float*)d_in[3];
    const float* cust_w2 = (const float*)d_in[4];
    const float* cust_b2 = (const float*)d_in[5];
    const float* wih0 = (const float*)d_in[6];
    const float* whh0 = (const float*)d_in[7];
    const float* bih0 = (const float*)d_in[8];
    const float* bhh0 = (const float*)d_in[9];
    const float* wih1 = (const float*)d_in[10];
    const float* whh1 = (const float*)d_in[11];
    const float* bih1 = (const float*)d_in[12];
    const float* bhh1 = (const float*)d_in[13];
    const float* cand_w = (const float*)d_in[14];
    const float* cand_b = (const float*)d_in[15];
    const float* fc1w = (const float*)d_in[16];
    const float* fc1b = (const float*)d_in[17];
    const float* fc2w = (const float*)d_in[18];
    const float* fc2b = (const float*)d_in[19];
    const float* fc3w = (const float*)d_in[20];
    const float* fc3b = (const float*)d_in[21];

    cudaFuncSetAttribute(k_gru, cudaFuncAttributeMaxDynamicSharedMemorySize, GRU_SMEM);
    cudaFuncSetAttribute(k_cust_mma, cudaFuncAttributeMaxDynamicSharedMemorySize, CB_SMEM);

    k_prep_gru<<<(26 * 16384 + 255) / 256, 256>>>(wih0, whh0, wih1, whh1);
    k_prep_cblob<<<(12288 + 8192 + 255) / 256, 256>>>(cust_w1, cust_w2);
    k_cust_mma<<<NROWS / 128, 512, CB_SMEM>>>(customers, cust_b1, cust_b2);
    k_gru<<<NSEQ / NTILE, 512, GRU_SMEM>>>(bih0, bhh0, bih1, bhh1);
    k_final<<<BATCH, 128>>>(candidates, cand_w, cand_b,
                            fc1w, fc1b, fc2w, fc2b, fc3w, fc3b,
                            (float*)d_out);
}

// round 16
// speedup vs baseline: 4.4270x; 1.0279x over previous
#include <cuda_runtime.h>
#include <cuda_fp16.h>
#include <math.h>
#include <stdint.h>
#include <stddef.h>

#define FEAT    36
#define NNODES  24
#define NROUTES 48
#define CH      128
#define COUT    32
#define RH      128
#define BATCH   512
#define NSEQ    (BATCH * NROUTES)
#define G3      (3 * RH)
#define NROWS   (NNODES * NSEQ)

typedef unsigned long long ull;
typedef unsigned int u32;

/* ---- fast gate nonlinearities (clamped; MUFU-based) ---- */
__device__ __forceinline__ float fsigm(float x) {
    x = fminf(fmaxf(x, -20.f), 20.f);
    float e = __expf(-x);
    return __fdividef(1.f, 1.f + e);
}
__device__ __forceinline__ float ftanh(float x) {
    x = fminf(fmaxf(x, -10.f), 10.f);
    float e = __expf(-2.f * x);
    return __fdividef(1.f - e, 1.f + e);
}

__device__ __forceinline__ void cp16(float* dst, const float4* src) {
    unsigned s = (unsigned)__cvta_generic_to_shared(dst);
    asm volatile("cp.async.ca.shared.global [%0], [%1], 16;" :: "r"(s), "l"(src));
}
__device__ __forceinline__ u32 smem_u32(const void* p) {
    u32 a;
    asm("{ .reg .u64 t; cvta.to.shared.u64 t, %1; cvt.u32.u64 %0, t; }" : "=r"(a) : "l"(p));
    return a;
}

/* ---- HMMA helpers (sm_80 baseline; valid on plain sm_103) ---- */
__device__ __forceinline__ void mma_f16(float* c, const u32* a, u32 b0, u32 b1) {
    asm("mma.sync.aligned.m16n8k16.row.col.f32.f16.f16.f32 "
        "{%0,%1,%2,%3},{%4,%5,%6,%7},{%8,%9},{%0,%1,%2,%3};"
        : "+f"(c[0]), "+f"(c[1]), "+f"(c[2]), "+f"(c[3])
        : "r"(a[0]), "r"(a[1]), "r"(a[2]), "r"(a[3]), "r"(b0), "r"(b1));
}
__device__ __forceinline__ void ldsm_t2(u32& r0, u32& r1, u32 addr) {
    asm volatile("ldmatrix.sync.aligned.m8n8.x2.trans.shared.b16 {%0,%1}, [%2];"
                 : "=r"(r0), "=r"(r1) : "r"(addr));
}

/* ---- device scratch ---- */
__device__ float g_x32[(size_t)NROWS * COUT];
__device__ float g_last[(size_t)NSEQ * RH];
__device__ uint4 g_wblob[26 * 2048];      /* GRU A-fragment stream (fp16 split) */
__device__ uint4 g_cblob1[1536];          /* k_cust GEMM1 fragments */
__device__ uint4 g_cblob2[1024];          /* k_cust GEMM2 fragments */

/* ==================== prep: GRU A-fragment blob (split-fp16) ==================== */
__global__ __launch_bounds__(256) void k_prep_gru(
    const float* __restrict__ wih0, const float* __restrict__ whh0,
    const float* __restrict__ wih1, const float* __restrict__ whh1)
{
    int idx = blockIdx.x * 256 + threadIdx.x;     /* fp16 element index */
    if (idx >= 26 * 16384) return;
    int off  = idx * 2;
    int sg   = off >> 15;
    int rem  = off & 32767;
    int wid  = rem >> 11;
    int rem2 = rem & 2047;
    int frag = rem2 >> 9;
    int rem3 = rem2 & 511;
    int lane = rem3 >> 4;
    int b    = rem3 & 15;
    int pos  = b >> 1;
    int areg = pos >> 1, elt = pos & 1;
    int row  = (lane >> 2) + (areg & 1) * 8;
    int col  = (lane & 3) * 2 + (areg >> 1) * 8 + elt;
    int tile = frag & 1, split = frag >> 1;
    int j    = wid * 8 + (row & 7);
    int phase = (sg < 10) ? 0 : 1;
    int sl    = phase ? sg - 10 : sg;
    int nih   = phase ? 8 : 2;
    bool is_ih = sl < nih;
    int k = (is_ih ? sl : sl - nih) * 16 + col;
    const float* W = phase == 0 ? (is_ih ? wih0 : whh0) : (is_ih ? wih1 : whh1);
    int gcol = (tile == 0) ? ((row < 8) ? j : 128 + j) : 256 + j;
    bool valid = (tile == 0) || ((row < 8) ? is_ih : !is_ih);
    float v = valid ? W[k * G3 + gcol] : 0.f;
    __half hb = __float2half(v);
    __half out = split ? __float2half(v - __half2float(hb)) : hb;
    ((unsigned short*)g_wblob)[idx] = reinterpret_cast<unsigned short&>(out);
}

/* ==================== prep: k_cust fragment blobs (split-fp16) ==================== */
__global__ __launch_bounds__(256) void k_prep_cblob(
    const float* __restrict__ w1, const float* __restrict__ w2)
{
    int idx = blockIdx.x * 256 + threadIdx.x;
    if (idx >= 12288 + 8192) return;
    float v;
    unsigned short* dst;
    if (idx < 12288) {
        int p = idx & 7, l = idx >> 3;
        int areg = p >> 1, elt = p & 1;
        int lane = l & 31, split = (l >> 5) & 1, wm = (l >> 6) & 7, sl = l >> 9;
        int rowm = 16 * wm + (lane >> 2) + (areg & 1) * 8;
        int kcol = sl * 16 + (lane & 3) * 2 + (areg >> 1) * 8 + elt;
        v = (kcol < FEAT) ? w1[kcol * CH + rowm] : 0.f;
        if (split) { __half hb = __float2half(v); v = v - __half2float(hb); }
        dst = ((unsigned short*)g_cblob1) + idx;
    } else {
        int i2 = idx - 12288;
        int p = i2 & 7, l = i2 >> 3;
        int areg = p >> 1, elt = p & 1;
        int lane = l & 31, split = (l >> 5) & 1, mt = (l >> 6) & 1, sl = l >> 7;
        int rowo = 16 * mt + (lane >> 2) + (areg & 1) * 8;
        int kcol = sl * 16 + (lane & 3) * 2 + (areg >> 1) * 8 + elt;
        v = w2[kcol * COUT + rowo];
        if (split) { __half hb = __float2half(v); v = v - __half2float(hb); }
        dst = ((unsigned short*)g_cblob2) + i2;
    }
    __half out = __float2half(v);
    *dst = reinterpret_cast<unsigned short&>(out);
}

/* ==================== K1: customer MLP via HMMA (R15, frozen) ==================== */
#define CB_ROW   272
#define CB_STAGE 0
#define CB_XP    18432
#define CB_HP    31488
#define CB_SMEM  66304

__global__ __launch_bounds__(512) void k_cust_mma(
    const float* __restrict__ cust,
    const float* __restrict__ b1, const float* __restrict__ b2)
{
    extern __shared__ __align__(16) char smem[];
    const int tid = threadIdx.x;
    const int wid = tid >> 5;
    const int lane = tid & 31;
    const u32 sbase = smem_u32(smem);
    const long long row0 = (long long)blockIdx.x * 128;

    float* stage = (float*)(smem + CB_STAGE);

    #pragma unroll
    for (int rep = 0; rep < 3; rep++) {
        int e = tid + rep * 512;
        if (e < 128 * 9) {
            int s = e / 9, q = e - s * 9;
            long long row = row0 + s;
            int t = (int)(row / NSEQ);
            int n = (int)(row - (long long)t * NSEQ);
            cp16(stage + s * 36 + q * 4,
                 (const float4*)(cust + (size_t)n * (NNODES * FEAT) + t * FEAT) + q);
        }
    }
    asm volatile("cp.async.commit_group;");
    for (int i = tid; i < 12 * CB_ROW / 4; i += 512)
        *(u32*)(smem + CB_XP + 36 * CB_ROW + i * 4) = 0;
    asm volatile("cp.async.wait_group 0;");
    __syncthreads();

    #pragma unroll
    for (int i = 0; i < 9; i++) {
        int e = tid + i * 512;
        int f = e >> 7, s = e & 127;
        *(__half*)(smem + CB_XP + f * CB_ROW + s * 2) = __float2half(stage[s * 36 + f]);
    }
    __syncthreads();

    const int wg = wid >> 3;
    const int wm = wid & 7;
    float acc[32];
    #pragma unroll
    for (int i = 0; i < 32; i++) acc[i] = 0.f;
    {
        const u32 bb = sbase + CB_XP + wg * 128 + (lane & 15) * CB_ROW;
        #pragma unroll
        for (int sl = 0; sl < 3; sl++) {
            u32 b[16];
            #pragma unroll
            for (int nt = 0; nt < 8; nt++)
                ldsm_t2(b[2 * nt], b[2 * nt + 1], bb + sl * 16 * CB_ROW + nt * 16);
            uint4 ahi = g_cblob1[sl * 512 + wm * 64 + lane];
            uint4 alo = g_cblob1[sl * 512 + wm * 64 + 32 + lane];
            #pragma unroll
            for (int nt = 0; nt < 8; nt++)
                mma_f16(acc + nt * 4, (const u32*)&ahi, b[2 * nt], b[2 * nt + 1]);
            #pragma unroll
            for (int nt = 0; nt < 8; nt++)
                mma_f16(acc + nt * 4, (const u32*)&alo, b[2 * nt], b[2 * nt + 1]);
        }
    }
    {
        const int r0 = 16 * wm + (lane >> 2);
        const float ba = b1[r0], bb_ = b1[r0 + 8];
        #pragma unroll
        for (int nt = 0; nt < 8; nt++) {
            int col = wg * 64 + nt * 8 + 2 * (lane & 3);
            float t00 = ftanh(acc[nt * 4 + 0] + ba);
            float t01 = ftanh(acc[nt * 4 + 1] + ba);
            float t10 = ftanh(acc[nt * 4 + 2] + bb_);
            float t11 = ftanh(acc[nt * 4 + 3] + bb_);
            __half2 hA = __floats2half2_rn(t00, t01);
            __half2 hB = __floats2half2_rn(t10, t11);
            *(__half2*)(smem + CB_HP + r0 * CB_ROW + col * 2) = hA;
            *(__half2*)(smem + CB_HP + (r0 + 8) * CB_ROW + col * 2) = hB;
        }
    }
    __syncthreads();

    const int mt = wid & 1;
    const int sq = wid >> 1;
    float a2[8];
    #pragma unroll
    for (int i = 0; i < 8; i++) a2[i] = 0.f;
    {
        const u32 bb = sbase + CB_HP + sq * 32 + (lane & 15) * CB_ROW;
        #pragma unroll
        for (int sl = 0; sl < 8; sl++) {
            u32 b[4];
            ldsm_t2(b[0], b[1], bb + sl * 16 * CB_ROW);
            ldsm_t2(b[2], b[3], bb + sl * 16 * CB_ROW + 16);
            uint4 ahi = g_cblob2[sl * 128 + mt * 64 + lane];
            uint4 alo = g_cblob2[sl * 128 + mt * 64 + 32 + lane];
            mma_f16(a2 + 0, (const u32*)&ahi, b[0], b[1]);
            mma_f16(a2 + 4, (const u32*)&ahi, b[2], b[3]);
            mma_f16(a2 + 0, (const u32*)&alo, b[0], b[1]);
            mma_f16(a2 + 4, (const u32*)&alo, b[2], b[3]);
        }
    }
    {
        const int o0 = 16 * mt + (lane >> 2);
        const float ba = b2[o0], bb_ = b2[o0 + 8];
        #pragma unroll
        for (int nt = 0; nt < 2; nt++) {
            int s0 = sq * 16 + nt * 8 + 2 * (lane & 3);
            size_t base = (size_t)(row0 + s0) * COUT;
            g_x32[base + o0]            = ftanh(a2[nt * 4 + 0] + ba);
            g_x32[base + COUT + o0]     = ftanh(a2[nt * 4 + 1] + ba);
            g_x32[base + o0 + 8]        = ftanh(a2[nt * 4 + 2] + bb_);
            g_x32[base + COUT + o0 + 8] = ftanh(a2[nt * 4 + 3] + bb_);
        }
    }
}

/* ==================== K2: HMMA GRU — single barrier per timestep ==================== */
#define NTILE   64
#define BROW    144
#define OFF_H0HI 0
#define OFF_H1HI 36864
#define OFF_F32  73728
#define OFF_XB   147456
#define OFF_STG  156672
#define GRU_SMEM 164864

template<int NSL, int NIH>
__device__ __forceinline__ void gemm_phase(
    const uint4* __restrict__ pA,
    u32 bih_hi, u32 bhh_hi,
    int lane15, float* acc)
{
    uint4 a0 = pA[0], a1 = pA[32], a2 = pA[64], a3 = pA[96];
    #pragma unroll 1
    for (int sl = 0; sl < NSL; sl++) {
        u32 rh = (sl < NIH) ? (bih_hi + sl * 16 * BROW + lane15)
                            : (bhh_hi + (sl - NIH) * 16 * BROW + lane15);
        u32 b[16];
        #pragma unroll
        for (int nt = 0; nt < 8; nt++)
            ldsm_t2(b[2 * nt], b[2 * nt + 1], rh + nt * 16);
        uint4 n0, n1, n2, n3;
        if (sl + 1 < NSL) {
            const uint4* p = pA + (size_t)(sl + 1) * 2048;
            n0 = p[0]; n1 = p[32]; n2 = p[64]; n3 = p[96];
        }
        #pragma unroll
        for (int nt = 0; nt < 8; nt++) {
            mma_f16(acc + nt * 4,      (const u32*)&a0, b[2 * nt], b[2 * nt + 1]);
            mma_f16(acc + 32 + nt * 4, (const u32*)&a1, b[2 * nt], b[2 * nt + 1]);
        }
        #pragma unroll
        for (int nt = 0; nt < 8; nt++) {
            mma_f16(acc + nt * 4,      (const u32*)&a2, b[2 * nt], b[2 * nt + 1]);
            mma_f16(acc + 32 + nt * 4, (const u32*)&a3, b[2 * nt], b[2 * nt + 1]);
        }
        if (sl + 1 < NSL) { a0 = n0; a1 = n1; a2 = n2; a3 = n3; }
    }
}

/* biases pre-loaded into accumulators; epilogue reads acc directly */
__device__ __forceinline__ void gru_epilogue(
    const float* acc,
    u32 rowhi_w, u32 rowf,
    int sb, float* lastout, int j, int nbase)
{
    #pragma unroll
    for (int nt = 0; nt < 8; nt++) {
        int o = nt * 16 + sb;
        float2 hold;
        asm volatile("ld.shared.v2.f32 {%0,%1}, [%2];"
                     : "=f"(hold.x), "=f"(hold.y) : "r"(rowf + nt * 8));
        float r0 = fsigm(acc[nt * 4 + 0]);
        float r1 = fsigm(acc[nt * 4 + 1]);
        float z0 = fsigm(acc[nt * 4 + 2]);
        float z1 = fsigm(acc[nt * 4 + 3]);
        float n0 = ftanh(acc[32 + nt * 4 + 0] + r0 * acc[32 + nt * 4 + 2]);
        float n1 = ftanh(acc[32 + nt * 4 + 1] + r1 * acc[32 + nt * 4 + 3]);
        float h0 = (1.f - z0) * n0 + z0 * hold.x;
        float h1 = (1.f - z1) * n1 + z1 * hold.y;
        asm volatile("st.shared.v2.f32 [%0], {%1,%2};"
                     :: "r"(rowf + nt * 8), "f"(h0), "f"(h1) : "memory");
        __half2 H2 = __floats2half2_rn(h0, h1);
        u32 packh = *reinterpret_cast<u32*>(&H2);
        asm volatile("st.shared.b32 [%0], %1;" :: "r"(rowhi_w + o), "r"(packh) : "memory");
        if (lastout) {
            int s = nt * 8 + (sb >> 1);
            lastout[(size_t)(nbase + s) * RH + j]     = h0;
            lastout[(size_t)(nbase + s + 1) * RH + j] = h1;
        }
    }
}

__device__ __forceinline__ void conv_x(const float* stg, char* smemc, int xoff, int tid)
{
    #pragma unroll
    for (int i = 0; i < 4; i++) {
        int e = 4 * tid + i;
        float v = stg[e];
        int s = e >> 5, f = e & 31;
        *(__half*)(smemc + xoff + f * BROW + s * 2) = __float2half(v);
    }
}

__global__ __launch_bounds__(512, 1) void k_gru(
    const float* __restrict__ bih0, const float* __restrict__ bhh0,
    const float* __restrict__ bih1, const float* __restrict__ bhh1)
{
    extern __shared__ __align__(16) char smem[];
    const int tid = threadIdx.x;
    const int wid = tid >> 5;
    const int lane = tid & 31;
    const int nbase = blockIdx.x * NTILE;
    const u32 sbase = smem_u32(smem);

    for (int i = tid; i < OFF_XB / 4; i += 512) ((u32*)smem)[i] = 0;

    const int j = wid * 8 + (lane >> 2);
    /* n-gate biases folded into acc init: tile1 = i-part(bi) + r*(h-part(bn)) */
    const float br0 = bih0[j] + bhh0[j];
    const float bz0 = bih0[128 + j] + bhh0[128 + j];
    const float bi0 = bih0[256 + j];
    const float bn0 = bhh0[256 + j];
    const float br1 = bih1[j] + bhh1[j];
    const float bz1 = bih1[128 + j] + bhh1[128 + j];
    const float bi1 = bih1[256 + j];
    const float bn1 = bhh1[256 + j];

    const int lane15 = (lane & 15) * BROW;
    const int sb = (lane & 3) * 4;
    const u32 rowf0 = sbase + OFF_F32 + tid * 72;
    const u32 rowf1 = rowf0 + 36864;

    const uint4* pb0 = g_wblob + (size_t)wid * 128 + lane;
    const uint4* pb1 = pb0 + (size_t)10 * 2048;
    float* stg = (float*)(smem + OFF_STG);

    {
        const float4* src = (const float4*)(g_x32 + (size_t)nbase * 32);
        cp16(stg + 4 * tid, src + tid);
        asm volatile("cp.async.commit_group;");
        asm volatile("cp.async.wait_group 0;");
        conv_x(stg, smem, OFF_XB, tid);
    }
    __syncthreads();

    float acc[64];

    for (int t = 0; t < NNODES; t++) {
        const int p = t & 1;
        if (t < NNODES - 1) {
            const float4* src = (const float4*)(g_x32 + ((size_t)(t + 1) * NSEQ + nbase) * 32);
            cp16(stg + 4 * tid, src + tid);
            asm volatile("cp.async.commit_group;");
        }
        /* ---- layer 0: reads x[p], h0hi[p]; writes h0hi[p^1] ---- */
        #pragma unroll
        for (int nt = 0; nt < 8; nt++) {
            acc[nt * 4 + 0] = br0; acc[nt * 4 + 1] = br0;
            acc[nt * 4 + 2] = bz0; acc[nt * 4 + 3] = bz0;
            acc[32 + nt * 4 + 0] = bi0; acc[32 + nt * 4 + 1] = bi0;
            acc[32 + nt * 4 + 2] = bn0; acc[32 + nt * 4 + 3] = bn0;
        }
        gemm_phase<10, 2>(pb0, sbase + OFF_XB + p * 4608,
                          sbase + OFF_H0HI + p * 18432, lane15, acc);
        gru_epilogue(acc,
                     sbase + OFF_H0HI + (p ^ 1) * 18432 + j * BROW,
                     rowf0, sb, (float*)0, j, nbase);
        if (t < NNODES - 1) {   /* convert x(t+1) BEFORE the single barrier */
            asm volatile("cp.async.wait_group 0;");
            conv_x(stg, smem, OFF_XB + ((t + 1) & 1) * 4608, tid);
        }
        __syncthreads();   /* orders: h0hi[p^1], x[p^1], and (from t-1) h1hi[p] */

        /* ---- layer 1: reads h0hi[p^1], h1hi[p]; writes h1hi[p^1] ---- */
        #pragma unroll
        for (int nt = 0; nt < 8; nt++) {
            acc[nt * 4 + 0] = br1; acc[nt * 4 + 1] = br1;
            acc[nt * 4 + 2] = bz1; acc[nt * 4 + 3] = bz1;
            acc[32 + nt * 4 + 0] = bi1; acc[32 + nt * 4 + 1] = bi1;
            acc[32 + nt * 4 + 2] = bn1; acc[32 + nt * 4 + 3] = bn1;
        }
        gemm_phase<16, 8>(pb1, sbase + OFF_H0HI + (p ^ 1) * 18432,
                          sbase + OFF_H1HI + p * 18432, lane15, acc);
        gru_epilogue(acc,
                     sbase + OFF_H1HI + (p ^ 1) * 18432 + j * BROW,
                     rowf1, sb, (t == NNODES - 1) ? g_last : (float*)0, j, nbase);
        /* no end-of-step barrier: h1hi[p^1] readers sit behind next step's barrier */
    }
}

/* ==================== K3: mean over routes + head MLP ==================== */
__global__ __launch_bounds__(128) void k_final(
    const float* __restrict__ cand,
    const float* __restrict__ cand_w, const float* __restrict__ cand_b,
    const float* __restrict__ fc1w, const float* __restrict__ fc1b,
    const float* __restrict__ fc2w, const float* __restrict__ fc2b,
    const float* __restrict__ fc3w, const float* __restrict__ fc3b,
    float* __restrict__ out)
{
    __shared__ float xr[RH + 64];
    __shared__ float h[128];
    __shared__ float red[128];
    const int b = blockIdx.x, tid = threadIdx.x;
    {
        const float* base = g_last + (size_t)b * NROUTES * RH;
        float acc = 0.f;
        #pragma unroll 8
        for (int r = 0; r < NROUTES; r++) acc += base[r * RH + tid];
        xr[tid] = acc * (1.f / NROUTES);
    }
    if (tid < 64) {
        float a = cand_b[tid];
        #pragma unroll 8
        for (int i = 0; i < 2 * FEAT; i++)
            a += cand[b * 2 * FEAT + i] * cand_w[i * 64 + tid];
        xr[RH + tid] = a;
    }
    __syncthreads();
    {
        float a = fc1b[tid];
        #pragma unroll 8
        for (int i = 0; i < RH + 64; i++) a += xr[i] * fc1w[i * 128 + tid];
        h[tid] = tanhf(a);
    }
    __syncthreads();
    {
        float a = fc2b[tid];
        #pragma unroll 8
        for (int i = 0; i < 128; i++) a += h[i] * fc2w[i * 128 + tid];
        red[tid] = tanhf(a) * fc3w[tid];
    }
    __syncthreads();
    for (int s = 64; s > 0; s >>= 1) {
        if (tid < s) red[tid] += red[tid + s];
        __syncthreads();
    }
    if (tid == 0) out[b] = red[0] + fc3b[0];
}

/* ==================== launch ==================== */
extern "C" void kernel_launch(void* const* d_in, const int* in_sizes, int n_in,
                              void* d_out, int out_size)
{
    const float* candidates = (const float*)d_in[0];
    const float* customers  = (const float*)d_in[1];
    const float* cust_w1 = (const float*)d_in[2];
    const float* cust_b1 = (const float*)d_in[3];
    const float* cust_w2 = (const float*)d_in[4];
    const float* cust_b2 = (const float*)d_in[5];
    const float* wih0 = (const float*)d_in[6];
    const float* whh0 = (const float*)d_in[7];
    const float* bih0 = (const float*)d_in[8];
    const float* bhh0 = (const float*)d_in[9];
    const float* wih1 = (const float*)d_in[10];
    const float* whh1 = (const float*)d_in[11];
    const float* bih1 = (const float*)d_in[12];
    const float* bhh1 = (const float*)d_in[13];
    const float* cand_w = (const float*)d_in[14];
    const float* cand_b = (const float*)d_in[15];
    const float* fc1w = (const float*)d_in[16];
    const float* fc1b = (const float*)d_in[17];
    const float* fc2w = (const float*)d_in[18];
    const float* fc2b = (const float*)d_in[19];
    const float* fc3w = (const float*)d_in[20];
    const float* fc3b = (const float*)d_in[21];

    cudaFuncSetAttribute(k_gru, cudaFuncAttributeMaxDynamicSharedMemorySize, GRU_SMEM);
    cudaFuncSetAttribute(k_cust_mma, cudaFuncAttributeMaxDynamicSharedMemorySize, CB_SMEM);

    k_prep_gru<<<(26 * 16384 + 255) / 256, 256>>>(wih0, whh0, wih1, whh1);
    k_prep_cblob<<<(12288 + 8192 + 255) / 256, 256>>>(cust_w1, cust_w2);
    k_cust_mma<<<NROWS / 128, 512, CB_SMEM>>>(customers, cust_b1, cust_b2);
    k_gru<<<NSEQ / NTILE, 512, GRU_SMEM>>>(bih0, bhh0, bih1, bhh1);
    k_final<<<BATCH, 128>>>(candidates, cand_w, cand_b,
                            fc1w, fc1b, fc2w, fc2b, fc3w, fc3b,
                            (float*)d_out);
}

// round 17
// speedup vs baseline: 4.6838x; 1.0580x over previous
#include <cuda_runtime.h>
#include <cuda_fp16.h>
#include <math.h>
#include <stdint.h>
#include <stddef.h>

#define FEAT    36
#define NNODES  24
#define NROUTES 48
#define CH      128
#define COUT    32
#define RH      128
#define BATCH   512
#define NSEQ    (BATCH * NROUTES)
#define G3      (3 * RH)
#define NROWS   (NNODES * NSEQ)

typedef unsigned long long ull;
typedef unsigned int u32;

/* ---- fast gate nonlinearities (clamped; MUFU-based) ---- */
__device__ __forceinline__ float fsigm(float x) {
    x = fminf(fmaxf(x, -20.f), 20.f);
    float e = __expf(-x);
    return __fdividef(1.f, 1.f + e);
}
__device__ __forceinline__ float ftanh(float x) {
    x = fminf(fmaxf(x, -10.f), 10.f);
    float e = __expf(-2.f * x);
    return __fdividef(1.f - e, 1.f + e);
}

__device__ __forceinline__ void cp16(float* dst, const float4* src) {
    unsigned s = (unsigned)__cvta_generic_to_shared(dst);
    asm volatile("cp.async.ca.shared.global [%0], [%1], 16;" :: "r"(s), "l"(src));
}
__device__ __forceinline__ u32 smem_u32(const void* p) {
    u32 a;
    asm("{ .reg .u64 t; cvta.to.shared.u64 t, %1; cvt.u32.u64 %0, t; }" : "=r"(a) : "l"(p));
    return a;
}

/* ---- HMMA helpers (sm_80 baseline; valid on plain sm_103) ---- */
__device__ __forceinline__ void mma_f16(float* c, const u32* a, u32 b0, u32 b1) {
    asm("mma.sync.aligned.m16n8k16.row.col.f32.f16.f16.f32 "
        "{%0,%1,%2,%3},{%4,%5,%6,%7},{%8,%9},{%0,%1,%2,%3};"
        : "+f"(c[0]), "+f"(c[1]), "+f"(c[2]), "+f"(c[3])
        : "r"(a[0]), "r"(a[1]), "r"(a[2]), "r"(a[3]), "r"(b0), "r"(b1));
}
__device__ __forceinline__ void ldsm_t2(u32& r0, u32& r1, u32 addr) {
    asm volatile("ldmatrix.sync.aligned.m8n8.x2.trans.shared.b16 {%0,%1}, [%2];"
                 : "=r"(r0), "=r"(r1) : "r"(addr));
}

/* ---- device scratch ---- */
__device__ float g_x32[(size_t)NROWS * COUT];
__device__ float g_last[(size_t)NSEQ * RH];
__device__ uint4 g_wblob[26 * 2048];      /* GRU A-fragment stream (hi fragments used) */
__device__ uint4 g_cblob1[1536];          /* k_cust GEMM1 fragments */
__device__ uint4 g_cblob2[1024];          /* k_cust GEMM2 fragments */

/* ==================== prep: GRU A-fragment blob ==================== */
__global__ __launch_bounds__(256) void k_prep_gru(
    const float* __restrict__ wih0, const float* __restrict__ whh0,
    const float* __restrict__ wih1, const float* __restrict__ whh1)
{
    int idx = blockIdx.x * 256 + threadIdx.x;     /* fp16 element index */
    if (idx >= 26 * 16384) return;
    int off  = idx * 2;
    int sg   = off >> 15;
    int rem  = off & 32767;
    int wid  = rem >> 11;
    int rem2 = rem & 2047;
    int frag = rem2 >> 9;
    int rem3 = rem2 & 511;
    int lane = rem3 >> 4;
    int b    = rem3 & 15;
    int pos  = b >> 1;
    int areg = pos >> 1, elt = pos & 1;
    int row  = (lane >> 2) + (areg & 1) * 8;
    int col  = (lane & 3) * 2 + (areg >> 1) * 8 + elt;
    int tile = frag & 1, split = frag >> 1;
    int j    = wid * 8 + (row & 7);
    int phase = (sg < 10) ? 0 : 1;
    int sl    = phase ? sg - 10 : sg;
    int nih   = phase ? 8 : 2;
    bool is_ih = sl < nih;
    int k = (is_ih ? sl : sl - nih) * 16 + col;
    const float* W = phase == 0 ? (is_ih ? wih0 : whh0) : (is_ih ? wih1 : whh1);
    int gcol = (tile == 0) ? ((row < 8) ? j : 128 + j) : 256 + j;
    bool valid = (tile == 0) || ((row < 8) ? is_ih : !is_ih);
    float v = valid ? W[k * G3 + gcol] : 0.f;
    __half hb = __float2half(v);
    __half out = split ? __float2half(v - __half2float(hb)) : hb;
    ((unsigned short*)g_wblob)[idx] = reinterpret_cast<unsigned short&>(out);
}

/* ==================== prep: k_cust fragment blobs ==================== */
__global__ __launch_bounds__(256) void k_prep_cblob(
    const float* __restrict__ w1, const float* __restrict__ w2)
{
    int idx = blockIdx.x * 256 + threadIdx.x;
    if (idx >= 12288 + 8192) return;
    float v;
    unsigned short* dst;
    if (idx < 12288) {
        int p = idx & 7, l = idx >> 3;
        int areg = p >> 1, elt = p & 1;
        int lane = l & 31, split = (l >> 5) & 1, wm = (l >> 6) & 7, sl = l >> 9;
        int rowm = 16 * wm + (lane >> 2) + (areg & 1) * 8;
        int kcol = sl * 16 + (lane & 3) * 2 + (areg >> 1) * 8 + elt;
        v = (kcol < FEAT) ? w1[kcol * CH + rowm] : 0.f;
        if (split) { __half hb = __float2half(v); v = v - __half2float(hb); }
        dst = ((unsigned short*)g_cblob1) + idx;
    } else {
        int i2 = idx - 12288;
        int p = i2 & 7, l = i2 >> 3;
        int areg = p >> 1, elt = p & 1;
        int lane = l & 31, split = (l >> 5) & 1, mt = (l >> 6) & 1, sl = l >> 7;
        int rowo = 16 * mt + (lane >> 2) + (areg & 1) * 8;
        int kcol = sl * 16 + (lane & 3) * 2 + (areg >> 1) * 8 + elt;
        v = w2[kcol * COUT + rowo];
        if (split) { __half hb = __float2half(v); v = v - __half2float(hb); }
        dst = ((unsigned short*)g_cblob2) + i2;
    }
    __half out = __float2half(v);
    *dst = reinterpret_cast<unsigned short&>(out);
}

/* ==================== K1: customer MLP via HMMA (hi-only W) ==================== */
#define CB_ROW   272
#define CB_STAGE 0
#define CB_XP    18432
#define CB_HP    31488
#define CB_SMEM  66304

__global__ __launch_bounds__(512) void k_cust_mma(
    const float* __restrict__ cust,
    const float* __restrict__ b1, const float* __restrict__ b2)
{
    extern __shared__ __align__(16) char smem[];
    const int tid = threadIdx.x;
    const int wid = tid >> 5;
    const int lane = tid & 31;
    const u32 sbase = smem_u32(smem);
    const long long row0 = (long long)blockIdx.x * 128;

    float* stage = (float*)(smem + CB_STAGE);

    #pragma unroll
    for (int rep = 0; rep < 3; rep++) {
        int e = tid + rep * 512;
        if (e < 128 * 9) {
            int s = e / 9, q = e - s * 9;
            long long row = row0 + s;
            int t = (int)(row / NSEQ);
            int n = (int)(row - (long long)t * NSEQ);
            cp16(stage + s * 36 + q * 4,
                 (const float4*)(cust + (size_t)n * (NNODES * FEAT) + t * FEAT) + q);
        }
    }
    asm volatile("cp.async.commit_group;");
    for (int i = tid; i < 12 * CB_ROW / 4; i += 512)
        *(u32*)(smem + CB_XP + 36 * CB_ROW + i * 4) = 0;
    asm volatile("cp.async.wait_group 0;");
    __syncthreads();

    #pragma unroll
    for (int i = 0; i < 9; i++) {
        int e = tid + i * 512;
        int f = e >> 7, s = e & 127;
        *(__half*)(smem + CB_XP + f * CB_ROW + s * 2) = __float2half(stage[s * 36 + f]);
    }
    __syncthreads();

    const int wg = wid >> 3;
    const int wm = wid & 7;
    float acc[32];
    #pragma unroll
    for (int i = 0; i < 32; i++) acc[i] = 0.f;
    {
        const u32 bb = sbase + CB_XP + wg * 128 + (lane & 15) * CB_ROW;
        #pragma unroll
        for (int sl = 0; sl < 3; sl++) {
            u32 b[16];
            #pragma unroll
            for (int nt = 0; nt < 8; nt++)
                ldsm_t2(b[2 * nt], b[2 * nt + 1], bb + sl * 16 * CB_ROW + nt * 16);
            uint4 ahi = g_cblob1[sl * 512 + wm * 64 + lane];
            #pragma unroll
            for (int nt = 0; nt < 8; nt++)
                mma_f16(acc + nt * 4, (const u32*)&ahi, b[2 * nt], b[2 * nt + 1]);
        }
    }
    {
        const int r0 = 16 * wm + (lane >> 2);
        const float ba = b1[r0], bb_ = b1[r0 + 8];
        #pragma unroll
        for (int nt = 0; nt < 8; nt++) {
            int col = wg * 64 + nt * 8 + 2 * (lane & 3);
            float t00 = ftanh(acc[nt * 4 + 0] + ba);
            float t01 = ftanh(acc[nt * 4 + 1] + ba);
            float t10 = ftanh(acc[nt * 4 + 2] + bb_);
            float t11 = ftanh(acc[nt * 4 + 3] + bb_);
            __half2 hA = __floats2half2_rn(t00, t01);
            __half2 hB = __floats2half2_rn(t10, t11);
            *(__half2*)(smem + CB_HP + r0 * CB_ROW + col * 2) = hA;
            *(__half2*)(smem + CB_HP + (r0 + 8) * CB_ROW + col * 2) = hB;
        }
    }
    __syncthreads();

    const int mt = wid & 1;
    const int sq = wid >> 1;
    float a2[8];
    #pragma unroll
    for (int i = 0; i < 8; i++) a2[i] = 0.f;
    {
        const u32 bb = sbase + CB_HP + sq * 32 + (lane & 15) * CB_ROW;
        #pragma unroll
        for (int sl = 0; sl < 8; sl++) {
            u32 b[4];
            ldsm_t2(b[0], b[1], bb + sl * 16 * CB_ROW);
            ldsm_t2(b[2], b[3], bb + sl * 16 * CB_ROW + 16);
            uint4 ahi = g_cblob2[sl * 128 + mt * 64 + lane];
            mma_f16(a2 + 0, (const u32*)&ahi, b[0], b[1]);
            mma_f16(a2 + 4, (const u32*)&ahi, b[2], b[3]);
        }
    }
    {
        const int o0 = 16 * mt + (lane >> 2);
        const float ba = b2[o0], bb_ = b2[o0 + 8];
        #pragma unroll
        for (int nt = 0; nt < 2; nt++) {
            int s0 = sq * 16 + nt * 8 + 2 * (lane & 3);
            size_t base = (size_t)(row0 + s0) * COUT;
            g_x32[base + o0]            = ftanh(a2[nt * 4 + 0] + ba);
            g_x32[base + COUT + o0]     = ftanh(a2[nt * 4 + 1] + ba);
            g_x32[base + o0 + 8]        = ftanh(a2[nt * 4 + 2] + bb_);
            g_x32[base + COUT + o0 + 8] = ftanh(a2[nt * 4 + 3] + bb_);
        }
    }
}

/* ==================== K2: HMMA GRU — fp16 W, single pass, one barrier/step ==================== */
#define NTILE   64
#define BROW    144
#define OFF_H0HI 0
#define OFF_H1HI 36864
#define OFF_F32  73728
#define OFF_XB   147456
#define OFF_STG  156672
#define GRU_SMEM 164864

template<int NSL, int NIH>
__device__ __forceinline__ void gemm_phase(
    const uint4* __restrict__ pA,
    u32 bih_hi, u32 bhh_hi,
    int lane15, float* acc)
{
    uint4 a0 = pA[0], a1 = pA[32];
    #pragma unroll 1
    for (int sl = 0; sl < NSL; sl++) {
        u32 rh = (sl < NIH) ? (bih_hi + sl * 16 * BROW + lane15)
                            : (bhh_hi + (sl - NIH) * 16 * BROW + lane15);
        u32 b[16];
        #pragma unroll
        for (int nt = 0; nt < 8; nt++)
            ldsm_t2(b[2 * nt], b[2 * nt + 1], rh + nt * 16);
        uint4 n0, n1;
        if (sl + 1 < NSL) {
            const uint4* p = pA + (size_t)(sl + 1) * 2048;
            n0 = p[0]; n1 = p[32];
        }
        #pragma unroll
        for (int nt = 0; nt < 8; nt++) {
            mma_f16(acc + nt * 4,      (const u32*)&a0, b[2 * nt], b[2 * nt + 1]);
            mma_f16(acc + 32 + nt * 4, (const u32*)&a1, b[2 * nt], b[2 * nt + 1]);
        }
        if (sl + 1 < NSL) { a0 = n0; a1 = n1; }
    }
}

/* biases pre-loaded into accumulators; epilogue reads acc directly */
__device__ __forceinline__ void gru_epilogue(
    const float* acc,
    u32 rowhi_w, u32 rowf,
    int sb, float* lastout, int j, int nbase)
{
    #pragma unroll
    for (int nt = 0; nt < 8; nt++) {
        int o = nt * 16 + sb;
        float2 hold;
        asm volatile("ld.shared.v2.f32 {%0,%1}, [%2];"
                     : "=f"(hold.x), "=f"(hold.y) : "r"(rowf + nt * 8));
        float r0 = fsigm(acc[nt * 4 + 0]);
        float r1 = fsigm(acc[nt * 4 + 1]);
        float z0 = fsigm(acc[nt * 4 + 2]);
        float z1 = fsigm(acc[nt * 4 + 3]);
        float n0 = ftanh(acc[32 + nt * 4 + 0] + r0 * acc[32 + nt * 4 + 2]);
        float n1 = ftanh(acc[32 + nt * 4 + 1] + r1 * acc[32 + nt * 4 + 3]);
        float h0 = (1.f - z0) * n0 + z0 * hold.x;
        float h1 = (1.f - z1) * n1 + z1 * hold.y;
        asm volatile("st.shared.v2.f32 [%0], {%1,%2};"
                     :: "r"(rowf + nt * 8), "f"(h0), "f"(h1) : "memory");
        __half2 H2 = __floats2half2_rn(h0, h1);
        u32 packh = *reinterpret_cast<u32*>(&H2);
        asm volatile("st.shared.b32 [%0], %1;" :: "r"(rowhi_w + o), "r"(packh) : "memory");
        if (lastout) {
            int s = nt * 8 + (sb >> 1);
            lastout[(size_t)(nbase + s) * RH + j]     = h0;
            lastout[(size_t)(nbase + s + 1) * RH + j] = h1;
        }
    }
}

__device__ __forceinline__ void conv_x(const float* stg, char* smemc, int xoff, int tid)
{
    #pragma unroll
    for (int i = 0; i < 4; i++) {
        int e = 4 * tid + i;
        float v = stg[e];
        int s = e >> 5, f = e & 31;
        *(__half*)(smemc + xoff + f * BROW + s * 2) = __float2half(v);
    }
}

__global__ __launch_bounds__(512, 1) void k_gru(
    const float* __restrict__ bih0, const float* __restrict__ bhh0,
    const float* __restrict__ bih1, const float* __restrict__ bhh1)
{
    extern __shared__ __align__(16) char smem[];
    const int tid = threadIdx.x;
    const int wid = tid >> 5;
    const int lane = tid & 31;
    const int nbase = blockIdx.x * NTILE;
    const u32 sbase = smem_u32(smem);

    for (int i = tid; i < OFF_XB / 4; i += 512) ((u32*)smem)[i] = 0;

    const int j = wid * 8 + (lane >> 2);
    const float br0 = bih0[j] + bhh0[j];
    const float bz0 = bih0[128 + j] + bhh0[128 + j];
    const float bi0 = bih0[256 + j];
    const float bn0 = bhh0[256 + j];
    const float br1 = bih1[j] + bhh1[j];
    const float bz1 = bih1[128 + j] + bhh1[128 + j];
    const float bi1 = bih1[256 + j];
    const float bn1 = bhh1[256 + j];

    const int lane15 = (lane & 15) * BROW;
    const int sb = (lane & 3) * 4;
    const u32 rowf0 = sbase + OFF_F32 + tid * 72;
    const u32 rowf1 = rowf0 + 36864;

    const uint4* pb0 = g_wblob + (size_t)wid * 128 + lane;
    const uint4* pb1 = pb0 + (size_t)10 * 2048;
    float* stg = (float*)(smem + OFF_STG);

    {
        const float4* src = (const float4*)(g_x32 + (size_t)nbase * 32);
        cp16(stg + 4 * tid, src + tid);
        asm volatile("cp.async.commit_group;");
        asm volatile("cp.async.wait_group 0;");
        conv_x(stg, smem, OFF_XB, tid);
    }
    __syncthreads();

    float acc[64];

    for (int t = 0; t < NNODES; t++) {
        const int p = t & 1;
        if (t < NNODES - 1) {
            const float4* src = (const float4*)(g_x32 + ((size_t)(t + 1) * NSEQ + nbase) * 32);
            cp16(stg + 4 * tid, src + tid);
            asm volatile("cp.async.commit_group;");
        }
        /* ---- layer 0: reads x[p], h0hi[p]; writes h0hi[p^1] ---- */
        #pragma unroll
        for (int nt = 0; nt < 8; nt++) {
            acc[nt * 4 + 0] = br0; acc[nt * 4 + 1] = br0;
            acc[nt * 4 + 2] = bz0; acc[nt * 4 + 3] = bz0;
            acc[32 + nt * 4 + 0] = bi0; acc[32 + nt * 4 + 1] = bi0;
            acc[32 + nt * 4 + 2] = bn0; acc[32 + nt * 4 + 3] = bn0;
        }
        gemm_phase<10, 2>(pb0, sbase + OFF_XB + p * 4608,
                          sbase + OFF_H0HI + p * 18432, lane15, acc);
        gru_epilogue(acc,
                     sbase + OFF_H0HI + (p ^ 1) * 18432 + j * BROW,
                     rowf0, sb, (float*)0, j, nbase);
        if (t < NNODES - 1) {
            asm volatile("cp.async.wait_group 0;");
            conv_x(stg, smem, OFF_XB + ((t + 1) & 1) * 4608, tid);
        }
        __syncthreads();   /* orders: h0hi[p^1], x[p^1], and (from t-1) h1hi[p] */

        /* ---- layer 1: reads h0hi[p^1], h1hi[p]; writes h1hi[p^1] ---- */
        #pragma unroll
        for (int nt = 0; nt < 8; nt++) {
            acc[nt * 4 + 0] = br1; acc[nt * 4 + 1] = br1;
            acc[nt * 4 + 2] = bz1; acc[nt * 4 + 3] = bz1;
            acc[32 + nt * 4 + 0] = bi1; acc[32 + nt * 4 + 1] = bi1;
            acc[32 + nt * 4 + 2] = bn1; acc[32 + nt * 4 + 3] = bn1;
        }
        gemm_phase<16, 8>(pb1, sbase + OFF_H0HI + (p ^ 1) * 18432,
                          sbase + OFF_H1HI + p * 18432, lane15, acc);
        gru_epilogue(acc,
                     sbase + OFF_H1HI + (p ^ 1) * 18432 + j * BROW,
                     rowf1, sb, (t == NNODES - 1) ? g_last : (float*)0, j, nbase);
        /* no end-of-step barrier: h1hi[p^1] readers sit behind next step's barrier */
    }
}

/* ==================== K3: mean over routes + head MLP ==================== */
__global__ __launch_bounds__(128) void k_final(
    const float* __restrict__ cand,
    const float* __restrict__ cand_w, const float* __restrict__ cand_b,
    const float* __restrict__ fc1w, const float* __restrict__ fc1b,
    const float* __restrict__ fc2w, const float* __restrict__ fc2b,
    const float* __restrict__ fc3w, const float* __restrict__ fc3b,
    float* __restrict__ out)
{
    __shared__ float xr[RH + 64];
    __shared__ float h[128];
    __shared__ float red[128];
    const int b = blockIdx.x, tid = threadIdx.x;
    {
        const float* base = g_last + (size_t)b * NROUTES * RH;
        float acc = 0.f;
        #pragma unroll 8
        for (int r = 0; r < NROUTES; r++) acc += base[r * RH + tid];
        xr[tid] = acc * (1.f / NROUTES);
    }
    if (tid < 64) {
        float a = cand_b[tid];
        #pragma unroll 8
        for (int i = 0; i < 2 * FEAT; i++)
            a += cand[b * 2 * FEAT + i] * cand_w[i * 64 + tid];
        xr[RH + tid] = a;
    }
    __syncthreads();
    {
        float a = fc1b[tid];
        #pragma unroll 8
        for (int i = 0; i < RH + 64; i++) a += xr[i] * fc1w[i * 128 + tid];
        h[tid] = tanhf(a);
    }
    __syncthreads();
    {
        float a = fc2b[tid];
        #pragma unroll 8
        for (int i = 0; i < 128; i++) a += h[i] * fc2w[i * 128 + tid];
        red[tid] = tanhf(a) * fc3w[tid];
    }
    __syncthreads();
    for (int s = 64; s > 0; s >>= 1) {
        if (tid < s) red[tid] += red[tid + s];
        __syncthreads();
    }
    if (tid == 0) out[b] = red[0] + fc3b[0];
}

/* ==================== launch ==================== */
extern "C" void kernel_launch(void* const* d_in, const int* in_sizes, int n_in,
                              void* d_out, int out_size)
{
    const float* candidates = (const float*)d_in[0];
    const float* customers  = (const float*)d_in[1];
    const float* cust_w1 = (const float*)d_in[2];
    const float* cust_b1 = (const float*)d_in[3];
    const float* cust_w2 = (const float*)d_in[4];
    const float* cust_b2 = (const float*)d_in[5];
    const float* wih0 = (const float*)d_in[6];
    const float* whh0 = (const float*)d_in[7];
    const float* bih0 = (const float*)d_in[8];
    const float* bhh0 = (const float*)d_in[9];
    const float* wih1 = (const float*)d_in[10];
    const float* whh1 = (const float*)d_in[11];
    const float* bih1 = (const float*)d_in[12];
    const float* bhh1 = (const float*)d_in[13];
    const float* cand_w = (const float*)d_in[14];
    const float* cand_b = (const float*)d_in[15];
    const float* fc1w = (const float*)d_in[16];
    const float* fc1b = (const float*)d_in[17];
    const float* fc2w = (const float*)d_in[18];
    const float* fc2b = (const float*)d_in[19];
    const float* fc3w = (const float*)d_in[20];
    const float* fc3b = (const float*)d_in[21];

    cudaFuncSetAttribute(k_gru, cudaFuncAttributeMaxDynamicSharedMemorySize, GRU_SMEM);
    cudaFuncSetAttribute(k_cust_mma, cudaFuncAttributeMaxDynamicSharedMemorySize, CB_SMEM);

    k_prep_gru<<<(26 * 16384 + 255) / 256, 256>>>(wih0, whh0, wih1, whh1);
    k_prep_cblob<<<(12288 + 8192 + 255) / 256, 256>>>(cust_w1, cust_w2);
    k_cust_mma<<<NROWS / 128, 512, CB_SMEM>>>(customers, cust_b1, cust_b2);
    k_gru<<<NSEQ / NTILE, 512, GRU_SMEM>>>(bih0, bhh0, bih1, bhh1);
    k_final<<<BATCH, 128>>>(candidates, cand_w, cand_b,
                            fc1w, fc1b, fc2w, fc2b, fc3w, fc3b,
                            (float*)d_out);
}